// round 10
// baseline (speedup 1.0000x reference)
#include <cuda_runtime.h>
#include <cuda_fp16.h>
#include <cstdint>

constexpr int N    = 32768;
constexpr int EPER = 16384;
constexpr int T    = 8;
constexpr int E0   = T * EPER;   // 131072 typed edges
constexpr int E    = E0 + N;     // + self loops = 163840
constexpr int H    = 4;
constexpr float NEG = 0.2f;

// ---------------------------- scratch (device globals) ---------------------
__device__ float   g_agg[(size_t)N * 512];   // L1 fp32 [N,64]; L2/L3 half (aliased)
__device__ float   g_hbuf[(size_t)N * 128];  // inter-layer activations (fp32)
__device__ __half2 g_hbufh2[(size_t)N * 64]; // half mirror of hbuf for L3 gathers
__device__ float   g_ssrc[N * H];
__device__ float   g_sdst[N * H];
__device__ float   g_etab[3][(T + 1) * H];
__device__ float   g_usrc[3][512];
__device__ float   g_udst[3][512];
__device__ float   g_wst1[64 * 32];          // L1 fp32 [H*K, dout]
__device__ __half  g_wst2[128 * 128];        // L2 half [dout, H*K] K-major
__device__ __half  g_wst3[512 * 512];        // L3 half [dout, H*K] K-major
__device__ int     g_se[E];                  // dst-sorted packed edges: src | (et<<20)
__device__ int     g_src[E], g_dst[E], g_et[E];
__device__ int     g_deg[N], g_rowptr[N + 1], g_fill[N];

// ---------------------------- graph build (CSR by dst) ---------------------
__global__ void k_build(const int* __restrict__ eit) {
    int e = blockIdx.x * blockDim.x + threadIdx.x;
    if (e >= E) return;
    int s, d, t;
    if (e < E0) {
        t = e / EPER;
        int i = e - t * EPER;
        s = eit[t * 2 * EPER + i];
        d = eit[t * 2 * EPER + EPER + i];
    } else {
        s = d = e - E0;
        t = T;
    }
    g_src[e] = s; g_dst[e] = d; g_et[e] = t;
    atomicAdd(&g_deg[d], 1);
}

// scan also RE-ZEROES g_deg so the next call starts clean (call-invariant).
__global__ void k_scan() {
    __shared__ int sh[1024];
    int t = threadIdx.x;
    int base = t * 32;
    int loc[32];
    int sum = 0;
#pragma unroll
    for (int i = 0; i < 32; i++) { loc[i] = sum; sum += g_deg[base + i]; g_deg[base + i] = 0; }
    sh[t] = sum;
    __syncthreads();
    for (int off = 1; off < 1024; off <<= 1) {
        int v = (t >= off) ? sh[t - off] : 0;
        __syncthreads();
        if (t >= off) sh[t] += v;
        __syncthreads();
    }
    int prev = (t == 0) ? 0 : sh[t - 1];
#pragma unroll
    for (int i = 0; i < 32; i++) {
        int v = prev + loc[i];
        g_rowptr[base + i] = v;
        g_fill[base + i]   = v;
    }
    if (t == 1023) g_rowptr[N] = sh[1023];
}

__global__ void k_scatter() {
    int e = blockIdx.x * blockDim.x + threadIdx.x;
    if (e >= E) return;
    int pos = atomicAdd(&g_fill[g_dst[e]], 1);
    g_se[pos] = g_src[e] | (g_et[e] << 20);
}

// ------------- ONE fused prep kernel for all three layers ------------------
__global__ void k_prep_all(
    const float* __restrict__ W1, const float* __restrict__ as1,
    const float* __restrict__ ad1, const float* __restrict__ We1,
    const float* __restrict__ ae1,
    const float* __restrict__ W2, const float* __restrict__ as2,
    const float* __restrict__ ad2, const float* __restrict__ We2,
    const float* __restrict__ ae2,
    const float* __restrict__ W3, const float* __restrict__ as3,
    const float* __restrict__ ad3, const float* __restrict__ We3,
    const float* __restrict__ ae3) {
    __shared__ float sh[T][H];
    int b = blockIdx.x, tid = threadIdx.x;
    if (b < 8) {
        int idx = b * 256 + tid;                 // 2048 = 64*32
        int d = idx % 32, hk = idx / 32;
        int h = hk / 16, k = hk % 16;
        g_wst1[idx] = W1[(size_t)k * 128 + h * 32 + d] * 0.25f;
    } else if (b < 72) {
        int idx = (b - 8) * 256 + tid;           // 16384 = 128*128
        int hk = idx % 128, d = idx / 128;
        int h = hk / 32, k = hk % 32;
        g_wst2[(size_t)d * 128 + hk] = __float2half(W2[(size_t)k * 512 + h * 128 + d] * 0.25f);
    } else if (b < 1096) {
        int idx = (b - 72) * 256 + tid;          // 262144 = 512*512
        int hk = idx % 512, d = idx / 512;
        int h = hk / 128, k = hk % 128;
        g_wst3[(size_t)d * 512 + hk] = __float2half(W3[(size_t)k * 2048 + h * 512 + d] * 0.25f);
    } else if (b < 1099) {
        int L = b - 1096;
        int K = (L == 0) ? 16 : (L == 1) ? 32 : 128;
        int dout = (L == 0) ? 32 : (L == 1) ? 128 : 512;
        const float* W  = (L == 0) ? W1  : (L == 1) ? W2  : W3;
        const float* as = (L == 0) ? as1 : (L == 1) ? as2 : as3;
        const float* ad = (L == 0) ? ad1 : (L == 1) ? ad2 : ad3;
        for (int idx = tid; idx < H * K; idx += 256) {
            int h = idx / K, k = idx % K;
            const float* wr = W + (size_t)k * (H * dout) + h * dout;
            float vs = 0.f, vd = 0.f;
            for (int d = 0; d < dout; d++) {
                vs += wr[d] * as[h * dout + d];
                vd += wr[d] * ad[h * dout + d];
            }
            g_usrc[L][idx] = vs;
            g_udst[L][idx] = vd;
        }
    } else {
        int L = b - 1099;
        int dout = (L == 0) ? 32 : (L == 1) ? 128 : 512;
        const float* We = (L == 0) ? We1 : (L == 1) ? We2 : We3;
        const float* ae = (L == 0) ? ae1 : (L == 1) ? ae2 : ae3;
        int HC = H * dout;
        if (tid < T * H) {
            int t = tid >> 2, h = tid & 3;
            float s = 0.f;
            for (int c = 0; c < dout; c++) s += We[t * HC + h * dout + c] * ae[h * dout + c];
            sh[t][h] = s;
            g_etab[L][t * H + h] = s;
        }
        __syncthreads();
        if (tid < H) {
            float s = 0.f;
            for (int t = 0; t < T; t++) s += sh[t][tid];
            g_etab[L][T * H + tid] = s * (1.0f / T);
        }
    }
}

// ---------------------------- L1 attention scores (from x, K=16) -----------
__global__ void k_scores(const float* __restrict__ h, int K, int L) {
    int gw = (blockIdx.x * blockDim.x + threadIdx.x) >> 5;
    int lane = threadIdx.x & 31;
    if (gw >= N) return;
    const float* row = h + (size_t)gw * K;
    float acc[2][H];
#pragma unroll
    for (int i = 0; i < 2; i++)
#pragma unroll
        for (int hh = 0; hh < H; hh++) acc[i][hh] = 0.f;
    for (int k = lane; k < K; k += 32) {
        float x = row[k];
#pragma unroll
        for (int hh = 0; hh < H; hh++) {
            acc[0][hh] += x * g_usrc[L][hh * K + k];
            acc[1][hh] += x * g_udst[L][hh * K + k];
        }
    }
#pragma unroll
    for (int i = 0; i < 2; i++)
#pragma unroll
        for (int hh = 0; hh < H; hh++)
#pragma unroll
            for (int o = 16; o > 0; o >>= 1)
                acc[i][hh] += __shfl_xor_sync(0xffffffffu, acc[i][hh], o);
    if (lane < H)      g_ssrc[gw * H + lane] = acc[0][lane];
    else if (lane < 2 * H) g_sdst[gw * H + (lane - H)] = acc[1][lane - H];
}

// ------- fused alpha + softmax + aggregation, K<=32 (warp per node) --------
template <int K, bool CVT>
__global__ void k_gat_edge(const float* __restrict__ h, float* __restrict__ aggf, int L) {
    constexpr int CAP = 128;
    __shared__ int   s_pk[4][CAP];
    __shared__ float s_aw[4][CAP][H];

    int lane = threadIdx.x & 31;
    int grp  = threadIdx.x >> 5;
    int n    = blockIdx.x * 4 + grp;
    int b0 = g_rowptr[n], b1 = g_rowptr[n + 1];
    int D = b1 - b0;

    float a0 = 0.f, a1 = 0.f, a2 = 0.f, a3 = 0.f;

    if (D <= CAP) {
        for (int j = lane; j < D; j += 32) s_pk[grp][j] = g_se[b0 + j];
        __syncwarp();
        {
            int hh = lane & 3;
            int j0 = lane >> 2;
            float sd = g_sdst[n * H + hh];
            float m = -1e30f, s = 0.f;
            for (int jj = j0; jj < D; jj += 8) {
                int p = s_pk[grp][jj];
                int src = p & 0xFFFFF, et = p >> 20;
                float a = g_ssrc[src * H + hh] + sd + g_etab[L][et * H + hh];
                a = (a > 0.f) ? a : NEG * a;
                s_aw[grp][jj][hh] = a;
                float mn = fmaxf(m, a);
                s = s * __expf(m - mn) + __expf(a - mn);
                m = mn;
            }
#pragma unroll
            for (int o = 4; o <= 16; o <<= 1) {
                float m2 = __shfl_xor_sync(0xffffffffu, m, o);
                float s2 = __shfl_xor_sync(0xffffffffu, s, o);
                float mn = fmaxf(m, m2);
                s = s * __expf(m - mn) + s2 * __expf(m2 - mn);
                m = mn;
            }
            float inv = 1.f / s;
            for (int jj = j0; jj < D; jj += 8)
                s_aw[grp][jj][hh] = __expf(s_aw[grp][jj][hh] - m) * inv;
        }
        __syncwarp();
        if (lane < K) {
            for (int jj = 0; jj < D; jj++) {
                int src = s_pk[grp][jj] & 0xFFFFF;
                float v = h[(size_t)src * K + lane];
                a0 += s_aw[grp][jj][0] * v;
                a1 += s_aw[grp][jj][1] * v;
                a2 += s_aw[grp][jj][2] * v;
                a3 += s_aw[grp][jj][3] * v;
            }
        }
    } else {
        int hh = lane & 3;
        int j0 = lane >> 2;
        float sd = g_sdst[n * H + hh];
        float m = -1e30f, s = 0.f;
        for (int jj = j0; jj < D; jj += 8) {
            int p = g_se[b0 + jj];
            int src = p & 0xFFFFF, et = p >> 20;
            float a = g_ssrc[src * H + hh] + sd + g_etab[L][et * H + hh];
            a = (a > 0.f) ? a : NEG * a;
            float mn = fmaxf(m, a);
            s = s * __expf(m - mn) + __expf(a - mn);
            m = mn;
        }
#pragma unroll
        for (int o = 4; o <= 16; o <<= 1) {
            float m2 = __shfl_xor_sync(0xffffffffu, m, o);
            float s2 = __shfl_xor_sync(0xffffffffu, s, o);
            float mn = fmaxf(m, m2);
            s = s * __expf(m - mn) + s2 * __expf(m2 - mn);
            m = mn;
        }
        float inv = 1.f / s;
        float m4[H], i4[H];
#pragma unroll
        for (int h4 = 0; h4 < H; h4++) {
            m4[h4] = __shfl_sync(0xffffffffu, m, h4);
            i4[h4] = __shfl_sync(0xffffffffu, inv, h4);
        }
        if (lane < K) {
            float sd4[H];
#pragma unroll
            for (int h4 = 0; h4 < H; h4++) sd4[h4] = g_sdst[n * H + h4];
            for (int jj = 0; jj < D; jj++) {
                int p = g_se[b0 + jj];
                int src = p & 0xFFFFF, et = p >> 20;
                float v = h[(size_t)src * K + lane];
#pragma unroll
                for (int h4 = 0; h4 < H; h4++) {
                    float a = g_ssrc[src * H + h4] + sd4[h4] + g_etab[L][et * H + h4];
                    a = (a > 0.f) ? a : NEG * a;
                    float w = __expf(a - m4[h4]) * i4[h4];
                    if (h4 == 0) a0 += w * v;
                    else if (h4 == 1) a1 += w * v;
                    else if (h4 == 2) a2 += w * v;
                    else a3 += w * v;
                }
            }
        }
    }

    if (lane < K) {
        size_t base = (size_t)n * (H * K) + lane;
        if (CVT) {
            __half* ah = reinterpret_cast<__half*>(aggf);
            ah[base]         = __float2half(a0);
            ah[base + K]     = __float2half(a1);
            ah[base + 2 * K] = __float2half(a2);
            ah[base + 3 * K] = __float2half(a3);
        } else {
            aggf[base]         = a0;
            aggf[base + K]     = a1;
            aggf[base + 2 * K] = a2;
            aggf[base + 3 * K] = a3;
        }
    }
}

// ------- L3 edge kernel: 2 nodes per 128-thr block, half2 gathers ----------
__global__ void k_gat_edge3(const __half2* __restrict__ h2, __half2* __restrict__ agg2) {
    constexpr int CAP = 128;
    __shared__ int   s_pk[2][CAP];
    __shared__ float s_aw[2][CAP][H];
    __shared__ float s_ms[2][2][H];

    int grp  = threadIdx.x >> 6;
    int gtid = threadIdx.x & 63;
    int lane = threadIdx.x & 31;
    int wing = (threadIdx.x >> 5) & 1;
    int n = blockIdx.x * 2 + grp;
    int b0 = g_rowptr[n], b1 = g_rowptr[n + 1];
    int D = b1 - b0;
    bool fast = (D <= CAP);

    if (fast)
        for (int j = gtid; j < D; j += 64) s_pk[grp][j] = g_se[b0 + j];
    __syncthreads();

    if (wing == 0) {
        int hh = lane & 3;
        int j0 = lane >> 2;
        float sd = g_sdst[n * H + hh];
        float m = -1e30f, s = 0.f;
        if (fast) {
            for (int jj = j0; jj < D; jj += 8) {
                int p = s_pk[grp][jj];
                int src = p & 0xFFFFF, et = p >> 20;
                float a = g_ssrc[src * H + hh] + sd + g_etab[2][et * H + hh];
                a = (a > 0.f) ? a : NEG * a;
                s_aw[grp][jj][hh] = a;
                float mn = fmaxf(m, a);
                s = s * __expf(m - mn) + __expf(a - mn);
                m = mn;
            }
        } else {
            for (int jj = j0; jj < D; jj += 8) {
                int p = g_se[b0 + jj];
                int src = p & 0xFFFFF, et = p >> 20;
                float a = g_ssrc[src * H + hh] + sd + g_etab[2][et * H + hh];
                a = (a > 0.f) ? a : NEG * a;
                float mn = fmaxf(m, a);
                s = s * __expf(m - mn) + __expf(a - mn);
                m = mn;
            }
        }
#pragma unroll
        for (int o = 4; o <= 16; o <<= 1) {
            float m2 = __shfl_xor_sync(0xffffffffu, m, o);
            float s2 = __shfl_xor_sync(0xffffffffu, s, o);
            float mn = fmaxf(m, m2);
            s = s * __expf(m - mn) + s2 * __expf(m2 - mn);
            m = mn;
        }
        float inv = 1.f / s;
        if (fast) {
            for (int jj = j0; jj < D; jj += 8)
                s_aw[grp][jj][hh] = __expf(s_aw[grp][jj][hh] - m) * inv;
        } else if (lane < H) {
            s_ms[grp][0][lane] = m;
            s_ms[grp][1][lane] = inv;
        }
    }
    __syncthreads();

    float ax[H], ay[H];
#pragma unroll
    for (int h4 = 0; h4 < H; h4++) { ax[h4] = 0.f; ay[h4] = 0.f; }

    if (fast) {
        for (int jj = 0; jj < D; jj++) {
            int src = s_pk[grp][jj] & 0xFFFFF;
            float2 v = __half22float2(h2[(size_t)src * 64 + gtid]);
#pragma unroll
            for (int h4 = 0; h4 < H; h4++) {
                float w = s_aw[grp][jj][h4];
                ax[h4] += w * v.x;
                ay[h4] += w * v.y;
            }
        }
    } else {
        float m4[H], i4[H], sd4[H];
#pragma unroll
        for (int h4 = 0; h4 < H; h4++) {
            m4[h4] = s_ms[grp][0][h4];
            i4[h4] = s_ms[grp][1][h4];
            sd4[h4] = g_sdst[n * H + h4];
        }
        for (int jj = 0; jj < D; jj++) {
            int p = g_se[b0 + jj];
            int src = p & 0xFFFFF, et = p >> 20;
            float2 v = __half22float2(h2[(size_t)src * 64 + gtid]);
#pragma unroll
            for (int h4 = 0; h4 < H; h4++) {
                float a = g_ssrc[src * H + h4] + sd4[h4] + g_etab[2][et * H + h4];
                a = (a > 0.f) ? a : NEG * a;
                float w = __expf(a - m4[h4]) * i4[h4];
                ax[h4] += w * v.x;
                ay[h4] += w * v.y;
            }
        }
    }

    size_t base = (size_t)n * 256 + gtid;
#pragma unroll
    for (int h4 = 0; h4 < H; h4++)
        agg2[base + h4 * 64] = __floats2half2_rn(ax[h4], ay[h4]);
}

// --- L1 GEMM (warp = node) + FUSED layer-2 scores (butterfly reduction) ----
__global__ void k_gemm_small(const float* __restrict__ A, const float* __restrict__ B,
                             const float* __restrict__ bias, float* __restrict__ C) {
    constexpr int K = 64, NN = 32;
    int idx = blockIdx.x * blockDim.x + threadIdx.x;
    int n = idx >> 5, lane = idx & 31;     // warp = node, lane = out channel
    if (n >= N) return;
    const float* ar = A + (size_t)n * K;
    float acc = 0.f;
    for (int k = 0; k < K; k++) acc += ar[k] * B[k * NN + lane];
    acc += bias[lane];
    acc = fmaxf(acc, 0.f);
    C[(size_t)n * NN + lane] = acc;

    // fused layer-2 scores: s[h] = sum_d acc_d * U[1][h*32+d]
    float rs[H], rd[H];
#pragma unroll
    for (int h = 0; h < H; h++) {
        rs[h] = acc * g_usrc[1][h * 32 + lane];
        rd[h] = acc * g_udst[1][h * 32 + lane];
#pragma unroll
        for (int o = 16; o > 0; o >>= 1) {
            rs[h] += __shfl_xor_sync(0xffffffffu, rs[h], o);
            rd[h] += __shfl_xor_sync(0xffffffffu, rd[h], o);
        }
    }
    if (lane == 0) {
#pragma unroll
        for (int h = 0; h < H; h++) {
            g_ssrc[n * H + h] = rs[h];
            g_sdst[n * H + h] = rd[h];
        }
    }
}

// ------- fp16 TC GEMM: 128x128x32 tiles, 3-stage cp.async ring -------------
// Optional fused next-layer scores (requires grid.x == 1): Usrc/Udst != null.
constexpr int STG_BYTES = 128 * 40 * 2 * 2;    // A+B per stage = 20480 B
constexpr int SMEM_HF   = 3 * STG_BYTES;       // 61440 B

__device__ __forceinline__ uint32_t smem_u32(const void* p) {
    uint32_t a;
    asm("{ .reg .u64 t; cvta.to.shared.u64 t, %1; cvt.u32.u64 %0, t; }" : "=r"(a) : "l"(p));
    return a;
}

__global__ void __launch_bounds__(256, 2)
k_gemm_hf(const __half* __restrict__ A, const __half* __restrict__ Bt,
          const float* __restrict__ bias, float* __restrict__ C,
          __half2* __restrict__ Ch2, const float* __restrict__ Usrc,
          const float* __restrict__ Udst, int K, int NN, int relu) {
    extern __shared__ char hsm[];
    int tid = threadIdx.x;
    int wid = tid >> 5, lane = tid & 31;
    int bm = blockIdx.y * 128, bn = blockIdx.x * 128;
    int wm = (wid >> 2) * 64;
    int wn = (wid & 3) * 32;
    int grp = lane >> 2, tig = lane & 3;

    auto stA = [&](int s) { return reinterpret_cast<__half*>(hsm + s * STG_BYTES); };
    auto stB = [&](int s) { return reinterpret_cast<__half*>(hsm + s * STG_BYTES) + 128 * 40; };

    float c[4][4][4];
#pragma unroll
    for (int mt = 0; mt < 4; mt++)
#pragma unroll
        for (int nt = 0; nt < 4; nt++)
#pragma unroll
            for (int q = 0; q < 4; q++) c[mt][nt][q] = 0.f;

    int nk = K >> 5;

    auto copy_tile = [&](int s, int k0) {
        __half* As = stA(s);
        __half* Bs = stB(s);
#pragma unroll
        for (int i = 0; i < 2; i++) {
            int f = tid + i * 256;
            int m = f >> 2, q = f & 3;
            uint32_t dst = smem_u32(&As[m * 40 + q * 8]);
            const __half* src = &A[(size_t)(bm + m) * K + k0 + q * 8];
            asm volatile("cp.async.ca.shared.global [%0], [%1], 16;" :: "r"(dst), "l"(src));
        }
#pragma unroll
        for (int i = 0; i < 2; i++) {
            int f = tid + i * 256;
            int nrow = f >> 2, q = f & 3;
            uint32_t dst = smem_u32(&Bs[nrow * 40 + q * 8]);
            const __half* src = &Bt[(size_t)(bn + nrow) * K + k0 + q * 8];
            asm volatile("cp.async.ca.shared.global [%0], [%1], 16;" :: "r"(dst), "l"(src));
        }
        asm volatile("cp.async.commit_group;");
    };

    copy_tile(0, 0);
    copy_tile(1, 32);

    int mtx = lane >> 3;
    int rin = lane & 7;

    for (int it = 0; it < nk; it++) {
        int cur = it % 3;
        if (it + 1 < nk) asm volatile("cp.async.wait_group 1;");
        else             asm volatile("cp.async.wait_group 0;");
        __syncthreads();
        if (it + 2 < nk) copy_tile((it + 2) % 3, (it + 2) * 32);

        __half* As = stA(cur);
        __half* Bs = stB(cur);
#pragma unroll
        for (int ks = 0; ks < 2; ks++) {
            uint32_t a[4][4], b[4][2];
#pragma unroll
            for (int mt = 0; mt < 4; mt++) {
                int row = wm + mt * 16 + (mtx & 1) * 8 + rin;
                int col = ks * 16 + (mtx >> 1) * 8;
                uint32_t addr = smem_u32(&As[row * 40 + col]);
                asm volatile("ldmatrix.sync.aligned.m8n8.x4.shared.b16 {%0,%1,%2,%3}, [%4];"
                             : "=r"(a[mt][0]), "=r"(a[mt][1]), "=r"(a[mt][2]), "=r"(a[mt][3])
                             : "r"(addr));
            }
#pragma unroll
            for (int np = 0; np < 2; np++) {
                int row = wn + np * 16 + (mtx >> 1) * 8 + rin;
                int col = ks * 16 + (mtx & 1) * 8;
                uint32_t addr = smem_u32(&Bs[row * 40 + col]);
                asm volatile("ldmatrix.sync.aligned.m8n8.x4.shared.b16 {%0,%1,%2,%3}, [%4];"
                             : "=r"(b[np * 2][0]), "=r"(b[np * 2][1]),
                               "=r"(b[np * 2 + 1][0]), "=r"(b[np * 2 + 1][1])
                             : "r"(addr));
            }
#pragma unroll
            for (int mt = 0; mt < 4; mt++)
#pragma unroll
                for (int nt = 0; nt < 4; nt++) {
                    asm volatile(
                        "mma.sync.aligned.m16n8k16.row.col.f32.f16.f16.f32 "
                        "{%0,%1,%2,%3}, {%4,%5,%6,%7}, {%8,%9}, {%0,%1,%2,%3};"
                        : "+f"(c[mt][nt][0]), "+f"(c[mt][nt][1]),
                          "+f"(c[mt][nt][2]), "+f"(c[mt][nt][3])
                        : "r"(a[mt][0]), "r"(a[mt][1]), "r"(a[mt][2]), "r"(a[mt][3]),
                          "r"(b[nt][0]), "r"(b[nt][1]));
                }
        }
        __syncthreads();
    }

    // per-thread bias cache (cols fixed per thread)
    float bv[4][2];
#pragma unroll
    for (int nt = 0; nt < 4; nt++) {
        int col = bn + wn + nt * 8 + tig * 2;
        bv[nt][0] = bias[col];
        bv[nt][1] = bias[col + 1];
    }

#pragma unroll
    for (int mt = 0; mt < 4; mt++) {
#pragma unroll
        for (int nt = 0; nt < 4; nt++) {
            int col = bn + wn + nt * 8 + tig * 2;
            int r0 = bm + wm + mt * 16 + grp;
            float v00 = c[mt][nt][0] + bv[nt][0], v01 = c[mt][nt][1] + bv[nt][1];
            float v10 = c[mt][nt][2] + bv[nt][0], v11 = c[mt][nt][3] + bv[nt][1];
            if (relu) {
                v00 = fmaxf(v00, 0.f); v01 = fmaxf(v01, 0.f);
                v10 = fmaxf(v10, 0.f); v11 = fmaxf(v11, 0.f);
            }
            C[(size_t)r0 * NN + col]           = v00;
            C[(size_t)r0 * NN + col + 1]       = v01;
            C[(size_t)(r0 + 8) * NN + col]     = v10;
            C[(size_t)(r0 + 8) * NN + col + 1] = v11;
            if (Ch2) {
                Ch2[((size_t)r0 * NN + col) >> 1]       = __floats2half2_rn(v00, v01);
                Ch2[((size_t)(r0 + 8) * NN + col) >> 1] = __floats2half2_rn(v10, v11);
            }
        }
    }

    // ---- fused next-layer scores (grid.x==1 path): s[r][h] over full row --
    if (Usrc) {
        float* s_sc = reinterpret_cast<float*>(hsm);   // [128][8]: 4 src + 4 dst
        for (int i = tid; i < 128 * 8; i += 256) s_sc[i] = 0.f;
        __syncthreads();
#pragma unroll
        for (int h8 = 0; h8 < 8; h8++) {
            const float* U = (h8 < 4) ? (Usrc + h8 * NN) : (Udst + (h8 - 4) * NN);
            float u[4][2];
#pragma unroll
            for (int nt = 0; nt < 4; nt++) {
                int col = wn + nt * 8 + tig * 2;
                u[nt][0] = U[col];
                u[nt][1] = U[col + 1];
            }
#pragma unroll
            for (int mt = 0; mt < 4; mt++) {
                int r0 = wm + mt * 16 + grp;
                float p0 = 0.f, p1 = 0.f;
#pragma unroll
                for (int nt = 0; nt < 4; nt++) {
                    float v00 = c[mt][nt][0] + bv[nt][0], v01 = c[mt][nt][1] + bv[nt][1];
                    float v10 = c[mt][nt][2] + bv[nt][0], v11 = c[mt][nt][3] + bv[nt][1];
                    if (relu) {
                        v00 = fmaxf(v00, 0.f); v01 = fmaxf(v01, 0.f);
                        v10 = fmaxf(v10, 0.f); v11 = fmaxf(v11, 0.f);
                    }
                    p0 += v00 * u[nt][0] + v01 * u[nt][1];
                    p1 += v10 * u[nt][0] + v11 * u[nt][1];
                }
                // sum over tig quad (lanes differing in bits 0,1)
                p0 += __shfl_xor_sync(0xffffffffu, p0, 1);
                p0 += __shfl_xor_sync(0xffffffffu, p0, 2);
                p1 += __shfl_xor_sync(0xffffffffu, p1, 1);
                p1 += __shfl_xor_sync(0xffffffffu, p1, 2);
                if (tig == 0) {
                    atomicAdd(&s_sc[r0 * 8 + h8], p0);
                    atomicAdd(&s_sc[(r0 + 8) * 8 + h8], p1);
                }
            }
        }
        __syncthreads();
        for (int i = tid; i < 128 * 8; i += 256) {
            int r = i >> 3, h8 = i & 7;
            float v = s_sc[i];
            if (h8 < 4) g_ssrc[(bm + r) * H + h8] = v;
            else        g_sdst[(bm + r) * H + (h8 - 4)] = v;
        }
    }
}

// ---------------------------------------------------------------------------
extern "C" void kernel_launch(void* const* d_in, const int* in_sizes, int n_in,
                              void* d_out, int out_size) {
    const float* x   = (const float*)d_in[0];
    const int*   eit = (const int*)d_in[1];
    const float* W1  = (const float*)d_in[2];
    const float* We1 = (const float*)d_in[3];
    const float* as1 = (const float*)d_in[4];
    const float* ad1 = (const float*)d_in[5];
    const float* ae1 = (const float*)d_in[6];
    const float* b1  = (const float*)d_in[7];
    const float* W2  = (const float*)d_in[8];
    const float* We2 = (const float*)d_in[9];
    const float* as2 = (const float*)d_in[10];
    const float* ad2 = (const float*)d_in[11];
    const float* ae2 = (const float*)d_in[12];
    const float* b2  = (const float*)d_in[13];
    const float* W3  = (const float*)d_in[14];
    const float* We3 = (const float*)d_in[15];
    const float* as3 = (const float*)d_in[16];
    const float* ad3 = (const float*)d_in[17];
    const float* ae3 = (const float*)d_in[18];
    const float* b3  = (const float*)d_in[19];
    float* out = (float*)d_out;

    float *agg = nullptr, *hbuf = nullptr, *wst1 = nullptr;
    float *usrc = nullptr, *udst = nullptr;
    __half *wst2 = nullptr, *wst3 = nullptr;
    __half2 *hbufh2 = nullptr;
    cudaGetSymbolAddress((void**)&agg, g_agg);
    cudaGetSymbolAddress((void**)&hbuf, g_hbuf);
    cudaGetSymbolAddress((void**)&wst1, g_wst1);
    cudaGetSymbolAddress((void**)&wst2, g_wst2);
    cudaGetSymbolAddress((void**)&wst3, g_wst3);
    cudaGetSymbolAddress((void**)&hbufh2, g_hbufh2);
    cudaGetSymbolAddress((void**)&usrc, g_usrc);
    cudaGetSymbolAddress((void**)&udst, g_udst);
    const __half* aggh = (const __half*)agg;
    __half2* agg2 = (__half2*)agg;

    cudaFuncSetAttribute(k_gemm_hf, cudaFuncAttributeMaxDynamicSharedMemorySize, SMEM_HF);

    // ---- graph build + fused prep (g_deg re-zeroed by k_scan each call) ---
    k_build<<<E / 256, 256>>>(eit);
    k_scan<<<1, 1024>>>();
    k_scatter<<<E / 256, 256>>>();
    k_prep_all<<<1102, 256>>>(W1, as1, ad1, We1, ae1,
                              W2, as2, ad2, We2, ae2,
                              W3, as3, ad3, We3, ae3);

    // ---- layer 1: K=16 -> dout=32 (SIMT; gemm fuses L2 scores) ----
    k_scores<<<N / 8, 256>>>(x, 16, 0);
    k_gat_edge<16, false><<<N / 4, 128>>>(x, agg, 0);
    k_gemm_small<<<(N * 32) / 256, 256>>>(agg, wst1, b1, hbuf);

    // ---- layer 2: K=32 -> dout=128 (TC GEMM fuses L3 scores + half2 out) --
    k_gat_edge<32, true><<<N / 4, 128>>>(hbuf, agg, 1);
    k_gemm_hf<<<dim3(1, N / 128), 256, SMEM_HF>>>(aggh, wst2, b2, hbuf, hbufh2,
                                                  usrc + 2 * 512, udst + 2 * 512, 128, 128, 1);

    // ---- layer 3: K=128 -> dout=512 (half2 gathers; TC GEMM -> out) -------
    k_gat_edge3<<<N / 2, 128>>>(hbufh2, agg2);
    k_gemm_hf<<<dim3(4, N / 128), 256, SMEM_HF>>>(aggh, wst3, b3, out, nullptr,
                                                  nullptr, nullptr, 512, 512, 0);
}

// round 11
// speedup vs baseline: 1.3500x; 1.3500x over previous
#include <cuda_runtime.h>
#include <cuda_fp16.h>
#include <cstdint>

constexpr int N    = 32768;
constexpr int EPER = 16384;
constexpr int T    = 8;
constexpr int E0   = T * EPER;   // 131072 typed edges
constexpr int E    = E0 + N;     // + self loops = 163840
constexpr int H    = 4;
constexpr float NEG = 0.2f;

// ---------------------------- scratch (device globals) ---------------------
__device__ float   g_agg[(size_t)N * 512];   // L1 fp32 [N,64]; L2/L3 half (aliased)
__device__ float   g_hbuf[(size_t)N * 128];  // inter-layer activations (fp32)
__device__ __half2 g_hbufh2[(size_t)N * 64]; // half mirror of hbuf for L3 gathers
__device__ float   g_ssrc[N * H];
__device__ float   g_sdst[N * H];
__device__ float   g_etab[3][(T + 1) * H];
__device__ float   g_usrc[3][512];
__device__ float   g_udst[3][512];
__device__ float   g_wst1[64 * 32];          // L1 fp32 [H*K, dout]
__device__ __half  g_wst2[128 * 128];        // L2 half [dout, H*K] K-major
__device__ __half  g_wst3[512 * 512];        // L3 half [dout, H*K] K-major
__device__ int     g_se[E];                  // dst-sorted packed edges: src | (et<<20)
__device__ int     g_src[E], g_dst[E], g_et[E];
__device__ int     g_deg[N], g_rowptr[N + 1], g_fill[N];

// ---------------------------- graph build (CSR by dst) ---------------------
__global__ void k_build(const int* __restrict__ eit) {
    int e = blockIdx.x * blockDim.x + threadIdx.x;
    if (e >= E) return;
    int s, d, t;
    if (e < E0) {
        t = e / EPER;
        int i = e - t * EPER;
        s = eit[t * 2 * EPER + i];
        d = eit[t * 2 * EPER + EPER + i];
    } else {
        s = d = e - E0;
        t = T;
    }
    g_src[e] = s; g_dst[e] = d; g_et[e] = t;
    atomicAdd(&g_deg[d], 1);
}

// scan also RE-ZEROES g_deg so the next call starts clean (call-invariant).
__global__ void k_scan() {
    __shared__ int sh[1024];
    int t = threadIdx.x;
    int base = t * 32;
    int loc[32];
    int sum = 0;
#pragma unroll
    for (int i = 0; i < 32; i++) { loc[i] = sum; sum += g_deg[base + i]; g_deg[base + i] = 0; }
    sh[t] = sum;
    __syncthreads();
    for (int off = 1; off < 1024; off <<= 1) {
        int v = (t >= off) ? sh[t - off] : 0;
        __syncthreads();
        if (t >= off) sh[t] += v;
        __syncthreads();
    }
    int prev = (t == 0) ? 0 : sh[t - 1];
#pragma unroll
    for (int i = 0; i < 32; i++) {
        int v = prev + loc[i];
        g_rowptr[base + i] = v;
        g_fill[base + i]   = v;
    }
    if (t == 1023) g_rowptr[N] = sh[1023];
}

__global__ void k_scatter() {
    int e = blockIdx.x * blockDim.x + threadIdx.x;
    if (e >= E) return;
    int pos = atomicAdd(&g_fill[g_dst[e]], 1);
    g_se[pos] = g_src[e] | (g_et[e] << 20);
}

// ------------- ONE fused prep kernel, latency-optimized --------------------
// blocks [0,8): wst1 copy             (coalesced both sides)
// [8,72): wst2 transpose, d-major     (coalesced loads, scattered 2B stores)
// [72,1096): wst3 transpose, d-major  (coalesced loads, scattered 2B stores)
// [1096,1184): U vectors, WARP PER ENTRY (704 warps: 64 + 128 + 512)
// [1184,1187): edge tables, WARP PER (t,h) ENTRY + mean reduce
__global__ void k_prep_all(
    const float* __restrict__ W1, const float* __restrict__ as1,
    const float* __restrict__ ad1, const float* __restrict__ We1,
    const float* __restrict__ ae1,
    const float* __restrict__ W2, const float* __restrict__ as2,
    const float* __restrict__ ad2, const float* __restrict__ We2,
    const float* __restrict__ ae2,
    const float* __restrict__ W3, const float* __restrict__ as3,
    const float* __restrict__ ad3, const float* __restrict__ We3,
    const float* __restrict__ ae3) {
    __shared__ float sh[T + 1][H];
    int b = blockIdx.x, tid = threadIdx.x;
    if (b < 8) {
        int idx = b * 256 + tid;                 // 2048 = 64*32, d-contiguous
        int d = idx % 32, hk = idx / 32;
        int h = hk / 16, k = hk % 16;
        g_wst1[idx] = W1[(size_t)k * 128 + h * 32 + d] * 0.25f;
    } else if (b < 72) {
        int idx = (b - 8) * 256 + tid;           // 16384 = 128*128
        int d = idx & 127, hk = idx >> 7;        // d-contiguous -> coalesced load
        int h = hk >> 5, k = hk & 31;
        g_wst2[(size_t)d * 128 + hk] = __float2half(W2[(size_t)k * 512 + h * 128 + d] * 0.25f);
    } else if (b < 1096) {
        int idx = (b - 72) * 256 + tid;          // 262144 = 512*512
        int d = idx & 511, hk = idx >> 9;        // d-contiguous -> coalesced load
        int h = hk >> 7, k = hk & 127;
        g_wst3[(size_t)d * 512 + hk] = __float2half(W3[(size_t)k * 2048 + h * 512 + d] * 0.25f);
    } else if (b < 1184) {
        // warp per U entry: global warp id in [0, 704)
        int gw = (b - 1096) * 8 + (tid >> 5);
        int lane = tid & 31;
        int L, e;
        if (gw < 64)       { L = 0; e = gw; }
        else if (gw < 192) { L = 1; e = gw - 64; }
        else               { L = 2; e = gw - 192; }
        if (L == 2 && e >= 512) return;
        int K    = (L == 0) ? 16 : (L == 1) ? 32 : 128;
        int dout = (L == 0) ? 32 : (L == 1) ? 128 : 512;
        const float* W  = (L == 0) ? W1  : (L == 1) ? W2  : W3;
        const float* as = (L == 0) ? as1 : (L == 1) ? as2 : as3;
        const float* ad = (L == 0) ? ad1 : (L == 1) ? ad2 : ad3;
        int h = e / K, k = e % K;
        const float* wr = W + (size_t)k * (H * dout) + h * dout;
        float vs = 0.f, vd = 0.f;
        for (int d = lane; d < dout; d += 32) {
            float w = wr[d];
            vs += w * as[h * dout + d];
            vd += w * ad[h * dout + d];
        }
#pragma unroll
        for (int o = 16; o > 0; o >>= 1) {
            vs += __shfl_xor_sync(0xffffffffu, vs, o);
            vd += __shfl_xor_sync(0xffffffffu, vd, o);
        }
        if (lane == 0) {
            g_usrc[L][e] = vs;
            g_udst[L][e] = vd;
        }
    } else {
        // edge table for layer L: warp per (t,h) entry (8 warps x 4 entries)
        int L = b - 1184;
        int dout = (L == 0) ? 32 : (L == 1) ? 128 : 512;
        const float* We = (L == 0) ? We1 : (L == 1) ? We2 : We3;
        const float* ae = (L == 0) ? ae1 : (L == 1) ? ae2 : ae3;
        int HC = H * dout;
        int wrp = tid >> 5, lane = tid & 31;
#pragma unroll
        for (int i = 0; i < 4; i++) {
            int e = wrp * 4 + i;                // 0..31 = (t,h)
            int t = e >> 2, h = e & 3;
            float s = 0.f;
            for (int c = lane; c < dout; c += 32)
                s += We[t * HC + h * dout + c] * ae[h * dout + c];
#pragma unroll
            for (int o = 16; o > 0; o >>= 1)
                s += __shfl_xor_sync(0xffffffffu, s, o);
            if (lane == 0) {
                sh[t][h] = s;
                g_etab[L][t * H + h] = s;
            }
        }
        __syncthreads();
        if (tid < H) {
            float s = 0.f;
            for (int t = 0; t < T; t++) s += sh[t][tid];
            g_etab[L][T * H + tid] = s * (1.0f / T);
        }
    }
}

// ---------------------------- L1 attention scores (from x, K=16) -----------
__global__ void k_scores(const float* __restrict__ h, int K, int L) {
    int gw = (blockIdx.x * blockDim.x + threadIdx.x) >> 5;
    int lane = threadIdx.x & 31;
    if (gw >= N) return;
    const float* row = h + (size_t)gw * K;
    float acc[2][H];
#pragma unroll
    for (int i = 0; i < 2; i++)
#pragma unroll
        for (int hh = 0; hh < H; hh++) acc[i][hh] = 0.f;
    for (int k = lane; k < K; k += 32) {
        float x = row[k];
#pragma unroll
        for (int hh = 0; hh < H; hh++) {
            acc[0][hh] += x * g_usrc[L][hh * K + k];
            acc[1][hh] += x * g_udst[L][hh * K + k];
        }
    }
#pragma unroll
    for (int i = 0; i < 2; i++)
#pragma unroll
        for (int hh = 0; hh < H; hh++)
#pragma unroll
            for (int o = 16; o > 0; o >>= 1)
                acc[i][hh] += __shfl_xor_sync(0xffffffffu, acc[i][hh], o);
    if (lane < H)      g_ssrc[gw * H + lane] = acc[0][lane];
    else if (lane < 2 * H) g_sdst[gw * H + (lane - H)] = acc[1][lane - H];
}

// ------- fused alpha + softmax + aggregation, K<=32 (warp per node) --------
template <int K, bool CVT>
__global__ void k_gat_edge(const float* __restrict__ h, float* __restrict__ aggf, int L) {
    constexpr int CAP = 128;
    __shared__ int   s_pk[4][CAP];
    __shared__ float s_aw[4][CAP][H];

    int lane = threadIdx.x & 31;
    int grp  = threadIdx.x >> 5;
    int n    = blockIdx.x * 4 + grp;
    int b0 = g_rowptr[n], b1 = g_rowptr[n + 1];
    int D = b1 - b0;

    float a0 = 0.f, a1 = 0.f, a2 = 0.f, a3 = 0.f;

    if (D <= CAP) {
        for (int j = lane; j < D; j += 32) s_pk[grp][j] = g_se[b0 + j];
        __syncwarp();
        {
            int hh = lane & 3;
            int j0 = lane >> 2;
            float sd = g_sdst[n * H + hh];
            float m = -1e30f, s = 0.f;
            for (int jj = j0; jj < D; jj += 8) {
                int p = s_pk[grp][jj];
                int src = p & 0xFFFFF, et = p >> 20;
                float a = g_ssrc[src * H + hh] + sd + g_etab[L][et * H + hh];
                a = (a > 0.f) ? a : NEG * a;
                s_aw[grp][jj][hh] = a;
                float mn = fmaxf(m, a);
                s = s * __expf(m - mn) + __expf(a - mn);
                m = mn;
            }
#pragma unroll
            for (int o = 4; o <= 16; o <<= 1) {
                float m2 = __shfl_xor_sync(0xffffffffu, m, o);
                float s2 = __shfl_xor_sync(0xffffffffu, s, o);
                float mn = fmaxf(m, m2);
                s = s * __expf(m - mn) + s2 * __expf(m2 - mn);
                m = mn;
            }
            float inv = 1.f / s;
            for (int jj = j0; jj < D; jj += 8)
                s_aw[grp][jj][hh] = __expf(s_aw[grp][jj][hh] - m) * inv;
        }
        __syncwarp();
        if (lane < K) {
            for (int jj = 0; jj < D; jj++) {
                int src = s_pk[grp][jj] & 0xFFFFF;
                float v = h[(size_t)src * K + lane];
                a0 += s_aw[grp][jj][0] * v;
                a1 += s_aw[grp][jj][1] * v;
                a2 += s_aw[grp][jj][2] * v;
                a3 += s_aw[grp][jj][3] * v;
            }
        }
    } else {
        int hh = lane & 3;
        int j0 = lane >> 2;
        float sd = g_sdst[n * H + hh];
        float m = -1e30f, s = 0.f;
        for (int jj = j0; jj < D; jj += 8) {
            int p = g_se[b0 + jj];
            int src = p & 0xFFFFF, et = p >> 20;
            float a = g_ssrc[src * H + hh] + sd + g_etab[L][et * H + hh];
            a = (a > 0.f) ? a : NEG * a;
            float mn = fmaxf(m, a);
            s = s * __expf(m - mn) + __expf(a - mn);
            m = mn;
        }
#pragma unroll
        for (int o = 4; o <= 16; o <<= 1) {
            float m2 = __shfl_xor_sync(0xffffffffu, m, o);
            float s2 = __shfl_xor_sync(0xffffffffu, s, o);
            float mn = fmaxf(m, m2);
            s = s * __expf(m - mn) + s2 * __expf(m2 - mn);
            m = mn;
        }
        float inv = 1.f / s;
        float m4[H], i4[H];
#pragma unroll
        for (int h4 = 0; h4 < H; h4++) {
            m4[h4] = __shfl_sync(0xffffffffu, m, h4);
            i4[h4] = __shfl_sync(0xffffffffu, inv, h4);
        }
        if (lane < K) {
            float sd4[H];
#pragma unroll
            for (int h4 = 0; h4 < H; h4++) sd4[h4] = g_sdst[n * H + h4];
            for (int jj = 0; jj < D; jj++) {
                int p = g_se[b0 + jj];
                int src = p & 0xFFFFF, et = p >> 20;
                float v = h[(size_t)src * K + lane];
#pragma unroll
                for (int h4 = 0; h4 < H; h4++) {
                    float a = g_ssrc[src * H + h4] + sd4[h4] + g_etab[L][et * H + h4];
                    a = (a > 0.f) ? a : NEG * a;
                    float w = __expf(a - m4[h4]) * i4[h4];
                    if (h4 == 0) a0 += w * v;
                    else if (h4 == 1) a1 += w * v;
                    else if (h4 == 2) a2 += w * v;
                    else a3 += w * v;
                }
            }
        }
    }

    if (lane < K) {
        size_t base = (size_t)n * (H * K) + lane;
        if (CVT) {
            __half* ah = reinterpret_cast<__half*>(aggf);
            ah[base]         = __float2half(a0);
            ah[base + K]     = __float2half(a1);
            ah[base + 2 * K] = __float2half(a2);
            ah[base + 3 * K] = __float2half(a3);
        } else {
            aggf[base]         = a0;
            aggf[base + K]     = a1;
            aggf[base + 2 * K] = a2;
            aggf[base + 3 * K] = a3;
        }
    }
}

// ------- L3 edge kernel: 2 nodes per 128-thr block, half2 gathers ----------
__global__ void k_gat_edge3(const __half2* __restrict__ h2, __half2* __restrict__ agg2) {
    constexpr int CAP = 128;
    __shared__ int   s_pk[2][CAP];
    __shared__ float s_aw[2][CAP][H];
    __shared__ float s_ms[2][2][H];

    int grp  = threadIdx.x >> 6;
    int gtid = threadIdx.x & 63;
    int lane = threadIdx.x & 31;
    int wing = (threadIdx.x >> 5) & 1;
    int n = blockIdx.x * 2 + grp;
    int b0 = g_rowptr[n], b1 = g_rowptr[n + 1];
    int D = b1 - b0;
    bool fast = (D <= CAP);

    if (fast)
        for (int j = gtid; j < D; j += 64) s_pk[grp][j] = g_se[b0 + j];
    __syncthreads();

    if (wing == 0) {
        int hh = lane & 3;
        int j0 = lane >> 2;
        float sd = g_sdst[n * H + hh];
        float m = -1e30f, s = 0.f;
        if (fast) {
            for (int jj = j0; jj < D; jj += 8) {
                int p = s_pk[grp][jj];
                int src = p & 0xFFFFF, et = p >> 20;
                float a = g_ssrc[src * H + hh] + sd + g_etab[2][et * H + hh];
                a = (a > 0.f) ? a : NEG * a;
                s_aw[grp][jj][hh] = a;
                float mn = fmaxf(m, a);
                s = s * __expf(m - mn) + __expf(a - mn);
                m = mn;
            }
        } else {
            for (int jj = j0; jj < D; jj += 8) {
                int p = g_se[b0 + jj];
                int src = p & 0xFFFFF, et = p >> 20;
                float a = g_ssrc[src * H + hh] + sd + g_etab[2][et * H + hh];
                a = (a > 0.f) ? a : NEG * a;
                float mn = fmaxf(m, a);
                s = s * __expf(m - mn) + __expf(a - mn);
                m = mn;
            }
        }
#pragma unroll
        for (int o = 4; o <= 16; o <<= 1) {
            float m2 = __shfl_xor_sync(0xffffffffu, m, o);
            float s2 = __shfl_xor_sync(0xffffffffu, s, o);
            float mn = fmaxf(m, m2);
            s = s * __expf(m - mn) + s2 * __expf(m2 - mn);
            m = mn;
        }
        float inv = 1.f / s;
        if (fast) {
            for (int jj = j0; jj < D; jj += 8)
                s_aw[grp][jj][hh] = __expf(s_aw[grp][jj][hh] - m) * inv;
        } else if (lane < H) {
            s_ms[grp][0][lane] = m;
            s_ms[grp][1][lane] = inv;
        }
    }
    __syncthreads();

    float ax[H], ay[H];
#pragma unroll
    for (int h4 = 0; h4 < H; h4++) { ax[h4] = 0.f; ay[h4] = 0.f; }

    if (fast) {
        for (int jj = 0; jj < D; jj++) {
            int src = s_pk[grp][jj] & 0xFFFFF;
            float2 v = __half22float2(h2[(size_t)src * 64 + gtid]);
#pragma unroll
            for (int h4 = 0; h4 < H; h4++) {
                float w = s_aw[grp][jj][h4];
                ax[h4] += w * v.x;
                ay[h4] += w * v.y;
            }
        }
    } else {
        float m4[H], i4[H], sd4[H];
#pragma unroll
        for (int h4 = 0; h4 < H; h4++) {
            m4[h4] = s_ms[grp][0][h4];
            i4[h4] = s_ms[grp][1][h4];
            sd4[h4] = g_sdst[n * H + h4];
        }
        for (int jj = 0; jj < D; jj++) {
            int p = g_se[b0 + jj];
            int src = p & 0xFFFFF, et = p >> 20;
            float2 v = __half22float2(h2[(size_t)src * 64 + gtid]);
#pragma unroll
            for (int h4 = 0; h4 < H; h4++) {
                float a = g_ssrc[src * H + h4] + sd4[h4] + g_etab[2][et * H + h4];
                a = (a > 0.f) ? a : NEG * a;
                float w = __expf(a - m4[h4]) * i4[h4];
                ax[h4] += w * v.x;
                ay[h4] += w * v.y;
            }
        }
    }

    size_t base = (size_t)n * 256 + gtid;
#pragma unroll
    for (int h4 = 0; h4 < H; h4++)
        agg2[base + h4 * 64] = __floats2half2_rn(ax[h4], ay[h4]);
}

// --- L1 GEMM (warp = node) + FUSED layer-2 scores (butterfly reduction) ----
__global__ void k_gemm_small(const float* __restrict__ A, const float* __restrict__ B,
                             const float* __restrict__ bias, float* __restrict__ C) {
    constexpr int K = 64, NN = 32;
    int idx = blockIdx.x * blockDim.x + threadIdx.x;
    int n = idx >> 5, lane = idx & 31;     // warp = node, lane = out channel
    if (n >= N) return;
    const float* ar = A + (size_t)n * K;
    float acc = 0.f;
    for (int k = 0; k < K; k++) acc += ar[k] * B[k * NN + lane];
    acc += bias[lane];
    acc = fmaxf(acc, 0.f);
    C[(size_t)n * NN + lane] = acc;

    // fused layer-2 scores: s[h] = sum_d acc_d * U[1][h*32+d]
    float rs[H], rd[H];
#pragma unroll
    for (int h = 0; h < H; h++) {
        rs[h] = acc * g_usrc[1][h * 32 + lane];
        rd[h] = acc * g_udst[1][h * 32 + lane];
#pragma unroll
        for (int o = 16; o > 0; o >>= 1) {
            rs[h] += __shfl_xor_sync(0xffffffffu, rs[h], o);
            rd[h] += __shfl_xor_sync(0xffffffffu, rd[h], o);
        }
    }
    if (lane == 0) {
#pragma unroll
        for (int h = 0; h < H; h++) {
            g_ssrc[n * H + h] = rs[h];
            g_sdst[n * H + h] = rd[h];
        }
    }
}

// ------- fp16 TC GEMM: 128x128x32 tiles, 3-stage cp.async ring -------------
// Optional fused next-layer scores (requires grid.x == 1): Usrc/Udst != null.
constexpr int STG_BYTES = 128 * 40 * 2 * 2;    // A+B per stage = 20480 B
constexpr int SMEM_HF   = 3 * STG_BYTES;       // 61440 B

__device__ __forceinline__ uint32_t smem_u32(const void* p) {
    uint32_t a;
    asm("{ .reg .u64 t; cvta.to.shared.u64 t, %1; cvt.u32.u64 %0, t; }" : "=r"(a) : "l"(p));
    return a;
}

__global__ void __launch_bounds__(256, 2)
k_gemm_hf(const __half* __restrict__ A, const __half* __restrict__ Bt,
          const float* __restrict__ bias, float* __restrict__ C,
          __half2* __restrict__ Ch2, const float* __restrict__ Usrc,
          const float* __restrict__ Udst, int K, int NN, int relu) {
    extern __shared__ char hsm[];
    int tid = threadIdx.x;
    int wid = tid >> 5, lane = tid & 31;
    int bm = blockIdx.y * 128, bn = blockIdx.x * 128;
    int wm = (wid >> 2) * 64;
    int wn = (wid & 3) * 32;
    int grp = lane >> 2, tig = lane & 3;

    auto stA = [&](int s) { return reinterpret_cast<__half*>(hsm + s * STG_BYTES); };
    auto stB = [&](int s) { return reinterpret_cast<__half*>(hsm + s * STG_BYTES) + 128 * 40; };

    float c[4][4][4];
#pragma unroll
    for (int mt = 0; mt < 4; mt++)
#pragma unroll
        for (int nt = 0; nt < 4; nt++)
#pragma unroll
            for (int q = 0; q < 4; q++) c[mt][nt][q] = 0.f;

    int nk = K >> 5;

    auto copy_tile = [&](int s, int k0) {
        __half* As = stA(s);
        __half* Bs = stB(s);
#pragma unroll
        for (int i = 0; i < 2; i++) {
            int f = tid + i * 256;
            int m = f >> 2, q = f & 3;
            uint32_t dst = smem_u32(&As[m * 40 + q * 8]);
            const __half* src = &A[(size_t)(bm + m) * K + k0 + q * 8];
            asm volatile("cp.async.ca.shared.global [%0], [%1], 16;" :: "r"(dst), "l"(src));
        }
#pragma unroll
        for (int i = 0; i < 2; i++) {
            int f = tid + i * 256;
            int nrow = f >> 2, q = f & 3;
            uint32_t dst = smem_u32(&Bs[nrow * 40 + q * 8]);
            const __half* src = &Bt[(size_t)(bn + nrow) * K + k0 + q * 8];
            asm volatile("cp.async.ca.shared.global [%0], [%1], 16;" :: "r"(dst), "l"(src));
        }
        asm volatile("cp.async.commit_group;");
    };

    copy_tile(0, 0);
    copy_tile(1, 32);

    int mtx = lane >> 3;
    int rin = lane & 7;

    for (int it = 0; it < nk; it++) {
        int cur = it % 3;
        if (it + 1 < nk) asm volatile("cp.async.wait_group 1;");
        else             asm volatile("cp.async.wait_group 0;");
        __syncthreads();
        if (it + 2 < nk) copy_tile((it + 2) % 3, (it + 2) * 32);

        __half* As = stA(cur);
        __half* Bs = stB(cur);
#pragma unroll
        for (int ks = 0; ks < 2; ks++) {
            uint32_t a[4][4], b[4][2];
#pragma unroll
            for (int mt = 0; mt < 4; mt++) {
                int row = wm + mt * 16 + (mtx & 1) * 8 + rin;
                int col = ks * 16 + (mtx >> 1) * 8;
                uint32_t addr = smem_u32(&As[row * 40 + col]);
                asm volatile("ldmatrix.sync.aligned.m8n8.x4.shared.b16 {%0,%1,%2,%3}, [%4];"
                             : "=r"(a[mt][0]), "=r"(a[mt][1]), "=r"(a[mt][2]), "=r"(a[mt][3])
                             : "r"(addr));
            }
#pragma unroll
            for (int np = 0; np < 2; np++) {
                int row = wn + np * 16 + (mtx >> 1) * 8 + rin;
                int col = ks * 16 + (mtx & 1) * 8;
                uint32_t addr = smem_u32(&Bs[row * 40 + col]);
                asm volatile("ldmatrix.sync.aligned.m8n8.x4.shared.b16 {%0,%1,%2,%3}, [%4];"
                             : "=r"(b[np * 2][0]), "=r"(b[np * 2][1]),
                               "=r"(b[np * 2 + 1][0]), "=r"(b[np * 2 + 1][1])
                             : "r"(addr));
            }
#pragma unroll
            for (int mt = 0; mt < 4; mt++)
#pragma unroll
                for (int nt = 0; nt < 4; nt++) {
                    asm volatile(
                        "mma.sync.aligned.m16n8k16.row.col.f32.f16.f16.f32 "
                        "{%0,%1,%2,%3}, {%4,%5,%6,%7}, {%8,%9}, {%0,%1,%2,%3};"
                        : "+f"(c[mt][nt][0]), "+f"(c[mt][nt][1]),
                          "+f"(c[mt][nt][2]), "+f"(c[mt][nt][3])
                        : "r"(a[mt][0]), "r"(a[mt][1]), "r"(a[mt][2]), "r"(a[mt][3]),
                          "r"(b[nt][0]), "r"(b[nt][1]));
                }
        }
        __syncthreads();
    }

    // per-thread bias cache (cols fixed per thread)
    float bv[4][2];
#pragma unroll
    for (int nt = 0; nt < 4; nt++) {
        int col = bn + wn + nt * 8 + tig * 2;
        bv[nt][0] = bias[col];
        bv[nt][1] = bias[col + 1];
    }

#pragma unroll
    for (int mt = 0; mt < 4; mt++) {
#pragma unroll
        for (int nt = 0; nt < 4; nt++) {
            int col = bn + wn + nt * 8 + tig * 2;
            int r0 = bm + wm + mt * 16 + grp;
            float v00 = c[mt][nt][0] + bv[nt][0], v01 = c[mt][nt][1] + bv[nt][1];
            float v10 = c[mt][nt][2] + bv[nt][0], v11 = c[mt][nt][3] + bv[nt][1];
            if (relu) {
                v00 = fmaxf(v00, 0.f); v01 = fmaxf(v01, 0.f);
                v10 = fmaxf(v10, 0.f); v11 = fmaxf(v11, 0.f);
            }
            C[(size_t)r0 * NN + col]           = v00;
            C[(size_t)r0 * NN + col + 1]       = v01;
            C[(size_t)(r0 + 8) * NN + col]     = v10;
            C[(size_t)(r0 + 8) * NN + col + 1] = v11;
            if (Ch2) {
                Ch2[((size_t)r0 * NN + col) >> 1]       = __floats2half2_rn(v00, v01);
                Ch2[((size_t)(r0 + 8) * NN + col) >> 1] = __floats2half2_rn(v10, v11);
            }
        }
    }

    // ---- fused next-layer scores (grid.x==1 path): s[r][h] over full row --
    if (Usrc) {
        float* s_sc = reinterpret_cast<float*>(hsm);   // [128][8]: 4 src + 4 dst
        for (int i = tid; i < 128 * 8; i += 256) s_sc[i] = 0.f;
        __syncthreads();
#pragma unroll
        for (int h8 = 0; h8 < 8; h8++) {
            const float* U = (h8 < 4) ? (Usrc + h8 * NN) : (Udst + (h8 - 4) * NN);
            float u[4][2];
#pragma unroll
            for (int nt = 0; nt < 4; nt++) {
                int col = wn + nt * 8 + tig * 2;
                u[nt][0] = U[col];
                u[nt][1] = U[col + 1];
            }
#pragma unroll
            for (int mt = 0; mt < 4; mt++) {
                int r0 = wm + mt * 16 + grp;
                float p0 = 0.f, p1 = 0.f;
#pragma unroll
                for (int nt = 0; nt < 4; nt++) {
                    float v00 = c[mt][nt][0] + bv[nt][0], v01 = c[mt][nt][1] + bv[nt][1];
                    float v10 = c[mt][nt][2] + bv[nt][0], v11 = c[mt][nt][3] + bv[nt][1];
                    if (relu) {
                        v00 = fmaxf(v00, 0.f); v01 = fmaxf(v01, 0.f);
                        v10 = fmaxf(v10, 0.f); v11 = fmaxf(v11, 0.f);
                    }
                    p0 += v00 * u[nt][0] + v01 * u[nt][1];
                    p1 += v10 * u[nt][0] + v11 * u[nt][1];
                }
                p0 += __shfl_xor_sync(0xffffffffu, p0, 1);
                p0 += __shfl_xor_sync(0xffffffffu, p0, 2);
                p1 += __shfl_xor_sync(0xffffffffu, p1, 1);
                p1 += __shfl_xor_sync(0xffffffffu, p1, 2);
                if (tig == 0) {
                    atomicAdd(&s_sc[r0 * 8 + h8], p0);
                    atomicAdd(&s_sc[(r0 + 8) * 8 + h8], p1);
                }
            }
        }
        __syncthreads();
        for (int i = tid; i < 128 * 8; i += 256) {
            int r = i >> 3, h8 = i & 7;
            float v = s_sc[i];
            if (h8 < 4) g_ssrc[(bm + r) * H + h8] = v;
            else        g_sdst[(bm + r) * H + (h8 - 4)] = v;
        }
    }
}

// ---------------------------------------------------------------------------
extern "C" void kernel_launch(void* const* d_in, const int* in_sizes, int n_in,
                              void* d_out, int out_size) {
    const float* x   = (const float*)d_in[0];
    const int*   eit = (const int*)d_in[1];
    const float* W1  = (const float*)d_in[2];
    const float* We1 = (const float*)d_in[3];
    const float* as1 = (const float*)d_in[4];
    const float* ad1 = (const float*)d_in[5];
    const float* ae1 = (const float*)d_in[6];
    const float* b1  = (const float*)d_in[7];
    const float* W2  = (const float*)d_in[8];
    const float* We2 = (const float*)d_in[9];
    const float* as2 = (const float*)d_in[10];
    const float* ad2 = (const float*)d_in[11];
    const float* ae2 = (const float*)d_in[12];
    const float* b2  = (const float*)d_in[13];
    const float* W3  = (const float*)d_in[14];
    const float* We3 = (const float*)d_in[15];
    const float* as3 = (const float*)d_in[16];
    const float* ad3 = (const float*)d_in[17];
    const float* ae3 = (const float*)d_in[18];
    const float* b3  = (const float*)d_in[19];
    float* out = (float*)d_out;

    float *agg = nullptr, *hbuf = nullptr, *wst1 = nullptr;
    float *usrc = nullptr, *udst = nullptr;
    __half *wst2 = nullptr, *wst3 = nullptr;
    __half2 *hbufh2 = nullptr;
    cudaGetSymbolAddress((void**)&agg, g_agg);
    cudaGetSymbolAddress((void**)&hbuf, g_hbuf);
    cudaGetSymbolAddress((void**)&wst1, g_wst1);
    cudaGetSymbolAddress((void**)&wst2, g_wst2);
    cudaGetSymbolAddress((void**)&wst3, g_wst3);
    cudaGetSymbolAddress((void**)&hbufh2, g_hbufh2);
    cudaGetSymbolAddress((void**)&usrc, g_usrc);
    cudaGetSymbolAddress((void**)&udst, g_udst);
    const __half* aggh = (const __half*)agg;
    __half2* agg2 = (__half2*)agg;

    cudaFuncSetAttribute(k_gemm_hf, cudaFuncAttributeMaxDynamicSharedMemorySize, SMEM_HF);

    // ---- graph build + fused prep (g_deg re-zeroed by k_scan each call) ---
    k_build<<<E / 256, 256>>>(eit);
    k_scan<<<1, 1024>>>();
    k_scatter<<<E / 256, 256>>>();
    k_prep_all<<<1187, 256>>>(W1, as1, ad1, We1, ae1,
                              W2, as2, ad2, We2, ae2,
                              W3, as3, ad3, We3, ae3);

    // ---- layer 1: K=16 -> dout=32 (SIMT; gemm fuses L2 scores) ----
    k_scores<<<N / 8, 256>>>(x, 16, 0);
    k_gat_edge<16, false><<<N / 4, 128>>>(x, agg, 0);
    k_gemm_small<<<(N * 32) / 256, 256>>>(agg, wst1, b1, hbuf);

    // ---- layer 2: K=32 -> dout=128 (TC GEMM fuses L3 scores + half2 out) --
    k_gat_edge<32, true><<<N / 4, 128>>>(hbuf, agg, 1);
    k_gemm_hf<<<dim3(1, N / 128), 256, SMEM_HF>>>(aggh, wst2, b2, hbuf, hbufh2,
                                                  usrc + 2 * 512, udst + 2 * 512, 128, 128, 1);

    // ---- layer 3: K=128 -> dout=512 (half2 gathers; TC GEMM -> out) -------
    k_gat_edge3<<<N / 2, 128>>>(hbufh2, agg2);
    k_gemm_hf<<<dim3(4, N / 128), 256, SMEM_HF>>>(aggh, wst3, b3, out, nullptr,
                                                  nullptr, nullptr, 512, 512, 0);
}

// round 12
// speedup vs baseline: 1.3681x; 1.0134x over previous
#include <cuda_runtime.h>
#include <cuda_fp16.h>
#include <cstdint>

constexpr int N    = 32768;
constexpr int EPER = 16384;
constexpr int T    = 8;
constexpr int E0   = T * EPER;   // 131072 typed edges
constexpr int E    = E0 + N;     // + self loops = 163840
constexpr int H    = 4;
constexpr float NEG = 0.2f;

// ---------------------------- scratch (device globals) ---------------------
__device__ float   g_agg[(size_t)N * 512];   // L1 fp32 [N,64]; L2/L3 half (aliased)
__device__ float   g_hbuf[(size_t)N * 128];  // inter-layer activations (fp32)
__device__ __half2 g_hbufh2[(size_t)N * 64]; // half mirror of hbuf for L3 gathers
__device__ float   g_ssrc[N * H];
__device__ float   g_sdst[N * H];
__device__ float   g_etab[3][(T + 1) * H];
__device__ float   g_usrc[3][512];
__device__ float   g_udst[3][512];
__device__ float   g_wst1[64 * 32];          // L1 fp32 [H*K, dout]
__device__ __half  g_wst2[128 * 128];        // L2 half [dout, H*K] K-major
__device__ __half  g_wst3[512 * 512];        // L3 half [dout, H*K] K-major
__device__ int     g_se[E];                  // dst-sorted packed edges: src | (et<<20)
__device__ int     g_src[E], g_dst[E], g_et[E];
__device__ int     g_deg[N], g_rowptr[N + 1], g_fill[N];

// ---------- ONE setup kernel: graph build + all weight prep (overlapped) ---
// blocks [0,640): edge build          [640,648): wst1 copy
// [648,664): wst2 tile transpose      [664,920): wst3 tile transpose
// [920,1008): U vectors (warp/entry)  [1008,1011): edge tables
__global__ void k_setup(const int* __restrict__ eit,
    const float* __restrict__ W1, const float* __restrict__ as1,
    const float* __restrict__ ad1, const float* __restrict__ We1,
    const float* __restrict__ ae1,
    const float* __restrict__ W2, const float* __restrict__ as2,
    const float* __restrict__ ad2, const float* __restrict__ We2,
    const float* __restrict__ ae2,
    const float* __restrict__ W3, const float* __restrict__ as3,
    const float* __restrict__ ad3, const float* __restrict__ We3,
    const float* __restrict__ ae3) {
    __shared__ float sm[32][33];
    int b = blockIdx.x, tid = threadIdx.x;

    if (b < 640) {
        // ---- graph edge build ----
        int e = b * 256 + tid;
        if (e >= E) return;
        int s, d, t;
        if (e < E0) {
            t = e / EPER;
            int i = e - t * EPER;
            s = eit[t * 2 * EPER + i];
            d = eit[t * 2 * EPER + EPER + i];
        } else {
            s = d = e - E0;
            t = T;
        }
        g_src[e] = s; g_dst[e] = d; g_et[e] = t;
        atomicAdd(&g_deg[d], 1);
    } else if (b < 648) {
        // ---- wst1 plain copy (both sides coalesced) ----
        int idx = (b - 640) * 256 + tid;         // 2048 = 64*32
        int d = idx % 32, hk = idx / 32;
        int h = hk / 16, k = hk % 16;
        g_wst1[idx] = W1[(size_t)k * 128 + h * 32 + d] * 0.25f;
    } else if (b < 664) {
        // ---- wst2 transpose via smem tile: W2[32k x (h*128+d)] -> [d][h*32+k]
        int rel = b - 648;
        int h = rel >> 2, dt = rel & 3;          // 4 d-tiles of 32
        int ty = tid >> 5, tx = tid & 31;
#pragma unroll
        for (int p = 0; p < 4; p++) {
            int k = p * 8 + ty;
            sm[k][tx] = W2[(size_t)k * 512 + h * 128 + dt * 32 + tx];
        }
        __syncthreads();
#pragma unroll
        for (int p = 0; p < 4; p++) {
            int d = p * 8 + ty;
            g_wst2[(size_t)(dt * 32 + d) * 128 + h * 32 + tx] =
                __float2half(sm[tx][d] * 0.25f);
        }
    } else if (b < 920) {
        // ---- wst3 transpose via smem tile: W3[128k x (h*512+d)] -> [d][h*128+k]
        int rel = b - 664;                       // 256 = 4h * 4kt * 16dt
        int h = rel >> 6, rem = rel & 63;
        int kt = rem >> 4, dt = rem & 15;
        int ty = tid >> 5, tx = tid & 31;
#pragma unroll
        for (int p = 0; p < 4; p++) {
            int k = p * 8 + ty;
            sm[k][tx] = W3[(size_t)(kt * 32 + k) * 2048 + h * 512 + dt * 32 + tx];
        }
        __syncthreads();
#pragma unroll
        for (int p = 0; p < 4; p++) {
            int d = p * 8 + ty;
            g_wst3[(size_t)(dt * 32 + d) * 512 + h * 128 + kt * 32 + tx] =
                __float2half(sm[tx][d] * 0.25f);
        }
    } else if (b < 1008) {
        // ---- U vectors: warp per entry (704 warps: 64 + 128 + 512) ----
        int gw = (b - 920) * 8 + (tid >> 5);
        int lane = tid & 31;
        int L, e;
        if (gw < 64)       { L = 0; e = gw; }
        else if (gw < 192) { L = 1; e = gw - 64; }
        else               { L = 2; e = gw - 192; }
        if (L == 2 && e >= 512) return;
        int K    = (L == 0) ? 16 : (L == 1) ? 32 : 128;
        int dout = (L == 0) ? 32 : (L == 1) ? 128 : 512;
        const float* W  = (L == 0) ? W1  : (L == 1) ? W2  : W3;
        const float* as = (L == 0) ? as1 : (L == 1) ? as2 : as3;
        const float* ad = (L == 0) ? ad1 : (L == 1) ? ad2 : ad3;
        int h = e / K, k = e % K;
        const float* wr = W + (size_t)k * (H * dout) + h * dout;
        float vs = 0.f, vd = 0.f;
        for (int d = lane; d < dout; d += 32) {
            float w = wr[d];
            vs += w * as[h * dout + d];
            vd += w * ad[h * dout + d];
        }
#pragma unroll
        for (int o = 16; o > 0; o >>= 1) {
            vs += __shfl_xor_sync(0xffffffffu, vs, o);
            vd += __shfl_xor_sync(0xffffffffu, vd, o);
        }
        if (lane == 0) {
            g_usrc[L][e] = vs;
            g_udst[L][e] = vd;
        }
    } else {
        // ---- edge table for layer L: warp per (t,h) entry ----
        int L = b - 1008;
        int dout = (L == 0) ? 32 : (L == 1) ? 128 : 512;
        const float* We = (L == 0) ? We1 : (L == 1) ? We2 : We3;
        const float* ae = (L == 0) ? ae1 : (L == 1) ? ae2 : ae3;
        int HC = H * dout;
        int wrp = tid >> 5, lane = tid & 31;
#pragma unroll
        for (int i = 0; i < 4; i++) {
            int e = wrp * 4 + i;                // 0..31 = (t,h)
            int t = e >> 2, h = e & 3;
            float s = 0.f;
            for (int c = lane; c < dout; c += 32)
                s += We[t * HC + h * dout + c] * ae[h * dout + c];
#pragma unroll
            for (int o = 16; o > 0; o >>= 1)
                s += __shfl_xor_sync(0xffffffffu, s, o);
            if (lane == 0) {
                sm[t][h] = s;
                g_etab[L][t * H + h] = s;
            }
        }
        __syncthreads();
        if (tid < H) {
            float s = 0.f;
            for (int t = 0; t < T; t++) s += sm[t][tid];
            g_etab[L][T * H + tid] = s * (1.0f / T);
        }
    }
}

// scan also RE-ZEROES g_deg so the next call starts clean (call-invariant).
__global__ void k_scan() {
    __shared__ int sh[1024];
    int t = threadIdx.x;
    int base = t * 32;
    int loc[32];
    int sum = 0;
#pragma unroll
    for (int i = 0; i < 32; i++) { loc[i] = sum; sum += g_deg[base + i]; g_deg[base + i] = 0; }
    sh[t] = sum;
    __syncthreads();
    for (int off = 1; off < 1024; off <<= 1) {
        int v = (t >= off) ? sh[t - off] : 0;
        __syncthreads();
        if (t >= off) sh[t] += v;
        __syncthreads();
    }
    int prev = (t == 0) ? 0 : sh[t - 1];
#pragma unroll
    for (int i = 0; i < 32; i++) {
        int v = prev + loc[i];
        g_rowptr[base + i] = v;
        g_fill[base + i]   = v;
    }
    if (t == 1023) g_rowptr[N] = sh[1023];
}

__global__ void k_scatter() {
    int e = blockIdx.x * blockDim.x + threadIdx.x;
    if (e >= E) return;
    int pos = atomicAdd(&g_fill[g_dst[e]], 1);
    g_se[pos] = g_src[e] | (g_et[e] << 20);
}

// ---------------------------- L1 attention scores (from x, K=16) -----------
__global__ void k_scores(const float* __restrict__ h, int K, int L) {
    int gw = (blockIdx.x * blockDim.x + threadIdx.x) >> 5;
    int lane = threadIdx.x & 31;
    if (gw >= N) return;
    const float* row = h + (size_t)gw * K;
    float acc[2][H];
#pragma unroll
    for (int i = 0; i < 2; i++)
#pragma unroll
        for (int hh = 0; hh < H; hh++) acc[i][hh] = 0.f;
    for (int k = lane; k < K; k += 32) {
        float x = row[k];
#pragma unroll
        for (int hh = 0; hh < H; hh++) {
            acc[0][hh] += x * g_usrc[L][hh * K + k];
            acc[1][hh] += x * g_udst[L][hh * K + k];
        }
    }
#pragma unroll
    for (int i = 0; i < 2; i++)
#pragma unroll
        for (int hh = 0; hh < H; hh++)
#pragma unroll
            for (int o = 16; o > 0; o >>= 1)
                acc[i][hh] += __shfl_xor_sync(0xffffffffu, acc[i][hh], o);
    if (lane < H)      g_ssrc[gw * H + lane] = acc[0][lane];
    else if (lane < 2 * H) g_sdst[gw * H + (lane - H)] = acc[1][lane - H];
}

// ------- fused alpha + softmax + aggregation, K<=32 (warp per node) --------
template <int K, bool CVT>
__global__ void k_gat_edge(const float* __restrict__ h, float* __restrict__ aggf, int L) {
    constexpr int CAP = 128;
    __shared__ int   s_pk[4][CAP];
    __shared__ float s_aw[4][CAP][H];

    int lane = threadIdx.x & 31;
    int grp  = threadIdx.x >> 5;
    int n    = blockIdx.x * 4 + grp;
    int b0 = g_rowptr[n], b1 = g_rowptr[n + 1];
    int D = b1 - b0;

    float a0 = 0.f, a1 = 0.f, a2 = 0.f, a3 = 0.f;

    if (D <= CAP) {
        for (int j = lane; j < D; j += 32) s_pk[grp][j] = g_se[b0 + j];
        __syncwarp();
        {
            int hh = lane & 3;
            int j0 = lane >> 2;
            float sd = g_sdst[n * H + hh];
            float m = -1e30f, s = 0.f;
            for (int jj = j0; jj < D; jj += 8) {
                int p = s_pk[grp][jj];
                int src = p & 0xFFFFF, et = p >> 20;
                float a = g_ssrc[src * H + hh] + sd + g_etab[L][et * H + hh];
                a = (a > 0.f) ? a : NEG * a;
                s_aw[grp][jj][hh] = a;
                float mn = fmaxf(m, a);
                s = s * __expf(m - mn) + __expf(a - mn);
                m = mn;
            }
#pragma unroll
            for (int o = 4; o <= 16; o <<= 1) {
                float m2 = __shfl_xor_sync(0xffffffffu, m, o);
                float s2 = __shfl_xor_sync(0xffffffffu, s, o);
                float mn = fmaxf(m, m2);
                s = s * __expf(m - mn) + s2 * __expf(m2 - mn);
                m = mn;
            }
            float inv = 1.f / s;
            for (int jj = j0; jj < D; jj += 8)
                s_aw[grp][jj][hh] = __expf(s_aw[grp][jj][hh] - m) * inv;
        }
        __syncwarp();
        if (lane < K) {
            for (int jj = 0; jj < D; jj++) {
                int src = s_pk[grp][jj] & 0xFFFFF;
                float v = h[(size_t)src * K + lane];
                a0 += s_aw[grp][jj][0] * v;
                a1 += s_aw[grp][jj][1] * v;
                a2 += s_aw[grp][jj][2] * v;
                a3 += s_aw[grp][jj][3] * v;
            }
        }
    } else {
        int hh = lane & 3;
        int j0 = lane >> 2;
        float sd = g_sdst[n * H + hh];
        float m = -1e30f, s = 0.f;
        for (int jj = j0; jj < D; jj += 8) {
            int p = g_se[b0 + jj];
            int src = p & 0xFFFFF, et = p >> 20;
            float a = g_ssrc[src * H + hh] + sd + g_etab[L][et * H + hh];
            a = (a > 0.f) ? a : NEG * a;
            float mn = fmaxf(m, a);
            s = s * __expf(m - mn) + __expf(a - mn);
            m = mn;
        }
#pragma unroll
        for (int o = 4; o <= 16; o <<= 1) {
            float m2 = __shfl_xor_sync(0xffffffffu, m, o);
            float s2 = __shfl_xor_sync(0xffffffffu, s, o);
            float mn = fmaxf(m, m2);
            s = s * __expf(m - mn) + s2 * __expf(m2 - mn);
            m = mn;
        }
        float inv = 1.f / s;
        float m4[H], i4[H];
#pragma unroll
        for (int h4 = 0; h4 < H; h4++) {
            m4[h4] = __shfl_sync(0xffffffffu, m, h4);
            i4[h4] = __shfl_sync(0xffffffffu, inv, h4);
        }
        if (lane < K) {
            float sd4[H];
#pragma unroll
            for (int h4 = 0; h4 < H; h4++) sd4[h4] = g_sdst[n * H + h4];
            for (int jj = 0; jj < D; jj++) {
                int p = g_se[b0 + jj];
                int src = p & 0xFFFFF, et = p >> 20;
                float v = h[(size_t)src * K + lane];
#pragma unroll
                for (int h4 = 0; h4 < H; h4++) {
                    float a = g_ssrc[src * H + h4] + sd4[h4] + g_etab[L][et * H + h4];
                    a = (a > 0.f) ? a : NEG * a;
                    float w = __expf(a - m4[h4]) * i4[h4];
                    if (h4 == 0) a0 += w * v;
                    else if (h4 == 1) a1 += w * v;
                    else if (h4 == 2) a2 += w * v;
                    else a3 += w * v;
                }
            }
        }
    }

    if (lane < K) {
        size_t base = (size_t)n * (H * K) + lane;
        if (CVT) {
            __half* ah = reinterpret_cast<__half*>(aggf);
            ah[base]         = __float2half(a0);
            ah[base + K]     = __float2half(a1);
            ah[base + 2 * K] = __float2half(a2);
            ah[base + 3 * K] = __float2half(a3);
        } else {
            aggf[base]         = a0;
            aggf[base + K]     = a1;
            aggf[base + 2 * K] = a2;
            aggf[base + 3 * K] = a3;
        }
    }
}

// ------- L3 edge kernel: 2 nodes per 128-thr block, half2 gathers ----------
__global__ void k_gat_edge3(const __half2* __restrict__ h2, __half2* __restrict__ agg2) {
    constexpr int CAP = 128;
    __shared__ int   s_pk[2][CAP];
    __shared__ float s_aw[2][CAP][H];
    __shared__ float s_ms[2][2][H];

    int grp  = threadIdx.x >> 6;
    int gtid = threadIdx.x & 63;
    int lane = threadIdx.x & 31;
    int wing = (threadIdx.x >> 5) & 1;
    int n = blockIdx.x * 2 + grp;
    int b0 = g_rowptr[n], b1 = g_rowptr[n + 1];
    int D = b1 - b0;
    bool fast = (D <= CAP);

    if (fast)
        for (int j = gtid; j < D; j += 64) s_pk[grp][j] = g_se[b0 + j];
    __syncthreads();

    if (wing == 0) {
        int hh = lane & 3;
        int j0 = lane >> 2;
        float sd = g_sdst[n * H + hh];
        float m = -1e30f, s = 0.f;
        if (fast) {
            for (int jj = j0; jj < D; jj += 8) {
                int p = s_pk[grp][jj];
                int src = p & 0xFFFFF, et = p >> 20;
                float a = g_ssrc[src * H + hh] + sd + g_etab[2][et * H + hh];
                a = (a > 0.f) ? a : NEG * a;
                s_aw[grp][jj][hh] = a;
                float mn = fmaxf(m, a);
                s = s * __expf(m - mn) + __expf(a - mn);
                m = mn;
            }
        } else {
            for (int jj = j0; jj < D; jj += 8) {
                int p = g_se[b0 + jj];
                int src = p & 0xFFFFF, et = p >> 20;
                float a = g_ssrc[src * H + hh] + sd + g_etab[2][et * H + hh];
                a = (a > 0.f) ? a : NEG * a;
                float mn = fmaxf(m, a);
                s = s * __expf(m - mn) + __expf(a - mn);
                m = mn;
            }
        }
#pragma unroll
        for (int o = 4; o <= 16; o <<= 1) {
            float m2 = __shfl_xor_sync(0xffffffffu, m, o);
            float s2 = __shfl_xor_sync(0xffffffffu, s, o);
            float mn = fmaxf(m, m2);
            s = s * __expf(m - mn) + s2 * __expf(m2 - mn);
            m = mn;
        }
        float inv = 1.f / s;
        if (fast) {
            for (int jj = j0; jj < D; jj += 8)
                s_aw[grp][jj][hh] = __expf(s_aw[grp][jj][hh] - m) * inv;
        } else if (lane < H) {
            s_ms[grp][0][lane] = m;
            s_ms[grp][1][lane] = inv;
        }
    }
    __syncthreads();

    float ax[H], ay[H];
#pragma unroll
    for (int h4 = 0; h4 < H; h4++) { ax[h4] = 0.f; ay[h4] = 0.f; }

    if (fast) {
        for (int jj = 0; jj < D; jj++) {
            int src = s_pk[grp][jj] & 0xFFFFF;
            float2 v = __half22float2(h2[(size_t)src * 64 + gtid]);
#pragma unroll
            for (int h4 = 0; h4 < H; h4++) {
                float w = s_aw[grp][jj][h4];
                ax[h4] += w * v.x;
                ay[h4] += w * v.y;
            }
        }
    } else {
        float m4[H], i4[H], sd4[H];
#pragma unroll
        for (int h4 = 0; h4 < H; h4++) {
            m4[h4] = s_ms[grp][0][h4];
            i4[h4] = s_ms[grp][1][h4];
            sd4[h4] = g_sdst[n * H + h4];
        }
        for (int jj = 0; jj < D; jj++) {
            int p = g_se[b0 + jj];
            int src = p & 0xFFFFF, et = p >> 20;
            float2 v = __half22float2(h2[(size_t)src * 64 + gtid]);
#pragma unroll
            for (int h4 = 0; h4 < H; h4++) {
                float a = g_ssrc[src * H + h4] + sd4[h4] + g_etab[2][et * H + h4];
                a = (a > 0.f) ? a : NEG * a;
                float w = __expf(a - m4[h4]) * i4[h4];
                ax[h4] += w * v.x;
                ay[h4] += w * v.y;
            }
        }
    }

    size_t base = (size_t)n * 256 + gtid;
#pragma unroll
    for (int h4 = 0; h4 < H; h4++)
        agg2[base + h4 * 64] = __floats2half2_rn(ax[h4], ay[h4]);
}

// --- L1 GEMM (warp = node) + FUSED layer-2 scores (butterfly reduction) ----
__global__ void k_gemm_small(const float* __restrict__ A, const float* __restrict__ B,
                             const float* __restrict__ bias, float* __restrict__ C) {
    constexpr int K = 64, NN = 32;
    int idx = blockIdx.x * blockDim.x + threadIdx.x;
    int n = idx >> 5, lane = idx & 31;     // warp = node, lane = out channel
    if (n >= N) return;
    const float* ar = A + (size_t)n * K;
    float acc = 0.f;
    for (int k = 0; k < K; k++) acc += ar[k] * B[k * NN + lane];
    acc += bias[lane];
    acc = fmaxf(acc, 0.f);
    C[(size_t)n * NN + lane] = acc;

    // fused layer-2 scores: s[h] = sum_d acc_d * U[1][h*32+d]
    float rs[H], rd[H];
#pragma unroll
    for (int h = 0; h < H; h++) {
        rs[h] = acc * g_usrc[1][h * 32 + lane];
        rd[h] = acc * g_udst[1][h * 32 + lane];
#pragma unroll
        for (int o = 16; o > 0; o >>= 1) {
            rs[h] += __shfl_xor_sync(0xffffffffu, rs[h], o);
            rd[h] += __shfl_xor_sync(0xffffffffu, rd[h], o);
        }
    }
    if (lane == 0) {
#pragma unroll
        for (int h = 0; h < H; h++) {
            g_ssrc[n * H + h] = rs[h];
            g_sdst[n * H + h] = rd[h];
        }
    }
}

// ------- fp16 TC GEMM: 128x128x32 tiles, 3-stage cp.async ring -------------
// Optional fused next-layer scores (requires grid.x == 1): Usrc/Udst != null.
constexpr int STG_BYTES = 128 * 40 * 2 * 2;    // A+B per stage = 20480 B
constexpr int SMEM_HF   = 3 * STG_BYTES;       // 61440 B

__device__ __forceinline__ uint32_t smem_u32(const void* p) {
    uint32_t a;
    asm("{ .reg .u64 t; cvta.to.shared.u64 t, %1; cvt.u32.u64 %0, t; }" : "=r"(a) : "l"(p));
    return a;
}

__global__ void __launch_bounds__(256, 2)
k_gemm_hf(const __half* __restrict__ A, const __half* __restrict__ Bt,
          const float* __restrict__ bias, float* __restrict__ C,
          __half2* __restrict__ Ch2, const float* __restrict__ Usrc,
          const float* __restrict__ Udst, int K, int NN, int relu) {
    extern __shared__ char hsm[];
    int tid = threadIdx.x;
    int wid = tid >> 5, lane = tid & 31;
    int bm = blockIdx.y * 128, bn = blockIdx.x * 128;
    int wm = (wid >> 2) * 64;
    int wn = (wid & 3) * 32;
    int grp = lane >> 2, tig = lane & 3;

    auto stA = [&](int s) { return reinterpret_cast<__half*>(hsm + s * STG_BYTES); };
    auto stB = [&](int s) { return reinterpret_cast<__half*>(hsm + s * STG_BYTES) + 128 * 40; };

    float c[4][4][4];
#pragma unroll
    for (int mt = 0; mt < 4; mt++)
#pragma unroll
        for (int nt = 0; nt < 4; nt++)
#pragma unroll
            for (int q = 0; q < 4; q++) c[mt][nt][q] = 0.f;

    int nk = K >> 5;

    auto copy_tile = [&](int s, int k0) {
        __half* As = stA(s);
        __half* Bs = stB(s);
#pragma unroll
        for (int i = 0; i < 2; i++) {
            int f = tid + i * 256;
            int m = f >> 2, q = f & 3;
            uint32_t dst = smem_u32(&As[m * 40 + q * 8]);
            const __half* src = &A[(size_t)(bm + m) * K + k0 + q * 8];
            asm volatile("cp.async.ca.shared.global [%0], [%1], 16;" :: "r"(dst), "l"(src));
        }
#pragma unroll
        for (int i = 0; i < 2; i++) {
            int f = tid + i * 256;
            int nrow = f >> 2, q = f & 3;
            uint32_t dst = smem_u32(&Bs[nrow * 40 + q * 8]);
            const __half* src = &Bt[(size_t)(bn + nrow) * K + k0 + q * 8];
            asm volatile("cp.async.ca.shared.global [%0], [%1], 16;" :: "r"(dst), "l"(src));
        }
        asm volatile("cp.async.commit_group;");
    };

    copy_tile(0, 0);
    copy_tile(1, 32);

    int mtx = lane >> 3;
    int rin = lane & 7;

    for (int it = 0; it < nk; it++) {
        int cur = it % 3;
        if (it + 1 < nk) asm volatile("cp.async.wait_group 1;");
        else             asm volatile("cp.async.wait_group 0;");
        __syncthreads();
        if (it + 2 < nk) copy_tile((it + 2) % 3, (it + 2) * 32);

        __half* As = stA(cur);
        __half* Bs = stB(cur);
#pragma unroll
        for (int ks = 0; ks < 2; ks++) {
            uint32_t a[4][4], b[4][2];
#pragma unroll
            for (int mt = 0; mt < 4; mt++) {
                int row = wm + mt * 16 + (mtx & 1) * 8 + rin;
                int col = ks * 16 + (mtx >> 1) * 8;
                uint32_t addr = smem_u32(&As[row * 40 + col]);
                asm volatile("ldmatrix.sync.aligned.m8n8.x4.shared.b16 {%0,%1,%2,%3}, [%4];"
                             : "=r"(a[mt][0]), "=r"(a[mt][1]), "=r"(a[mt][2]), "=r"(a[mt][3])
                             : "r"(addr));
            }
#pragma unroll
            for (int np = 0; np < 2; np++) {
                int row = wn + np * 16 + (mtx >> 1) * 8 + rin;
                int col = ks * 16 + (mtx & 1) * 8;
                uint32_t addr = smem_u32(&Bs[row * 40 + col]);
                asm volatile("ldmatrix.sync.aligned.m8n8.x4.shared.b16 {%0,%1,%2,%3}, [%4];"
                             : "=r"(b[np * 2][0]), "=r"(b[np * 2][1]),
                               "=r"(b[np * 2 + 1][0]), "=r"(b[np * 2 + 1][1])
                             : "r"(addr));
            }
#pragma unroll
            for (int mt = 0; mt < 4; mt++)
#pragma unroll
                for (int nt = 0; nt < 4; nt++) {
                    asm volatile(
                        "mma.sync.aligned.m16n8k16.row.col.f32.f16.f16.f32 "
                        "{%0,%1,%2,%3}, {%4,%5,%6,%7}, {%8,%9}, {%0,%1,%2,%3};"
                        : "+f"(c[mt][nt][0]), "+f"(c[mt][nt][1]),
                          "+f"(c[mt][nt][2]), "+f"(c[mt][nt][3])
                        : "r"(a[mt][0]), "r"(a[mt][1]), "r"(a[mt][2]), "r"(a[mt][3]),
                          "r"(b[nt][0]), "r"(b[nt][1]));
                }
        }
        __syncthreads();
    }

    // per-thread bias cache (cols fixed per thread)
    float bv[4][2];
#pragma unroll
    for (int nt = 0; nt < 4; nt++) {
        int col = bn + wn + nt * 8 + tig * 2;
        bv[nt][0] = bias[col];
        bv[nt][1] = bias[col + 1];
    }

#pragma unroll
    for (int mt = 0; mt < 4; mt++) {
#pragma unroll
        for (int nt = 0; nt < 4; nt++) {
            int col = bn + wn + nt * 8 + tig * 2;
            int r0 = bm + wm + mt * 16 + grp;
            float v00 = c[mt][nt][0] + bv[nt][0], v01 = c[mt][nt][1] + bv[nt][1];
            float v10 = c[mt][nt][2] + bv[nt][0], v11 = c[mt][nt][3] + bv[nt][1];
            if (relu) {
                v00 = fmaxf(v00, 0.f); v01 = fmaxf(v01, 0.f);
                v10 = fmaxf(v10, 0.f); v11 = fmaxf(v11, 0.f);
            }
            C[(size_t)r0 * NN + col]           = v00;
            C[(size_t)r0 * NN + col + 1]       = v01;
            C[(size_t)(r0 + 8) * NN + col]     = v10;
            C[(size_t)(r0 + 8) * NN + col + 1] = v11;
            if (Ch2) {
                Ch2[((size_t)r0 * NN + col) >> 1]       = __floats2half2_rn(v00, v01);
                Ch2[((size_t)(r0 + 8) * NN + col) >> 1] = __floats2half2_rn(v10, v11);
            }
        }
    }

    // ---- fused next-layer scores (grid.x==1 path): s[r][h] over full row --
    if (Usrc) {
        float* s_sc = reinterpret_cast<float*>(hsm);   // [128][8]: 4 src + 4 dst
        for (int i = tid; i < 128 * 8; i += 256) s_sc[i] = 0.f;
        __syncthreads();
#pragma unroll
        for (int h8 = 0; h8 < 8; h8++) {
            const float* U = (h8 < 4) ? (Usrc + h8 * NN) : (Udst + (h8 - 4) * NN);
            float u[4][2];
#pragma unroll
            for (int nt = 0; nt < 4; nt++) {
                int col = wn + nt * 8 + tig * 2;
                u[nt][0] = U[col];
                u[nt][1] = U[col + 1];
            }
#pragma unroll
            for (int mt = 0; mt < 4; mt++) {
                int r0 = wm + mt * 16 + grp;
                float p0 = 0.f, p1 = 0.f;
#pragma unroll
                for (int nt = 0; nt < 4; nt++) {
                    float v00 = c[mt][nt][0] + bv[nt][0], v01 = c[mt][nt][1] + bv[nt][1];
                    float v10 = c[mt][nt][2] + bv[nt][0], v11 = c[mt][nt][3] + bv[nt][1];
                    if (relu) {
                        v00 = fmaxf(v00, 0.f); v01 = fmaxf(v01, 0.f);
                        v10 = fmaxf(v10, 0.f); v11 = fmaxf(v11, 0.f);
                    }
                    p0 += v00 * u[nt][0] + v01 * u[nt][1];
                    p1 += v10 * u[nt][0] + v11 * u[nt][1];
                }
                p0 += __shfl_xor_sync(0xffffffffu, p0, 1);
                p0 += __shfl_xor_sync(0xffffffffu, p0, 2);
                p1 += __shfl_xor_sync(0xffffffffu, p1, 1);
                p1 += __shfl_xor_sync(0xffffffffu, p1, 2);
                if (tig == 0) {
                    atomicAdd(&s_sc[r0 * 8 + h8], p0);
                    atomicAdd(&s_sc[(r0 + 8) * 8 + h8], p1);
                }
            }
        }
        __syncthreads();
        for (int i = tid; i < 128 * 8; i += 256) {
            int r = i >> 3, h8 = i & 7;
            float v = s_sc[i];
            if (h8 < 4) g_ssrc[(bm + r) * H + h8] = v;
            else        g_sdst[(bm + r) * H + (h8 - 4)] = v;
        }
    }
}

// ---------------------------------------------------------------------------
extern "C" void kernel_launch(void* const* d_in, const int* in_sizes, int n_in,
                              void* d_out, int out_size) {
    const float* x   = (const float*)d_in[0];
    const int*   eit = (const int*)d_in[1];
    const float* W1  = (const float*)d_in[2];
    const float* We1 = (const float*)d_in[3];
    const float* as1 = (const float*)d_in[4];
    const float* ad1 = (const float*)d_in[5];
    const float* ae1 = (const float*)d_in[6];
    const float* b1  = (const float*)d_in[7];
    const float* W2  = (const float*)d_in[8];
    const float* We2 = (const float*)d_in[9];
    const float* as2 = (const float*)d_in[10];
    const float* ad2 = (const float*)d_in[11];
    const float* ae2 = (const float*)d_in[12];
    const float* b2  = (const float*)d_in[13];
    const float* W3  = (const float*)d_in[14];
    const float* We3 = (const float*)d_in[15];
    const float* as3 = (const float*)d_in[16];
    const float* ad3 = (const float*)d_in[17];
    const float* ae3 = (const float*)d_in[18];
    const float* b3  = (const float*)d_in[19];
    float* out = (float*)d_out;

    float *agg = nullptr, *hbuf = nullptr, *wst1 = nullptr;
    float *usrc = nullptr, *udst = nullptr;
    __half *wst2 = nullptr, *wst3 = nullptr;
    __half2 *hbufh2 = nullptr;
    cudaGetSymbolAddress((void**)&agg, g_agg);
    cudaGetSymbolAddress((void**)&hbuf, g_hbuf);
    cudaGetSymbolAddress((void**)&wst1, g_wst1);
    cudaGetSymbolAddress((void**)&wst2, g_wst2);
    cudaGetSymbolAddress((void**)&wst3, g_wst3);
    cudaGetSymbolAddress((void**)&hbufh2, g_hbufh2);
    cudaGetSymbolAddress((void**)&usrc, g_usrc);
    cudaGetSymbolAddress((void**)&udst, g_udst);
    const __half* aggh = (const __half*)agg;
    __half2* agg2 = (__half2*)agg;

    cudaFuncSetAttribute(k_gemm_hf, cudaFuncAttributeMaxDynamicSharedMemorySize, SMEM_HF);

    // ---- fused graph build + prep, then scan + scatter ----
    k_setup<<<1011, 256>>>(eit,
                           W1, as1, ad1, We1, ae1,
                           W2, as2, ad2, We2, ae2,
                           W3, as3, ad3, We3, ae3);
    k_scan<<<1, 1024>>>();
    k_scatter<<<E / 256, 256>>>();

    // ---- layer 1: K=16 -> dout=32 (SIMT; gemm fuses L2 scores) ----
    k_scores<<<N / 8, 256>>>(x, 16, 0);
    k_gat_edge<16, false><<<N / 4, 128>>>(x, agg, 0);
    k_gemm_small<<<(N * 32) / 256, 256>>>(agg, wst1, b1, hbuf);

    // ---- layer 2: K=32 -> dout=128 (TC GEMM fuses L3 scores + half2 out) --
    k_gat_edge<32, true><<<N / 4, 128>>>(hbuf, agg, 1);
    k_gemm_hf<<<dim3(1, N / 128), 256, SMEM_HF>>>(aggh, wst2, b2, hbuf, hbufh2,
                                                  usrc + 2 * 512, udst + 2 * 512, 128, 128, 1);

    // ---- layer 3: K=128 -> dout=512 (half2 gathers; TC GEMM -> out) -------
    k_gat_edge3<<<N / 2, 128>>>(hbufh2, agg2);
    k_gemm_hf<<<dim3(4, N / 128), 256, SMEM_HF>>>(aggh, wst3, b3, out, nullptr,
                                                  nullptr, nullptr, 512, 512, 0);
}

// round 13
// speedup vs baseline: 1.3981x; 1.0219x over previous
#include <cuda_runtime.h>
#include <cuda_fp16.h>
#include <cstdint>

constexpr int N    = 32768;
constexpr int EPER = 16384;
constexpr int T    = 8;
constexpr int E0   = T * EPER;   // 131072 typed edges
constexpr int E    = E0 + N;     // + self loops = 163840
constexpr int H    = 4;
constexpr float NEG = 0.2f;

// ---------------------------- scratch (device globals) ---------------------
__device__ float   g_agg[(size_t)N * 512];   // L1 fp32 [N,64]; L2/L3 half (aliased)
__device__ float   g_hbuf[(size_t)N * 128];  // inter-layer activations (fp32)
__device__ __half2 g_hbufh2[(size_t)N * 64]; // half mirror of hbuf for L3 gathers
__device__ float   g_ssrc[N * H];
__device__ float   g_sdst[N * H];
__device__ float   g_etab[3][(T + 1) * H];
__device__ float   g_usrc[3][512];
__device__ float   g_udst[3][512];
__device__ float   g_wst1[64 * 32];          // L1 fp32 [H*K, dout]
__device__ __half  g_wst2[128 * 128];        // L2 half [dout, H*K] K-major
__device__ __half  g_wst3[512 * 512];        // L3 half [dout, H*K] K-major
__device__ int     g_se[E];                  // dst-sorted packed edges: src | (et<<20)
__device__ int     g_src[E], g_dst[E], g_et[E];
__device__ int     g_deg[N], g_rowptr[N + 1], g_fill[N];

// ---------- ONE setup kernel: graph build + all weight prep (overlapped) ---
__global__ void k_setup(const int* __restrict__ eit,
    const float* __restrict__ W1, const float* __restrict__ as1,
    const float* __restrict__ ad1, const float* __restrict__ We1,
    const float* __restrict__ ae1,
    const float* __restrict__ W2, const float* __restrict__ as2,
    const float* __restrict__ ad2, const float* __restrict__ We2,
    const float* __restrict__ ae2,
    const float* __restrict__ W3, const float* __restrict__ as3,
    const float* __restrict__ ad3, const float* __restrict__ We3,
    const float* __restrict__ ae3) {
    __shared__ float sm[32][33];
    int b = blockIdx.x, tid = threadIdx.x;

    if (b < 640) {
        int e = b * 256 + tid;
        if (e >= E) return;
        int s, d, t;
        if (e < E0) {
            t = e / EPER;
            int i = e - t * EPER;
            s = eit[t * 2 * EPER + i];
            d = eit[t * 2 * EPER + EPER + i];
        } else {
            s = d = e - E0;
            t = T;
        }
        g_src[e] = s; g_dst[e] = d; g_et[e] = t;
        atomicAdd(&g_deg[d], 1);
    } else if (b < 648) {
        int idx = (b - 640) * 256 + tid;         // 2048 = 64*32
        int d = idx % 32, hk = idx / 32;
        int h = hk / 16, k = hk % 16;
        g_wst1[idx] = W1[(size_t)k * 128 + h * 32 + d] * 0.25f;
    } else if (b < 664) {
        int rel = b - 648;
        int h = rel >> 2, dt = rel & 3;
        int ty = tid >> 5, tx = tid & 31;
#pragma unroll
        for (int p = 0; p < 4; p++) {
            int k = p * 8 + ty;
            sm[k][tx] = W2[(size_t)k * 512 + h * 128 + dt * 32 + tx];
        }
        __syncthreads();
#pragma unroll
        for (int p = 0; p < 4; p++) {
            int d = p * 8 + ty;
            g_wst2[(size_t)(dt * 32 + d) * 128 + h * 32 + tx] =
                __float2half(sm[tx][d] * 0.25f);
        }
    } else if (b < 920) {
        int rel = b - 664;                       // 256 = 4h * 4kt * 16dt
        int h = rel >> 6, rem = rel & 63;
        int kt = rem >> 4, dt = rem & 15;
        int ty = tid >> 5, tx = tid & 31;
#pragma unroll
        for (int p = 0; p < 4; p++) {
            int k = p * 8 + ty;
            sm[k][tx] = W3[(size_t)(kt * 32 + k) * 2048 + h * 512 + dt * 32 + tx];
        }
        __syncthreads();
#pragma unroll
        for (int p = 0; p < 4; p++) {
            int d = p * 8 + ty;
            g_wst3[(size_t)(dt * 32 + d) * 512 + h * 128 + kt * 32 + tx] =
                __float2half(sm[tx][d] * 0.25f);
        }
    } else if (b < 1008) {
        int gw = (b - 920) * 8 + (tid >> 5);
        int lane = tid & 31;
        int L, e;
        if (gw < 64)       { L = 0; e = gw; }
        else if (gw < 192) { L = 1; e = gw - 64; }
        else               { L = 2; e = gw - 192; }
        if (L == 2 && e >= 512) return;
        int K    = (L == 0) ? 16 : (L == 1) ? 32 : 128;
        int dout = (L == 0) ? 32 : (L == 1) ? 128 : 512;
        const float* W  = (L == 0) ? W1  : (L == 1) ? W2  : W3;
        const float* as = (L == 0) ? as1 : (L == 1) ? as2 : as3;
        const float* ad = (L == 0) ? ad1 : (L == 1) ? ad2 : ad3;
        int h = e / K, k = e % K;
        const float* wr = W + (size_t)k * (H * dout) + h * dout;
        float vs = 0.f, vd = 0.f;
        for (int d = lane; d < dout; d += 32) {
            float w = wr[d];
            vs += w * as[h * dout + d];
            vd += w * ad[h * dout + d];
        }
#pragma unroll
        for (int o = 16; o > 0; o >>= 1) {
            vs += __shfl_xor_sync(0xffffffffu, vs, o);
            vd += __shfl_xor_sync(0xffffffffu, vd, o);
        }
        if (lane == 0) {
            g_usrc[L][e] = vs;
            g_udst[L][e] = vd;
        }
    } else {
        int L = b - 1008;
        int dout = (L == 0) ? 32 : (L == 1) ? 128 : 512;
        const float* We = (L == 0) ? We1 : (L == 1) ? We2 : We3;
        const float* ae = (L == 0) ? ae1 : (L == 1) ? ae2 : ae3;
        int HC = H * dout;
        int wrp = tid >> 5, lane = tid & 31;
#pragma unroll
        for (int i = 0; i < 4; i++) {
            int e = wrp * 4 + i;
            int t = e >> 2, h = e & 3;
            float s = 0.f;
            for (int c = lane; c < dout; c += 32)
                s += We[t * HC + h * dout + c] * ae[h * dout + c];
#pragma unroll
            for (int o = 16; o > 0; o >>= 1)
                s += __shfl_xor_sync(0xffffffffu, s, o);
            if (lane == 0) {
                sm[t][h] = s;
                g_etab[L][t * H + h] = s;
            }
        }
        __syncthreads();
        if (tid < H) {
            float s = 0.f;
            for (int t = 0; t < T; t++) s += sm[t][tid];
            g_etab[L][T * H + tid] = s * (1.0f / T);
        }
    }
}

// scan also RE-ZEROES g_deg so the next call starts clean (call-invariant).
__global__ void k_scan() {
    __shared__ int sh[1024];
    int t = threadIdx.x;
    int base = t * 32;
    int loc[32];
    int sum = 0;
#pragma unroll
    for (int i = 0; i < 32; i++) { loc[i] = sum; sum += g_deg[base + i]; g_deg[base + i] = 0; }
    sh[t] = sum;
    __syncthreads();
    for (int off = 1; off < 1024; off <<= 1) {
        int v = (t >= off) ? sh[t - off] : 0;
        __syncthreads();
        if (t >= off) sh[t] += v;
        __syncthreads();
    }
    int prev = (t == 0) ? 0 : sh[t - 1];
#pragma unroll
    for (int i = 0; i < 32; i++) {
        int v = prev + loc[i];
        g_rowptr[base + i] = v;
        g_fill[base + i]   = v;
    }
    if (t == 1023) g_rowptr[N] = sh[1023];
}

// ---- fused scatter + L1 scores (independent work, overlapped) -------------
// blocks [0,640): edge scatter    [640, 640+2048): L1 scores, 2 nodes/warp
__global__ void k_scat_scores(const float* __restrict__ x) {
    int b = blockIdx.x, tid = threadIdx.x;
    if (b < 640) {
        int e = b * 256 + tid;
        if (e >= E) return;
        int pos = atomicAdd(&g_fill[g_dst[e]], 1);
        g_se[pos] = g_src[e] | (g_et[e] << 20);
    } else {
        // 2 nodes per warp: lanes 0-15 node 2gw, lanes 16-31 node 2gw+1
        int gw = (b - 640) * 8 + (tid >> 5);
        int lane = tid & 31, sl = lane & 15;
        int n = gw * 2 + (lane >> 4);
        float xv = x[n * 16 + sl];
        float p[8];
#pragma unroll
        for (int h = 0; h < H; h++) {
            p[h]     = xv * g_usrc[0][h * 16 + sl];
            p[h + 4] = xv * g_udst[0][h * 16 + sl];
        }
#pragma unroll
        for (int o = 8; o > 0; o >>= 1)
#pragma unroll
            for (int i = 0; i < 8; i++)
                p[i] += __shfl_xor_sync(0xffffffffu, p[i], o);
        if (sl < 8) {
            float v = p[sl];
            if (sl < 4) g_ssrc[n * H + sl] = v;
            else        g_sdst[n * H + (sl - 4)] = v;
        }
    }
}

// ------- fused alpha + softmax + aggregation, K<=32 (warp per node) --------
template <int K, bool CVT>
__global__ void k_gat_edge(const float* __restrict__ h, float* __restrict__ aggf, int L) {
    constexpr int CAP = 128;
    __shared__ int   s_pk[4][CAP];
    __shared__ float s_aw[4][CAP][H];

    int lane = threadIdx.x & 31;
    int grp  = threadIdx.x >> 5;
    int n    = blockIdx.x * 4 + grp;
    int b0 = g_rowptr[n], b1 = g_rowptr[n + 1];
    int D = b1 - b0;

    float a0 = 0.f, a1 = 0.f, a2 = 0.f, a3 = 0.f;

    if (D <= CAP) {
        for (int j = lane; j < D; j += 32) s_pk[grp][j] = g_se[b0 + j];
        __syncwarp();
        {
            int hh = lane & 3;
            int j0 = lane >> 2;
            float sd = g_sdst[n * H + hh];
            float m = -1e30f, s = 0.f;
            for (int jj = j0; jj < D; jj += 8) {
                int p = s_pk[grp][jj];
                int src = p & 0xFFFFF, et = p >> 20;
                float a = g_ssrc[src * H + hh] + sd + g_etab[L][et * H + hh];
                a = (a > 0.f) ? a : NEG * a;
                s_aw[grp][jj][hh] = a;
                float mn = fmaxf(m, a);
                s = s * __expf(m - mn) + __expf(a - mn);
                m = mn;
            }
#pragma unroll
            for (int o = 4; o <= 16; o <<= 1) {
                float m2 = __shfl_xor_sync(0xffffffffu, m, o);
                float s2 = __shfl_xor_sync(0xffffffffu, s, o);
                float mn = fmaxf(m, m2);
                s = s * __expf(m - mn) + s2 * __expf(m2 - mn);
                m = mn;
            }
            float inv = 1.f / s;
            for (int jj = j0; jj < D; jj += 8)
                s_aw[grp][jj][hh] = __expf(s_aw[grp][jj][hh] - m) * inv;
        }
        __syncwarp();
        if (lane < K) {
            // strip-of-4: batch independent gathers (MLP=4)
            int jj = 0;
            for (; jj + 4 <= D; jj += 4) {
                int s0 = s_pk[grp][jj]     & 0xFFFFF;
                int s1 = s_pk[grp][jj + 1] & 0xFFFFF;
                int s2 = s_pk[grp][jj + 2] & 0xFFFFF;
                int s3 = s_pk[grp][jj + 3] & 0xFFFFF;
                float v0 = h[(size_t)s0 * K + lane];
                float v1 = h[(size_t)s1 * K + lane];
                float v2 = h[(size_t)s2 * K + lane];
                float v3 = h[(size_t)s3 * K + lane];
                a0 += s_aw[grp][jj][0] * v0 + s_aw[grp][jj + 1][0] * v1
                    + s_aw[grp][jj + 2][0] * v2 + s_aw[grp][jj + 3][0] * v3;
                a1 += s_aw[grp][jj][1] * v0 + s_aw[grp][jj + 1][1] * v1
                    + s_aw[grp][jj + 2][1] * v2 + s_aw[grp][jj + 3][1] * v3;
                a2 += s_aw[grp][jj][2] * v0 + s_aw[grp][jj + 1][2] * v1
                    + s_aw[grp][jj + 2][2] * v2 + s_aw[grp][jj + 3][2] * v3;
                a3 += s_aw[grp][jj][3] * v0 + s_aw[grp][jj + 1][3] * v1
                    + s_aw[grp][jj + 2][3] * v2 + s_aw[grp][jj + 3][3] * v3;
            }
            for (; jj < D; jj++) {
                int src = s_pk[grp][jj] & 0xFFFFF;
                float v = h[(size_t)src * K + lane];
                a0 += s_aw[grp][jj][0] * v;
                a1 += s_aw[grp][jj][1] * v;
                a2 += s_aw[grp][jj][2] * v;
                a3 += s_aw[grp][jj][3] * v;
            }
        }
    } else {
        int hh = lane & 3;
        int j0 = lane >> 2;
        float sd = g_sdst[n * H + hh];
        float m = -1e30f, s = 0.f;
        for (int jj = j0; jj < D; jj += 8) {
            int p = g_se[b0 + jj];
            int src = p & 0xFFFFF, et = p >> 20;
            float a = g_ssrc[src * H + hh] + sd + g_etab[L][et * H + hh];
            a = (a > 0.f) ? a : NEG * a;
            float mn = fmaxf(m, a);
            s = s * __expf(m - mn) + __expf(a - mn);
            m = mn;
        }
#pragma unroll
        for (int o = 4; o <= 16; o <<= 1) {
            float m2 = __shfl_xor_sync(0xffffffffu, m, o);
            float s2 = __shfl_xor_sync(0xffffffffu, s, o);
            float mn = fmaxf(m, m2);
            s = s * __expf(m - mn) + s2 * __expf(m2 - mn);
            m = mn;
        }
        float inv = 1.f / s;
        float m4[H], i4[H];
#pragma unroll
        for (int h4 = 0; h4 < H; h4++) {
            m4[h4] = __shfl_sync(0xffffffffu, m, h4);
            i4[h4] = __shfl_sync(0xffffffffu, inv, h4);
        }
        if (lane < K) {
            float sd4[H];
#pragma unroll
            for (int h4 = 0; h4 < H; h4++) sd4[h4] = g_sdst[n * H + h4];
            for (int jj = 0; jj < D; jj++) {
                int p = g_se[b0 + jj];
                int src = p & 0xFFFFF, et = p >> 20;
                float v = h[(size_t)src * K + lane];
#pragma unroll
                for (int h4 = 0; h4 < H; h4++) {
                    float a = g_ssrc[src * H + h4] + sd4[h4] + g_etab[L][et * H + h4];
                    a = (a > 0.f) ? a : NEG * a;
                    float w = __expf(a - m4[h4]) * i4[h4];
                    if (h4 == 0) a0 += w * v;
                    else if (h4 == 1) a1 += w * v;
                    else if (h4 == 2) a2 += w * v;
                    else a3 += w * v;
                }
            }
        }
    }

    if (lane < K) {
        size_t base = (size_t)n * (H * K) + lane;
        if (CVT) {
            __half* ah = reinterpret_cast<__half*>(aggf);
            ah[base]         = __float2half(a0);
            ah[base + K]     = __float2half(a1);
            ah[base + 2 * K] = __float2half(a2);
            ah[base + 3 * K] = __float2half(a3);
        } else {
            aggf[base]         = a0;
            aggf[base + K]     = a1;
            aggf[base + 2 * K] = a2;
            aggf[base + 3 * K] = a3;
        }
    }
}

// ------- L3 edge kernel: 2 nodes per 128-thr block, half2 gathers ----------
__global__ void k_gat_edge3(const __half2* __restrict__ h2, __half2* __restrict__ agg2) {
    constexpr int CAP = 128;
    __shared__ int   s_pk[2][CAP];
    __shared__ float s_aw[2][CAP][H];
    __shared__ float s_ms[2][2][H];

    int grp  = threadIdx.x >> 6;
    int gtid = threadIdx.x & 63;
    int lane = threadIdx.x & 31;
    int wing = (threadIdx.x >> 5) & 1;
    int n = blockIdx.x * 2 + grp;
    int b0 = g_rowptr[n], b1 = g_rowptr[n + 1];
    int D = b1 - b0;
    bool fast = (D <= CAP);

    if (fast)
        for (int j = gtid; j < D; j += 64) s_pk[grp][j] = g_se[b0 + j];
    __syncthreads();

    if (wing == 0) {
        int hh = lane & 3;
        int j0 = lane >> 2;
        float sd = g_sdst[n * H + hh];
        float m = -1e30f, s = 0.f;
        if (fast) {
            for (int jj = j0; jj < D; jj += 8) {
                int p = s_pk[grp][jj];
                int src = p & 0xFFFFF, et = p >> 20;
                float a = g_ssrc[src * H + hh] + sd + g_etab[2][et * H + hh];
                a = (a > 0.f) ? a : NEG * a;
                s_aw[grp][jj][hh] = a;
                float mn = fmaxf(m, a);
                s = s * __expf(m - mn) + __expf(a - mn);
                m = mn;
            }
        } else {
            for (int jj = j0; jj < D; jj += 8) {
                int p = g_se[b0 + jj];
                int src = p & 0xFFFFF, et = p >> 20;
                float a = g_ssrc[src * H + hh] + sd + g_etab[2][et * H + hh];
                a = (a > 0.f) ? a : NEG * a;
                float mn = fmaxf(m, a);
                s = s * __expf(m - mn) + __expf(a - mn);
                m = mn;
            }
        }
#pragma unroll
        for (int o = 4; o <= 16; o <<= 1) {
            float m2 = __shfl_xor_sync(0xffffffffu, m, o);
            float s2 = __shfl_xor_sync(0xffffffffu, s, o);
            float mn = fmaxf(m, m2);
            s = s * __expf(m - mn) + s2 * __expf(m2 - mn);
            m = mn;
        }
        float inv = 1.f / s;
        if (fast) {
            for (int jj = j0; jj < D; jj += 8)
                s_aw[grp][jj][hh] = __expf(s_aw[grp][jj][hh] - m) * inv;
        } else if (lane < H) {
            s_ms[grp][0][lane] = m;
            s_ms[grp][1][lane] = inv;
        }
    }
    __syncthreads();

    float ax[H], ay[H];
#pragma unroll
    for (int h4 = 0; h4 < H; h4++) { ax[h4] = 0.f; ay[h4] = 0.f; }

    if (fast) {
        // strip-of-4: batch independent half2 gathers (MLP=4)
        int jj = 0;
        for (; jj + 4 <= D; jj += 4) {
            int s0 = s_pk[grp][jj]     & 0xFFFFF;
            int s1 = s_pk[grp][jj + 1] & 0xFFFFF;
            int s2 = s_pk[grp][jj + 2] & 0xFFFFF;
            int s3 = s_pk[grp][jj + 3] & 0xFFFFF;
            float2 v0 = __half22float2(h2[(size_t)s0 * 64 + gtid]);
            float2 v1 = __half22float2(h2[(size_t)s1 * 64 + gtid]);
            float2 v2 = __half22float2(h2[(size_t)s2 * 64 + gtid]);
            float2 v3 = __half22float2(h2[(size_t)s3 * 64 + gtid]);
#pragma unroll
            for (int h4 = 0; h4 < H; h4++) {
                float w0 = s_aw[grp][jj][h4],     w1 = s_aw[grp][jj + 1][h4];
                float w2 = s_aw[grp][jj + 2][h4], w3 = s_aw[grp][jj + 3][h4];
                ax[h4] += w0 * v0.x + w1 * v1.x + w2 * v2.x + w3 * v3.x;
                ay[h4] += w0 * v0.y + w1 * v1.y + w2 * v2.y + w3 * v3.y;
            }
        }
        for (; jj < D; jj++) {
            int src = s_pk[grp][jj] & 0xFFFFF;
            float2 v = __half22float2(h2[(size_t)src * 64 + gtid]);
#pragma unroll
            for (int h4 = 0; h4 < H; h4++) {
                float w = s_aw[grp][jj][h4];
                ax[h4] += w * v.x;
                ay[h4] += w * v.y;
            }
        }
    } else {
        float m4[H], i4[H], sd4[H];
#pragma unroll
        for (int h4 = 0; h4 < H; h4++) {
            m4[h4] = s_ms[grp][0][h4];
            i4[h4] = s_ms[grp][1][h4];
            sd4[h4] = g_sdst[n * H + h4];
        }
        for (int jj = 0; jj < D; jj++) {
            int p = g_se[b0 + jj];
            int src = p & 0xFFFFF, et = p >> 20;
            float2 v = __half22float2(h2[(size_t)src * 64 + gtid]);
#pragma unroll
            for (int h4 = 0; h4 < H; h4++) {
                float a = g_ssrc[src * H + h4] + sd4[h4] + g_etab[2][et * H + h4];
                a = (a > 0.f) ? a : NEG * a;
                float w = __expf(a - m4[h4]) * i4[h4];
                ax[h4] += w * v.x;
                ay[h4] += w * v.y;
            }
        }
    }

    size_t base = (size_t)n * 256 + gtid;
#pragma unroll
    for (int h4 = 0; h4 < H; h4++)
        agg2[base + h4 * 64] = __floats2half2_rn(ax[h4], ay[h4]);
}

// --- L1 GEMM (warp = node) + FUSED layer-2 scores (butterfly reduction) ----
__global__ void k_gemm_small(const float* __restrict__ A, const float* __restrict__ B,
                             const float* __restrict__ bias, float* __restrict__ C) {
    constexpr int K = 64, NN = 32;
    int idx = blockIdx.x * blockDim.x + threadIdx.x;
    int n = idx >> 5, lane = idx & 31;
    if (n >= N) return;
    const float* ar = A + (size_t)n * K;
    float acc = 0.f;
    for (int k = 0; k < K; k++) acc += ar[k] * B[k * NN + lane];
    acc += bias[lane];
    acc = fmaxf(acc, 0.f);
    C[(size_t)n * NN + lane] = acc;

    float rs[H], rd[H];
#pragma unroll
    for (int h = 0; h < H; h++) {
        rs[h] = acc * g_usrc[1][h * 32 + lane];
        rd[h] = acc * g_udst[1][h * 32 + lane];
#pragma unroll
        for (int o = 16; o > 0; o >>= 1) {
            rs[h] += __shfl_xor_sync(0xffffffffu, rs[h], o);
            rd[h] += __shfl_xor_sync(0xffffffffu, rd[h], o);
        }
    }
    if (lane == 0) {
#pragma unroll
        for (int h = 0; h < H; h++) {
            g_ssrc[n * H + h] = rs[h];
            g_sdst[n * H + h] = rd[h];
        }
    }
}

// ------- fp16 TC GEMM: 128x128x32 tiles, 3-stage cp.async ring -------------
constexpr int STG_BYTES = 128 * 40 * 2 * 2;    // A+B per stage = 20480 B
constexpr int SMEM_HF   = 3 * STG_BYTES;       // 61440 B

__device__ __forceinline__ uint32_t smem_u32(const void* p) {
    uint32_t a;
    asm("{ .reg .u64 t; cvta.to.shared.u64 t, %1; cvt.u32.u64 %0, t; }" : "=r"(a) : "l"(p));
    return a;
}

__global__ void __launch_bounds__(256, 2)
k_gemm_hf(const __half* __restrict__ A, const __half* __restrict__ Bt,
          const float* __restrict__ bias, float* __restrict__ C,
          __half2* __restrict__ Ch2, const float* __restrict__ Usrc,
          const float* __restrict__ Udst, int K, int NN, int relu) {
    extern __shared__ char hsm[];
    int tid = threadIdx.x;
    int wid = tid >> 5, lane = tid & 31;
    int bm = blockIdx.y * 128, bn = blockIdx.x * 128;
    int wm = (wid >> 2) * 64;
    int wn = (wid & 3) * 32;
    int grp = lane >> 2, tig = lane & 3;

    auto stA = [&](int s) { return reinterpret_cast<__half*>(hsm + s * STG_BYTES); };
    auto stB = [&](int s) { return reinterpret_cast<__half*>(hsm + s * STG_BYTES) + 128 * 40; };

    float c[4][4][4];
#pragma unroll
    for (int mt = 0; mt < 4; mt++)
#pragma unroll
        for (int nt = 0; nt < 4; nt++)
#pragma unroll
            for (int q = 0; q < 4; q++) c[mt][nt][q] = 0.f;

    int nk = K >> 5;

    auto copy_tile = [&](int s, int k0) {
        __half* As = stA(s);
        __half* Bs = stB(s);
#pragma unroll
        for (int i = 0; i < 2; i++) {
            int f = tid + i * 256;
            int m = f >> 2, q = f & 3;
            uint32_t dst = smem_u32(&As[m * 40 + q * 8]);
            const __half* src = &A[(size_t)(bm + m) * K + k0 + q * 8];
            asm volatile("cp.async.ca.shared.global [%0], [%1], 16;" :: "r"(dst), "l"(src));
        }
#pragma unroll
        for (int i = 0; i < 2; i++) {
            int f = tid + i * 256;
            int nrow = f >> 2, q = f & 3;
            uint32_t dst = smem_u32(&Bs[nrow * 40 + q * 8]);
            const __half* src = &Bt[(size_t)(bn + nrow) * K + k0 + q * 8];
            asm volatile("cp.async.ca.shared.global [%0], [%1], 16;" :: "r"(dst), "l"(src));
        }
        asm volatile("cp.async.commit_group;");
    };

    copy_tile(0, 0);
    copy_tile(1, 32);

    int mtx = lane >> 3;
    int rin = lane & 7;

    for (int it = 0; it < nk; it++) {
        int cur = it % 3;
        if (it + 1 < nk) asm volatile("cp.async.wait_group 1;");
        else             asm volatile("cp.async.wait_group 0;");
        __syncthreads();
        if (it + 2 < nk) copy_tile((it + 2) % 3, (it + 2) * 32);

        __half* As = stA(cur);
        __half* Bs = stB(cur);
#pragma unroll
        for (int ks = 0; ks < 2; ks++) {
            uint32_t a[4][4], b[4][2];
#pragma unroll
            for (int mt = 0; mt < 4; mt++) {
                int row = wm + mt * 16 + (mtx & 1) * 8 + rin;
                int col = ks * 16 + (mtx >> 1) * 8;
                uint32_t addr = smem_u32(&As[row * 40 + col]);
                asm volatile("ldmatrix.sync.aligned.m8n8.x4.shared.b16 {%0,%1,%2,%3}, [%4];"
                             : "=r"(a[mt][0]), "=r"(a[mt][1]), "=r"(a[mt][2]), "=r"(a[mt][3])
                             : "r"(addr));
            }
#pragma unroll
            for (int np = 0; np < 2; np++) {
                int row = wn + np * 16 + (mtx >> 1) * 8 + rin;
                int col = ks * 16 + (mtx & 1) * 8;
                uint32_t addr = smem_u32(&Bs[row * 40 + col]);
                asm volatile("ldmatrix.sync.aligned.m8n8.x4.shared.b16 {%0,%1,%2,%3}, [%4];"
                             : "=r"(b[np * 2][0]), "=r"(b[np * 2][1]),
                               "=r"(b[np * 2 + 1][0]), "=r"(b[np * 2 + 1][1])
                             : "r"(addr));
            }
#pragma unroll
            for (int mt = 0; mt < 4; mt++)
#pragma unroll
                for (int nt = 0; nt < 4; nt++) {
                    asm volatile(
                        "mma.sync.aligned.m16n8k16.row.col.f32.f16.f16.f32 "
                        "{%0,%1,%2,%3}, {%4,%5,%6,%7}, {%8,%9}, {%0,%1,%2,%3};"
                        : "+f"(c[mt][nt][0]), "+f"(c[mt][nt][1]),
                          "+f"(c[mt][nt][2]), "+f"(c[mt][nt][3])
                        : "r"(a[mt][0]), "r"(a[mt][1]), "r"(a[mt][2]), "r"(a[mt][3]),
                          "r"(b[nt][0]), "r"(b[nt][1]));
                }
        }
        __syncthreads();
    }

    float bv[4][2];
#pragma unroll
    for (int nt = 0; nt < 4; nt++) {
        int col = bn + wn + nt * 8 + tig * 2;
        bv[nt][0] = bias[col];
        bv[nt][1] = bias[col + 1];
    }

#pragma unroll
    for (int mt = 0; mt < 4; mt++) {
#pragma unroll
        for (int nt = 0; nt < 4; nt++) {
            int col = bn + wn + nt * 8 + tig * 2;
            int r0 = bm + wm + mt * 16 + grp;
            float v00 = c[mt][nt][0] + bv[nt][0], v01 = c[mt][nt][1] + bv[nt][1];
            float v10 = c[mt][nt][2] + bv[nt][0], v11 = c[mt][nt][3] + bv[nt][1];
            if (relu) {
                v00 = fmaxf(v00, 0.f); v01 = fmaxf(v01, 0.f);
                v10 = fmaxf(v10, 0.f); v11 = fmaxf(v11, 0.f);
            }
            C[(size_t)r0 * NN + col]           = v00;
            C[(size_t)r0 * NN + col + 1]       = v01;
            C[(size_t)(r0 + 8) * NN + col]     = v10;
            C[(size_t)(r0 + 8) * NN + col + 1] = v11;
            if (Ch2) {
                Ch2[((size_t)r0 * NN + col) >> 1]       = __floats2half2_rn(v00, v01);
                Ch2[((size_t)(r0 + 8) * NN + col) >> 1] = __floats2half2_rn(v10, v11);
            }
        }
    }

    if (Usrc) {
        float* s_sc = reinterpret_cast<float*>(hsm);
        for (int i = tid; i < 128 * 8; i += 256) s_sc[i] = 0.f;
        __syncthreads();
#pragma unroll
        for (int h8 = 0; h8 < 8; h8++) {
            const float* U = (h8 < 4) ? (Usrc + h8 * NN) : (Udst + (h8 - 4) * NN);
            float u[4][2];
#pragma unroll
            for (int nt = 0; nt < 4; nt++) {
                int col = wn + nt * 8 + tig * 2;
                u[nt][0] = U[col];
                u[nt][1] = U[col + 1];
            }
#pragma unroll
            for (int mt = 0; mt < 4; mt++) {
                int r0 = wm + mt * 16 + grp;
                float p0 = 0.f, p1 = 0.f;
#pragma unroll
                for (int nt = 0; nt < 4; nt++) {
                    float v00 = c[mt][nt][0] + bv[nt][0], v01 = c[mt][nt][1] + bv[nt][1];
                    float v10 = c[mt][nt][2] + bv[nt][0], v11 = c[mt][nt][3] + bv[nt][1];
                    v00 = fmaxf(v00, 0.f); v01 = fmaxf(v01, 0.f);
                    v10 = fmaxf(v10, 0.f); v11 = fmaxf(v11, 0.f);
                    p0 += v00 * u[nt][0] + v01 * u[nt][1];
                    p1 += v10 * u[nt][0] + v11 * u[nt][1];
                }
                p0 += __shfl_xor_sync(0xffffffffu, p0, 1);
                p0 += __shfl_xor_sync(0xffffffffu, p0, 2);
                p1 += __shfl_xor_sync(0xffffffffu, p1, 1);
                p1 += __shfl_xor_sync(0xffffffffu, p1, 2);
                if (tig == 0) {
                    atomicAdd(&s_sc[r0 * 8 + h8], p0);
                    atomicAdd(&s_sc[(r0 + 8) * 8 + h8], p1);
                }
            }
        }
        __syncthreads();
        for (int i = tid; i < 128 * 8; i += 256) {
            int r = i >> 3, h8 = i & 7;
            float v = s_sc[i];
            if (h8 < 4) g_ssrc[(bm + r) * H + h8] = v;
            else        g_sdst[(bm + r) * H + (h8 - 4)] = v;
        }
    }
}

// ---------------------------------------------------------------------------
extern "C" void kernel_launch(void* const* d_in, const int* in_sizes, int n_in,
                              void* d_out, int out_size) {
    const float* x   = (const float*)d_in[0];
    const int*   eit = (const int*)d_in[1];
    const float* W1  = (const float*)d_in[2];
    const float* We1 = (const float*)d_in[3];
    const float* as1 = (const float*)d_in[4];
    const float* ad1 = (const float*)d_in[5];
    const float* ae1 = (const float*)d_in[6];
    const float* b1  = (const float*)d_in[7];
    const float* W2  = (const float*)d_in[8];
    const float* We2 = (const float*)d_in[9];
    const float* as2 = (const float*)d_in[10];
    const float* ad2 = (const float*)d_in[11];
    const float* ae2 = (const float*)d_in[12];
    const float* b2  = (const float*)d_in[13];
    const float* W3  = (const float*)d_in[14];
    const float* We3 = (const float*)d_in[15];
    const float* as3 = (const float*)d_in[16];
    const float* ad3 = (const float*)d_in[17];
    const float* ae3 = (const float*)d_in[18];
    const float* b3  = (const float*)d_in[19];
    float* out = (float*)d_out;

    float *agg = nullptr, *hbuf = nullptr, *wst1 = nullptr;
    float *usrc = nullptr, *udst = nullptr;
    __half *wst2 = nullptr, *wst3 = nullptr;
    __half2 *hbufh2 = nullptr;
    cudaGetSymbolAddress((void**)&agg, g_agg);
    cudaGetSymbolAddress((void**)&hbuf, g_hbuf);
    cudaGetSymbolAddress((void**)&wst1, g_wst1);
    cudaGetSymbolAddress((void**)&wst2, g_wst2);
    cudaGetSymbolAddress((void**)&wst3, g_wst3);
    cudaGetSymbolAddress((void**)&hbufh2, g_hbufh2);
    cudaGetSymbolAddress((void**)&usrc, g_usrc);
    cudaGetSymbolAddress((void**)&udst, g_udst);
    const __half* aggh = (const __half*)agg;
    __half2* agg2 = (__half2*)agg;

    cudaFuncSetAttribute(k_gemm_hf, cudaFuncAttributeMaxDynamicSharedMemorySize, SMEM_HF);

    // ---- fused graph build + prep, scan, then fused scatter + L1 scores ---
    k_setup<<<1011, 256>>>(eit,
                           W1, as1, ad1, We1, ae1,
                           W2, as2, ad2, We2, ae2,
                           W3, as3, ad3, We3, ae3);
    k_scan<<<1, 1024>>>();
    k_scat_scores<<<640 + 2048, 256>>>(x);

    // ---- layer 1: K=16 -> dout=32 (SIMT; gemm fuses L2 scores) ----
    k_gat_edge<16, false><<<N / 4, 128>>>(x, agg, 0);
    k_gemm_small<<<(N * 32) / 256, 256>>>(agg, wst1, b1, hbuf);

    // ---- layer 2: K=32 -> dout=128 (TC GEMM fuses L3 scores + half2 out) --
    k_gat_edge<32, true><<<N / 4, 128>>>(hbuf, agg, 1);
    k_gemm_hf<<<dim3(1, N / 128), 256, SMEM_HF>>>(aggh, wst2, b2, hbuf, hbufh2,
                                                  usrc + 2 * 512, udst + 2 * 512, 128, 128, 1);

    // ---- layer 3: K=128 -> dout=512 (half2 gathers; TC GEMM -> out) -------
    k_gat_edge3<<<N / 2, 128>>>(hbufh2, agg2);
    k_gemm_hf<<<dim3(4, N / 128), 256, SMEM_HF>>>(aggh, wst3, b3, out, nullptr,
                                                  nullptr, nullptr, 512, 512, 0);
}

// round 15
// speedup vs baseline: 1.4165x; 1.0132x over previous
#include <cuda_runtime.h>
#include <cuda_fp16.h>
#include <cstdint>

constexpr int N    = 32768;
constexpr int EPER = 16384;
constexpr int T    = 8;
constexpr int E0   = T * EPER;   // 131072 typed edges
constexpr int E    = E0 + N;     // + self loops = 163840
constexpr int H    = 4;
constexpr float NEG = 0.2f;

// ---------------------------- scratch (device globals) ---------------------
__device__ float   g_agg[(size_t)N * 512];   // L2/L3 half agg (aliased)
__device__ float   g_hbuf[(size_t)N * 128];  // inter-layer activations (fp32)
__device__ __half2 g_hbufh2[(size_t)N * 64]; // half mirror of hbuf for L3 gathers
// score double buffers: A = L1 & L3 scores, B = L2 scores (avoids WAR race
// when a fused kernel writes next-layer scores while others read this layer's)
__device__ float   g_ssrcA[N * H], g_sdstA[N * H];
__device__ float   g_ssrcB[N * H], g_sdstB[N * H];
__device__ float   g_etab[3][(T + 1) * H];
__device__ float   g_usrc[3][512];
__device__ float   g_udst[3][512];
__device__ float   g_wst1[64 * 32];          // L1 fp32 [H*K, dout]
__device__ __half  g_wst2[128 * 128];        // L2 half [dout, H*K] K-major
__device__ __half  g_wst3[512 * 512];        // L3 half [dout, H*K] K-major
__device__ int     g_se[E];                  // dst-sorted packed edges: src | (et<<20)
__device__ int     g_src[E], g_dst[E], g_et[E];
__device__ int     g_deg[N], g_rowptr[N + 1], g_fill[N];

// ---------- ONE setup kernel: graph build + all weight prep (overlapped) ---
__global__ void k_setup(const int* __restrict__ eit,
    const float* __restrict__ W1, const float* __restrict__ as1,
    const float* __restrict__ ad1, const float* __restrict__ We1,
    const float* __restrict__ ae1,
    const float* __restrict__ W2, const float* __restrict__ as2,
    const float* __restrict__ ad2, const float* __restrict__ We2,
    const float* __restrict__ ae2,
    const float* __restrict__ W3, const float* __restrict__ as3,
    const float* __restrict__ ad3, const float* __restrict__ We3,
    const float* __restrict__ ae3) {
    __shared__ float sm[32][33];
    int b = blockIdx.x, tid = threadIdx.x;

    if (b < 640) {
        int e = b * 256 + tid;
        if (e >= E) return;
        int s, d, t;
        if (e < E0) {
            t = e / EPER;
            int i = e - t * EPER;
            s = eit[t * 2 * EPER + i];
            d = eit[t * 2 * EPER + EPER + i];
        } else {
            s = d = e - E0;
            t = T;
        }
        g_src[e] = s; g_dst[e] = d; g_et[e] = t;
        atomicAdd(&g_deg[d], 1);
    } else if (b < 648) {
        int idx = (b - 640) * 256 + tid;         // 2048 = 64*32
        int d = idx % 32, hk = idx / 32;
        int h = hk / 16, k = hk % 16;
        g_wst1[idx] = W1[(size_t)k * 128 + h * 32 + d] * 0.25f;
    } else if (b < 664) {
        int rel = b - 648;
        int h = rel >> 2, dt = rel & 3;
        int ty = tid >> 5, tx = tid & 31;
#pragma unroll
        for (int p = 0; p < 4; p++) {
            int k = p * 8 + ty;
            sm[k][tx] = W2[(size_t)k * 512 + h * 128 + dt * 32 + tx];
        }
        __syncthreads();
#pragma unroll
        for (int p = 0; p < 4; p++) {
            int d = p * 8 + ty;
            g_wst2[(size_t)(dt * 32 + d) * 128 + h * 32 + tx] =
                __float2half(sm[tx][d] * 0.25f);
        }
    } else if (b < 920) {
        int rel = b - 664;                       // 256 = 4h * 4kt * 16dt
        int h = rel >> 6, rem = rel & 63;
        int kt = rem >> 4, dt = rem & 15;
        int ty = tid >> 5, tx = tid & 31;
#pragma unroll
        for (int p = 0; p < 4; p++) {
            int k = p * 8 + ty;
            sm[k][tx] = W3[(size_t)(kt * 32 + k) * 2048 + h * 512 + dt * 32 + tx];
        }
        __syncthreads();
#pragma unroll
        for (int p = 0; p < 4; p++) {
            int d = p * 8 + ty;
            g_wst3[(size_t)(dt * 32 + d) * 512 + h * 128 + kt * 32 + tx] =
                __float2half(sm[tx][d] * 0.25f);
        }
    } else if (b < 1008) {
        int gw = (b - 920) * 8 + (tid >> 5);
        int lane = tid & 31;
        int L, e;
        if (gw < 64)       { L = 0; e = gw; }
        else if (gw < 192) { L = 1; e = gw - 64; }
        else               { L = 2; e = gw - 192; }
        if (L == 2 && e >= 512) return;
        int K    = (L == 0) ? 16 : (L == 1) ? 32 : 128;
        int dout = (L == 0) ? 32 : (L == 1) ? 128 : 512;
        const float* W  = (L == 0) ? W1  : (L == 1) ? W2  : W3;
        const float* as = (L == 0) ? as1 : (L == 1) ? as2 : as3;
        const float* ad = (L == 0) ? ad1 : (L == 1) ? ad2 : ad3;
        int h = e / K, k = e % K;
        const float* wr = W + (size_t)k * (H * dout) + h * dout;
        float vs = 0.f, vd = 0.f;
        for (int d = lane; d < dout; d += 32) {
            float w = wr[d];
            vs += w * as[h * dout + d];
            vd += w * ad[h * dout + d];
        }
#pragma unroll
        for (int o = 16; o > 0; o >>= 1) {
            vs += __shfl_xor_sync(0xffffffffu, vs, o);
            vd += __shfl_xor_sync(0xffffffffu, vd, o);
        }
        if (lane == 0) {
            g_usrc[L][e] = vs;
            g_udst[L][e] = vd;
        }
    } else {
        int L = b - 1008;
        int dout = (L == 0) ? 32 : (L == 1) ? 128 : 512;
        const float* We = (L == 0) ? We1 : (L == 1) ? We2 : We3;
        const float* ae = (L == 0) ? ae1 : (L == 1) ? ae2 : ae3;
        int HC = H * dout;
        int wrp = tid >> 5, lane = tid & 31;
#pragma unroll
        for (int i = 0; i < 4; i++) {
            int e = wrp * 4 + i;
            int t = e >> 2, h = e & 3;
            float s = 0.f;
            for (int c = lane; c < dout; c += 32)
                s += We[t * HC + h * dout + c] * ae[h * dout + c];
#pragma unroll
            for (int o = 16; o > 0; o >>= 1)
                s += __shfl_xor_sync(0xffffffffu, s, o);
            if (lane == 0) {
                sm[t][h] = s;
                g_etab[L][t * H + h] = s;
            }
        }
        __syncthreads();
        if (tid < H) {
            float s = 0.f;
            for (int t = 0; t < T; t++) s += sm[t][tid];
            g_etab[L][T * H + tid] = s * (1.0f / T);
        }
    }
}

// scan also RE-ZEROES g_deg (call-invariant).
__global__ void k_scan() {
    __shared__ int sh[1024];
    int t = threadIdx.x;
    int base = t * 32;
    int loc[32];
    int sum = 0;
#pragma unroll
    for (int i = 0; i < 32; i++) { loc[i] = sum; sum += g_deg[base + i]; g_deg[base + i] = 0; }
    sh[t] = sum;
    __syncthreads();
    for (int off = 1; off < 1024; off <<= 1) {
        int v = (t >= off) ? sh[t - off] : 0;
        __syncthreads();
        if (t >= off) sh[t] += v;
        __syncthreads();
    }
    int prev = (t == 0) ? 0 : sh[t - 1];
#pragma unroll
    for (int i = 0; i < 32; i++) {
        int v = prev + loc[i];
        g_rowptr[base + i] = v;
        g_fill[base + i]   = v;
    }
    if (t == 1023) g_rowptr[N] = sh[1023];
}

// ---- fused scatter + L1 scores (writes buffer A) ---------------------------
__global__ void k_scat_scores(const float* __restrict__ x) {
    int b = blockIdx.x, tid = threadIdx.x;
    if (b < 640) {
        int e = b * 256 + tid;
        if (e >= E) return;
        int pos = atomicAdd(&g_fill[g_dst[e]], 1);
        g_se[pos] = g_src[e] | (g_et[e] << 20);
    } else {
        int gw = (b - 640) * 8 + (tid >> 5);
        int lane = tid & 31, sl = lane & 15;
        int n = gw * 2 + (lane >> 4);
        float xv = x[n * 16 + sl];
        float p[8];
#pragma unroll
        for (int h = 0; h < H; h++) {
            p[h]     = xv * g_usrc[0][h * 16 + sl];
            p[h + 4] = xv * g_udst[0][h * 16 + sl];
        }
#pragma unroll
        for (int o = 8; o > 0; o >>= 1)
#pragma unroll
            for (int i = 0; i < 8; i++)
                p[i] += __shfl_xor_sync(0xffffffffu, p[i], o);
        if (sl < 8) {
            float v = p[sl];
            if (sl < 4) g_ssrcA[n * H + sl] = v;
            else        g_sdstA[n * H + (sl - 4)] = v;
        }
    }
}

// ---- shared edge-softmax helper (explicit score-buffer pointers) ----------
__device__ __forceinline__ void warp_softmax(const float* __restrict__ ssrc,
                                             const float* __restrict__ sdst,
                                             int n, int L, int D,
                                             const int* s_pk, float (*s_aw)[H],
                                             int lane) {
    int hh = lane & 3;
    int j0 = lane >> 2;
    float sd = sdst[n * H + hh];
    float m = -1e30f, s = 0.f;
    for (int jj = j0; jj < D; jj += 8) {
        int p = s_pk[jj];
        int src = p & 0xFFFFF, et = p >> 20;
        float a = ssrc[src * H + hh] + sd + g_etab[L][et * H + hh];
        a = (a > 0.f) ? a : NEG * a;
        s_aw[jj][hh] = a;
        float mn = fmaxf(m, a);
        s = s * __expf(m - mn) + __expf(a - mn);
        m = mn;
    }
#pragma unroll
    for (int o = 4; o <= 16; o <<= 1) {
        float m2 = __shfl_xor_sync(0xffffffffu, m, o);
        float s2 = __shfl_xor_sync(0xffffffffu, s, o);
        float mn = fmaxf(m, m2);
        s = s * __expf(m - mn) + s2 * __expf(m2 - mn);
        m = mn;
    }
    float inv = 1.f / s;
    for (int jj = j0; jj < D; jj += 8)
        s_aw[jj][hh] = __expf(s_aw[jj][hh] - m) * inv;
}

__device__ __forceinline__ void warp_softmax_stats(const float* __restrict__ ssrc,
                                                   const float* __restrict__ sdst,
                                                   int n, int L, int D, int b0,
                                                   float* m4, float* i4, int lane) {
    int hh = lane & 3;
    int j0 = lane >> 2;
    float sd = sdst[n * H + hh];
    float m = -1e30f, s = 0.f;
    for (int jj = j0; jj < D; jj += 8) {
        int p = g_se[b0 + jj];
        int src = p & 0xFFFFF, et = p >> 20;
        float a = ssrc[src * H + hh] + sd + g_etab[L][et * H + hh];
        a = (a > 0.f) ? a : NEG * a;
        float mn = fmaxf(m, a);
        s = s * __expf(m - mn) + __expf(a - mn);
        m = mn;
    }
#pragma unroll
    for (int o = 4; o <= 16; o <<= 1) {
        float m2 = __shfl_xor_sync(0xffffffffu, m, o);
        float s2 = __shfl_xor_sync(0xffffffffu, s, o);
        float mn = fmaxf(m, m2);
        s = s * __expf(m - mn) + s2 * __expf(m2 - mn);
        m = mn;
    }
    float inv = 1.f / s;
#pragma unroll
    for (int h4 = 0; h4 < H; h4++) {
        m4[h4] = __shfl_sync(0xffffffffu, m, h4);
        i4[h4] = __shfl_sync(0xffffffffu, inv, h4);
    }
}

// ---- L1 FUSED: edge (reads A) + GEMM 64x32 + L2 scores (writes B) ---------
constexpr int CAP = 64;

__global__ void __launch_bounds__(256)
k_l1_fused(const float* __restrict__ x, const float* __restrict__ bias,
           float* __restrict__ hbuf) {
    __shared__ float s_w1[64][32];            // wst1 tile (8 KB)
    __shared__ float s_b[32];
    __shared__ int   s_pk[8][CAP];
    __shared__ float s_aw[8][CAP][H];
    __shared__ float s_ag[8][64];

    int tid = threadIdx.x;
    int lane = tid & 31, grp = tid >> 5;
    int n = blockIdx.x * 8 + grp;

    for (int i = tid; i < 2048; i += 256) s_w1[i >> 5][i & 31] = g_wst1[i];
    if (tid < 32) s_b[tid] = bias[tid];
    __syncthreads();

    int b0 = g_rowptr[n], b1 = g_rowptr[n + 1];
    int D = b1 - b0;
    float a0 = 0.f, a1 = 0.f, a2 = 0.f, a3 = 0.f;

    if (D <= CAP) {
        for (int j = lane; j < D; j += 32) s_pk[grp][j] = g_se[b0 + j];
        __syncwarp();
        warp_softmax(g_ssrcA, g_sdstA, n, 0, D, s_pk[grp], s_aw[grp], lane);
        __syncwarp();
        if (lane < 16) {
            for (int jj = 0; jj < D; jj++) {
                int src = s_pk[grp][jj] & 0xFFFFF;
                float v = x[(size_t)src * 16 + lane];
                a0 += s_aw[grp][jj][0] * v;
                a1 += s_aw[grp][jj][1] * v;
                a2 += s_aw[grp][jj][2] * v;
                a3 += s_aw[grp][jj][3] * v;
            }
        }
    } else {
        float m4[H], i4[H];
        warp_softmax_stats(g_ssrcA, g_sdstA, n, 0, D, b0, m4, i4, lane);
        if (lane < 16) {
            float sd4[H];
#pragma unroll
            for (int h4 = 0; h4 < H; h4++) sd4[h4] = g_sdstA[n * H + h4];
            for (int jj = 0; jj < D; jj++) {
                int p = g_se[b0 + jj];
                int src = p & 0xFFFFF, et = p >> 20;
                float v = x[(size_t)src * 16 + lane];
#pragma unroll
                for (int h4 = 0; h4 < H; h4++) {
                    float a = g_ssrcA[src * H + h4] + sd4[h4] + g_etab[0][et * H + h4];
                    a = (a > 0.f) ? a : NEG * a;
                    float w = __expf(a - m4[h4]) * i4[h4];
                    if (h4 == 0) a0 += w * v;
                    else if (h4 == 1) a1 += w * v;
                    else if (h4 == 2) a2 += w * v;
                    else a3 += w * v;
                }
            }
        }
    }

    if (lane < 16) {
        s_ag[grp][lane]      = a0;
        s_ag[grp][16 + lane] = a1;
        s_ag[grp][32 + lane] = a2;
        s_ag[grp][48 + lane] = a3;
    }
    __syncwarp();

    float acc = 0.f;
#pragma unroll 16
    for (int hk = 0; hk < 64; hk++) acc += s_ag[grp][hk] * s_w1[hk][lane];
    acc += s_b[lane];
    acc = fmaxf(acc, 0.f);
    hbuf[(size_t)n * 32 + lane] = acc;

    // fused L2 scores -> buffer B (no aliasing with A reads above)
    float rs[H], rd[H];
#pragma unroll
    for (int h = 0; h < H; h++) {
        rs[h] = acc * g_usrc[1][h * 32 + lane];
        rd[h] = acc * g_udst[1][h * 32 + lane];
#pragma unroll
        for (int o = 16; o > 0; o >>= 1) {
            rs[h] += __shfl_xor_sync(0xffffffffu, rs[h], o);
            rd[h] += __shfl_xor_sync(0xffffffffu, rd[h], o);
        }
    }
    if (lane == 0) {
#pragma unroll
        for (int h = 0; h < H; h++) {
            g_ssrcB[n * H + h] = rs[h];
            g_sdstB[n * H + h] = rd[h];
        }
    }
}

// ------- L2 edge kernel: K=32, 8 nodes/block, reads B, half out ------------
__global__ void __launch_bounds__(256)
k_gat_edge2(const float* __restrict__ h, __half* __restrict__ ah) {
    __shared__ int   s_pk[8][CAP];
    __shared__ float s_aw[8][CAP][H];

    int lane = threadIdx.x & 31;
    int grp  = threadIdx.x >> 5;
    int n    = blockIdx.x * 8 + grp;
    int b0 = g_rowptr[n], b1 = g_rowptr[n + 1];
    int D = b1 - b0;

    float a0 = 0.f, a1 = 0.f, a2 = 0.f, a3 = 0.f;

    if (D <= CAP) {
        for (int j = lane; j < D; j += 32) s_pk[grp][j] = g_se[b0 + j];
        __syncwarp();
        warp_softmax(g_ssrcB, g_sdstB, n, 1, D, s_pk[grp], s_aw[grp], lane);
        __syncwarp();
        int jj = 0;
        for (; jj + 4 <= D; jj += 4) {
            int s0 = s_pk[grp][jj]     & 0xFFFFF;
            int s1 = s_pk[grp][jj + 1] & 0xFFFFF;
            int s2 = s_pk[grp][jj + 2] & 0xFFFFF;
            int s3 = s_pk[grp][jj + 3] & 0xFFFFF;
            float v0 = h[(size_t)s0 * 32 + lane];
            float v1 = h[(size_t)s1 * 32 + lane];
            float v2 = h[(size_t)s2 * 32 + lane];
            float v3 = h[(size_t)s3 * 32 + lane];
            a0 += s_aw[grp][jj][0] * v0 + s_aw[grp][jj + 1][0] * v1
                + s_aw[grp][jj + 2][0] * v2 + s_aw[grp][jj + 3][0] * v3;
            a1 += s_aw[grp][jj][1] * v0 + s_aw[grp][jj + 1][1] * v1
                + s_aw[grp][jj + 2][1] * v2 + s_aw[grp][jj + 3][1] * v3;
            a2 += s_aw[grp][jj][2] * v0 + s_aw[grp][jj + 1][2] * v1
                + s_aw[grp][jj + 2][2] * v2 + s_aw[grp][jj + 3][2] * v3;
            a3 += s_aw[grp][jj][3] * v0 + s_aw[grp][jj + 1][3] * v1
                + s_aw[grp][jj + 2][3] * v2 + s_aw[grp][jj + 3][3] * v3;
        }
        for (; jj < D; jj++) {
            int src = s_pk[grp][jj] & 0xFFFFF;
            float v = h[(size_t)src * 32 + lane];
            a0 += s_aw[grp][jj][0] * v;
            a1 += s_aw[grp][jj][1] * v;
            a2 += s_aw[grp][jj][2] * v;
            a3 += s_aw[grp][jj][3] * v;
        }
    } else {
        float m4[H], i4[H];
        warp_softmax_stats(g_ssrcB, g_sdstB, n, 1, D, b0, m4, i4, lane);
        float sd4[H];
#pragma unroll
        for (int h4 = 0; h4 < H; h4++) sd4[h4] = g_sdstB[n * H + h4];
        for (int jj = 0; jj < D; jj++) {
            int p = g_se[b0 + jj];
            int src = p & 0xFFFFF, et = p >> 20;
            float v = h[(size_t)src * 32 + lane];
#pragma unroll
            for (int h4 = 0; h4 < H; h4++) {
                float a = g_ssrcB[src * H + h4] + sd4[h4] + g_etab[1][et * H + h4];
                a = (a > 0.f) ? a : NEG * a;
                float w = __expf(a - m4[h4]) * i4[h4];
                if (h4 == 0) a0 += w * v;
                else if (h4 == 1) a1 += w * v;
                else if (h4 == 2) a2 += w * v;
                else a3 += w * v;
            }
        }
    }

    size_t base = (size_t)n * 128 + lane;
    ah[base]      = __float2half(a0);
    ah[base + 32] = __float2half(a1);
    ah[base + 64] = __float2half(a2);
    ah[base + 96] = __float2half(a3);
}

// ------- L3 edge kernel: reads A, 2 nodes/128-thr block, half2 gathers -----
__global__ void k_gat_edge3(const __half2* __restrict__ h2, __half2* __restrict__ agg2) {
    __shared__ int   s_pk[2][CAP];
    __shared__ float s_aw[2][CAP][H];
    __shared__ float s_ms[2][2][H];

    int grp  = threadIdx.x >> 6;
    int gtid = threadIdx.x & 63;
    int lane = threadIdx.x & 31;
    int wing = (threadIdx.x >> 5) & 1;
    int n = blockIdx.x * 2 + grp;
    int b0 = g_rowptr[n], b1 = g_rowptr[n + 1];
    int D = b1 - b0;
    bool fast = (D <= CAP);

    if (fast)
        for (int j = gtid; j < D; j += 64) s_pk[grp][j] = g_se[b0 + j];
    __syncthreads();

    if (wing == 0) {
        if (fast) {
            warp_softmax(g_ssrcA, g_sdstA, n, 2, D, s_pk[grp], s_aw[grp], lane);
        } else {
            float m4[H], i4[H];
            warp_softmax_stats(g_ssrcA, g_sdstA, n, 2, D, b0, m4, i4, lane);
            if (lane < H) {
                s_ms[grp][0][lane] = m4[lane];
                s_ms[grp][1][lane] = i4[lane];
            }
        }
    }
    __syncthreads();

    float ax[H], ay[H];
#pragma unroll
    for (int h4 = 0; h4 < H; h4++) { ax[h4] = 0.f; ay[h4] = 0.f; }

    if (fast) {
        int jj = 0;
        for (; jj + 4 <= D; jj += 4) {
            int s0 = s_pk[grp][jj]     & 0xFFFFF;
            int s1 = s_pk[grp][jj + 1] & 0xFFFFF;
            int s2 = s_pk[grp][jj + 2] & 0xFFFFF;
            int s3 = s_pk[grp][jj + 3] & 0xFFFFF;
            float2 v0 = __half22float2(h2[(size_t)s0 * 64 + gtid]);
            float2 v1 = __half22float2(h2[(size_t)s1 * 64 + gtid]);
            float2 v2 = __half22float2(h2[(size_t)s2 * 64 + gtid]);
            float2 v3 = __half22float2(h2[(size_t)s3 * 64 + gtid]);
#pragma unroll
            for (int h4 = 0; h4 < H; h4++) {
                float w0 = s_aw[grp][jj][h4],     w1 = s_aw[grp][jj + 1][h4];
                float w2 = s_aw[grp][jj + 2][h4], w3 = s_aw[grp][jj + 3][h4];
                ax[h4] += w0 * v0.x + w1 * v1.x + w2 * v2.x + w3 * v3.x;
                ay[h4] += w0 * v0.y + w1 * v1.y + w2 * v2.y + w3 * v3.y;
            }
        }
        for (; jj < D; jj++) {
            int src = s_pk[grp][jj] & 0xFFFFF;
            float2 v = __half22float2(h2[(size_t)src * 64 + gtid]);
#pragma unroll
            for (int h4 = 0; h4 < H; h4++) {
                float w = s_aw[grp][jj][h4];
                ax[h4] += w * v.x;
                ay[h4] += w * v.y;
            }
        }
    } else {
        float m4[H], i4[H], sd4[H];
#pragma unroll
        for (int h4 = 0; h4 < H; h4++) {
            m4[h4] = s_ms[grp][0][h4];
            i4[h4] = s_ms[grp][1][h4];
            sd4[h4] = g_sdstA[n * H + h4];
        }
        for (int jj = 0; jj < D; jj++) {
            int p = g_se[b0 + jj];
            int src = p & 0xFFFFF, et = p >> 20;
            float2 v = __half22float2(h2[(size_t)src * 64 + gtid]);
#pragma unroll
            for (int h4 = 0; h4 < H; h4++) {
                float a = g_ssrcA[src * H + h4] + sd4[h4] + g_etab[2][et * H + h4];
                a = (a > 0.f) ? a : NEG * a;
                float w = __expf(a - m4[h4]) * i4[h4];
                ax[h4] += w * v.x;
                ay[h4] += w * v.y;
            }
        }
    }

    size_t base = (size_t)n * 256 + gtid;
#pragma unroll
    for (int h4 = 0; h4 < H; h4++)
        agg2[base + h4 * 64] = __floats2half2_rn(ax[h4], ay[h4]);
}

// ------- fp16 TC GEMM: 128x128x32 tiles, 3-stage cp.async ring -------------
// L2 call fuses L3 scores -> buffer A (no reader of A runs concurrently).
constexpr int STG_BYTES = 128 * 40 * 2 * 2;    // A+B per stage = 20480 B
constexpr int SMEM_HF   = 3 * STG_BYTES;       // 61440 B

__device__ __forceinline__ uint32_t smem_u32(const void* p) {
    uint32_t a;
    asm("{ .reg .u64 t; cvta.to.shared.u64 t, %1; cvt.u32.u64 %0, t; }" : "=r"(a) : "l"(p));
    return a;
}

__global__ void __launch_bounds__(256, 2)
k_gemm_hf(const __half* __restrict__ A, const __half* __restrict__ Bt,
          const float* __restrict__ bias, float* __restrict__ C,
          __half2* __restrict__ Ch2, const float* __restrict__ Usrc,
          const float* __restrict__ Udst, int K, int NN, int relu) {
    extern __shared__ char hsm[];
    int tid = threadIdx.x;
    int wid = tid >> 5, lane = tid & 31;
    int bm = blockIdx.y * 128, bn = blockIdx.x * 128;
    int wm = (wid >> 2) * 64;
    int wn = (wid & 3) * 32;
    int grp = lane >> 2, tig = lane & 3;

    auto stA = [&](int s) { return reinterpret_cast<__half*>(hsm + s * STG_BYTES); };
    auto stB = [&](int s) { return reinterpret_cast<__half*>(hsm + s * STG_BYTES) + 128 * 40; };

    float c[4][4][4];
#pragma unroll
    for (int mt = 0; mt < 4; mt++)
#pragma unroll
        for (int nt = 0; nt < 4; nt++)
#pragma unroll
            for (int q = 0; q < 4; q++) c[mt][nt][q] = 0.f;

    int nk = K >> 5;

    auto copy_tile = [&](int s, int k0) {
        __half* As = stA(s);
        __half* Bs = stB(s);
#pragma unroll
        for (int i = 0; i < 2; i++) {
            int f = tid + i * 256;
            int m = f >> 2, q = f & 3;
            uint32_t dst = smem_u32(&As[m * 40 + q * 8]);
            const __half* src = &A[(size_t)(bm + m) * K + k0 + q * 8];
            asm volatile("cp.async.ca.shared.global [%0], [%1], 16;" :: "r"(dst), "l"(src));
        }
#pragma unroll
        for (int i = 0; i < 2; i++) {
            int f = tid + i * 256;
            int nrow = f >> 2, q = f & 3;
            uint32_t dst = smem_u32(&Bs[nrow * 40 + q * 8]);
            const __half* src = &Bt[(size_t)(bn + nrow) * K + k0 + q * 8];
            asm volatile("cp.async.ca.shared.global [%0], [%1], 16;" :: "r"(dst), "l"(src));
        }
        asm volatile("cp.async.commit_group;");
    };

    copy_tile(0, 0);
    copy_tile(1, 32);

    int mtx = lane >> 3;
    int rin = lane & 7;

    for (int it = 0; it < nk; it++) {
        int cur = it % 3;
        if (it + 1 < nk) asm volatile("cp.async.wait_group 1;");
        else             asm volatile("cp.async.wait_group 0;");
        __syncthreads();
        if (it + 2 < nk) copy_tile((it + 2) % 3, (it + 2) * 32);

        __half* As = stA(cur);
        __half* Bs = stB(cur);
#pragma unroll
        for (int ks = 0; ks < 2; ks++) {
            uint32_t a[4][4], b[4][2];
#pragma unroll
            for (int mt = 0; mt < 4; mt++) {
                int row = wm + mt * 16 + (mtx & 1) * 8 + rin;
                int col = ks * 16 + (mtx >> 1) * 8;
                uint32_t addr = smem_u32(&As[row * 40 + col]);
                asm volatile("ldmatrix.sync.aligned.m8n8.x4.shared.b16 {%0,%1,%2,%3}, [%4];"
                             : "=r"(a[mt][0]), "=r"(a[mt][1]), "=r"(a[mt][2]), "=r"(a[mt][3])
                             : "r"(addr));
            }
#pragma unroll
            for (int np = 0; np < 2; np++) {
                int row = wn + np * 16 + (mtx >> 1) * 8 + rin;
                int col = ks * 16 + (mtx & 1) * 8;
                uint32_t addr = smem_u32(&Bs[row * 40 + col]);
                asm volatile("ldmatrix.sync.aligned.m8n8.x4.shared.b16 {%0,%1,%2,%3}, [%4];"
                             : "=r"(b[np * 2][0]), "=r"(b[np * 2][1]),
                               "=r"(b[np * 2 + 1][0]), "=r"(b[np * 2 + 1][1])
                             : "r"(addr));
            }
#pragma unroll
            for (int mt = 0; mt < 4; mt++)
#pragma unroll
                for (int nt = 0; nt < 4; nt++) {
                    asm volatile(
                        "mma.sync.aligned.m16n8k16.row.col.f32.f16.f16.f32 "
                        "{%0,%1,%2,%3}, {%4,%5,%6,%7}, {%8,%9}, {%0,%1,%2,%3};"
                        : "+f"(c[mt][nt][0]), "+f"(c[mt][nt][1]),
                          "+f"(c[mt][nt][2]), "+f"(c[mt][nt][3])
                        : "r"(a[mt][0]), "r"(a[mt][1]), "r"(a[mt][2]), "r"(a[mt][3]),
                          "r"(b[nt][0]), "r"(b[nt][1]));
                }
        }
        __syncthreads();
    }

    float bv[4][2];
#pragma unroll
    for (int nt = 0; nt < 4; nt++) {
        int col = bn + wn + nt * 8 + tig * 2;
        bv[nt][0] = bias[col];
        bv[nt][1] = bias[col + 1];
    }

#pragma unroll
    for (int mt = 0; mt < 4; mt++) {
#pragma unroll
        for (int nt = 0; nt < 4; nt++) {
            int col = bn + wn + nt * 8 + tig * 2;
            int r0 = bm + wm + mt * 16 + grp;
            float v00 = c[mt][nt][0] + bv[nt][0], v01 = c[mt][nt][1] + bv[nt][1];
            float v10 = c[mt][nt][2] + bv[nt][0], v11 = c[mt][nt][3] + bv[nt][1];
            if (relu) {
                v00 = fmaxf(v00, 0.f); v01 = fmaxf(v01, 0.f);
                v10 = fmaxf(v10, 0.f); v11 = fmaxf(v11, 0.f);
            }
            C[(size_t)r0 * NN + col]           = v00;
            C[(size_t)r0 * NN + col + 1]       = v01;
            C[(size_t)(r0 + 8) * NN + col]     = v10;
            C[(size_t)(r0 + 8) * NN + col + 1] = v11;
            if (Ch2) {
                Ch2[((size_t)r0 * NN + col) >> 1]       = __floats2half2_rn(v00, v01);
                Ch2[((size_t)(r0 + 8) * NN + col) >> 1] = __floats2half2_rn(v10, v11);
            }
        }
    }

    if (Usrc) {
        float* s_sc = reinterpret_cast<float*>(hsm);
        for (int i = tid; i < 128 * 8; i += 256) s_sc[i] = 0.f;
        __syncthreads();
#pragma unroll
        for (int h8 = 0; h8 < 8; h8++) {
            const float* U = (h8 < 4) ? (Usrc + h8 * NN) : (Udst + (h8 - 4) * NN);
            float u[4][2];
#pragma unroll
            for (int nt = 0; nt < 4; nt++) {
                int col = wn + nt * 8 + tig * 2;
                u[nt][0] = U[col];
                u[nt][1] = U[col + 1];
            }
#pragma unroll
            for (int mt = 0; mt < 4; mt++) {
                int r0 = wm + mt * 16 + grp;
                float p0 = 0.f, p1 = 0.f;
#pragma unroll
                for (int nt = 0; nt < 4; nt++) {
                    float v00 = c[mt][nt][0] + bv[nt][0], v01 = c[mt][nt][1] + bv[nt][1];
                    float v10 = c[mt][nt][2] + bv[nt][0], v11 = c[mt][nt][3] + bv[nt][1];
                    v00 = fmaxf(v00, 0.f); v01 = fmaxf(v01, 0.f);
                    v10 = fmaxf(v10, 0.f); v11 = fmaxf(v11, 0.f);
                    p0 += v00 * u[nt][0] + v01 * u[nt][1];
                    p1 += v10 * u[nt][0] + v11 * u[nt][1];
                }
                p0 += __shfl_xor_sync(0xffffffffu, p0, 1);
                p0 += __shfl_xor_sync(0xffffffffu, p0, 2);
                p1 += __shfl_xor_sync(0xffffffffu, p1, 1);
                p1 += __shfl_xor_sync(0xffffffffu, p1, 2);
                if (tig == 0) {
                    atomicAdd(&s_sc[r0 * 8 + h8], p0);
                    atomicAdd(&s_sc[(r0 + 8) * 8 + h8], p1);
                }
            }
        }
        __syncthreads();
        for (int i = tid; i < 128 * 8; i += 256) {
            int r = i >> 3, h8 = i & 7;
            float v = s_sc[i];
            if (h8 < 4) g_ssrcA[(bm + r) * H + h8] = v;
            else        g_sdstA[(bm + r) * H + (h8 - 4)] = v;
        }
    }
}

// ---------------------------------------------------------------------------
extern "C" void kernel_launch(void* const* d_in, const int* in_sizes, int n_in,
                              void* d_out, int out_size) {
    const float* x   = (const float*)d_in[0];
    const int*   eit = (const int*)d_in[1];
    const float* W1  = (const float*)d_in[2];
    const float* We1 = (const float*)d_in[3];
    const float* as1 = (const float*)d_in[4];
    const float* ad1 = (const float*)d_in[5];
    const float* ae1 = (const float*)d_in[6];
    const float* b1  = (const float*)d_in[7];
    const float* W2  = (const float*)d_in[8];
    const float* We2 = (const float*)d_in[9];
    const float* as2 = (const float*)d_in[10];
    const float* ad2 = (const float*)d_in[11];
    const float* ae2 = (const float*)d_in[12];
    const float* b2  = (const float*)d_in[13];
    const float* W3  = (const float*)d_in[14];
    const float* We3 = (const float*)d_in[15];
    const float* as3 = (const float*)d_in[16];
    const float* ad3 = (const float*)d_in[17];
    const float* ae3 = (const float*)d_in[18];
    const float* b3  = (const float*)d_in[19];
    float* out = (float*)d_out;

    float *agg = nullptr, *hbuf = nullptr;
    float *usrc = nullptr, *udst = nullptr;
    __half *wst2 = nullptr, *wst3 = nullptr;
    __half2 *hbufh2 = nullptr;
    cudaGetSymbolAddress((void**)&agg, g_agg);
    cudaGetSymbolAddress((void**)&hbuf, g_hbuf);
    cudaGetSymbolAddress((void**)&wst2, g_wst2);
    cudaGetSymbolAddress((void**)&wst3, g_wst3);
    cudaGetSymbolAddress((void**)&hbufh2, g_hbufh2);
    cudaGetSymbolAddress((void**)&usrc, g_usrc);
    cudaGetSymbolAddress((void**)&udst, g_udst);
    const __half* aggh = (const __half*)agg;
    __half* aggw = (__half*)agg;
    __half2* agg2 = (__half2*)agg;

    cudaFuncSetAttribute(k_gemm_hf, cudaFuncAttributeMaxDynamicSharedMemorySize, SMEM_HF);

    // ---- setup (build+prep), scan, scatter+L1 scores (A) ----
    k_setup<<<1011, 256>>>(eit,
                           W1, as1, ad1, We1, ae1,
                           W2, as2, ad2, We2, ae2,
                           W3, as3, ad3, We3, ae3);
    k_scan<<<1, 1024>>>();
    k_scat_scores<<<640 + 2048, 256>>>(x);

    // ---- layer 1 FUSED: edge(A) + GEMM + L2 scores(B) ----
    k_l1_fused<<<N / 8, 256>>>(x, b1, hbuf);

    // ---- layer 2: edge(B) + TC GEMM (fuses L3 scores->A, half2 out) ----
    k_gat_edge2<<<N / 8, 256>>>(hbuf, aggw);
    k_gemm_hf<<<dim3(1, N / 128), 256, SMEM_HF>>>(aggh, wst2, b2, hbuf, hbufh2,
                                                  usrc + 2 * 512, udst + 2 * 512, 128, 128, 1);

    // ---- layer 3: edge(A) + TC GEMM -> out ----
    k_gat_edge3<<<N / 2, 128>>>(hbufh2, agg2);
    k_gemm_hf<<<dim3(4, N / 128), 256, SMEM_HF>>>(aggh, wst3, b3, out, nullptr,
                                                  nullptr, nullptr, 512, 512, 0);
}

// round 16
// speedup vs baseline: 1.4324x; 1.0112x over previous
#include <cuda_runtime.h>
#include <cuda_fp16.h>
#include <cstdint>

constexpr int N    = 32768;
constexpr int EPER = 16384;
constexpr int T    = 8;
constexpr int E0   = T * EPER;   // 131072 typed edges
constexpr int E    = E0 + N;     // + self loops = 163840
constexpr int H    = 4;
constexpr float NEG = 0.2f;

// ---------------------------- scratch (device globals) ---------------------
__device__ float   g_agg[(size_t)N * 512];   // L2/L3 half agg (aliased)
__device__ float   g_hbuf[(size_t)N * 128];  // inter-layer activations (fp32)
__device__ __half2 g_hbufh2[(size_t)N * 64]; // half mirror of hbuf for L3 gathers
// score double buffers: A = L1 & L3 scores, B = L2 scores
__device__ float   g_ssrcA[N * H], g_sdstA[N * H];
__device__ float   g_ssrcB[N * H], g_sdstB[N * H];
__device__ float   g_etab[3][(T + 1) * H];
__device__ float   g_usrc[3][512];
__device__ float   g_udst[3][512];
__device__ float   g_wst1[64 * 32];          // L1 fp32 [H*K, dout]
__device__ __half  g_wst2[128 * 128];        // L2 half [dout, H*K] K-major
__device__ __half  g_wst3[512 * 512];        // L3 half [dout, H*K] K-major
__device__ int     g_se[E];                  // dst-sorted packed edges: src | (et<<20)
__device__ int     g_src[E], g_dst[E], g_et[E];
__device__ int     g_deg[N], g_rowptr[N + 1], g_fill[N];

// ---------- ONE setup kernel: graph build + all weight prep (overlapped) ---
__global__ void k_setup(const int* __restrict__ eit,
    const float* __restrict__ W1, const float* __restrict__ as1,
    const float* __restrict__ ad1, const float* __restrict__ We1,
    const float* __restrict__ ae1,
    const float* __restrict__ W2, const float* __restrict__ as2,
    const float* __restrict__ ad2, const float* __restrict__ We2,
    const float* __restrict__ ae2,
    const float* __restrict__ W3, const float* __restrict__ as3,
    const float* __restrict__ ad3, const float* __restrict__ We3,
    const float* __restrict__ ae3) {
    __shared__ float sm[32][33];
    int b = blockIdx.x, tid = threadIdx.x;

    if (b < 640) {
        int e = b * 256 + tid;
        if (e >= E) return;
        int s, d, t;
        if (e < E0) {
            t = e / EPER;
            int i = e - t * EPER;
            s = eit[t * 2 * EPER + i];
            d = eit[t * 2 * EPER + EPER + i];
        } else {
            s = d = e - E0;
            t = T;
        }
        g_src[e] = s; g_dst[e] = d; g_et[e] = t;
        atomicAdd(&g_deg[d], 1);
    } else if (b < 648) {
        int idx = (b - 640) * 256 + tid;         // 2048 = 64*32
        int d = idx % 32, hk = idx / 32;
        int h = hk / 16, k = hk % 16;
        g_wst1[idx] = W1[(size_t)k * 128 + h * 32 + d] * 0.25f;
    } else if (b < 664) {
        int rel = b - 648;
        int h = rel >> 2, dt = rel & 3;
        int ty = tid >> 5, tx = tid & 31;
#pragma unroll
        for (int p = 0; p < 4; p++) {
            int k = p * 8 + ty;
            sm[k][tx] = W2[(size_t)k * 512 + h * 128 + dt * 32 + tx];
        }
        __syncthreads();
#pragma unroll
        for (int p = 0; p < 4; p++) {
            int d = p * 8 + ty;
            g_wst2[(size_t)(dt * 32 + d) * 128 + h * 32 + tx] =
                __float2half(sm[tx][d] * 0.25f);
        }
    } else if (b < 920) {
        int rel = b - 664;                       // 256 = 4h * 4kt * 16dt
        int h = rel >> 6, rem = rel & 63;
        int kt = rem >> 4, dt = rem & 15;
        int ty = tid >> 5, tx = tid & 31;
#pragma unroll
        for (int p = 0; p < 4; p++) {
            int k = p * 8 + ty;
            sm[k][tx] = W3[(size_t)(kt * 32 + k) * 2048 + h * 512 + dt * 32 + tx];
        }
        __syncthreads();
#pragma unroll
        for (int p = 0; p < 4; p++) {
            int d = p * 8 + ty;
            g_wst3[(size_t)(dt * 32 + d) * 512 + h * 128 + kt * 32 + tx] =
                __float2half(sm[tx][d] * 0.25f);
        }
    } else if (b < 1008) {
        int gw = (b - 920) * 8 + (tid >> 5);
        int lane = tid & 31;
        int L, e;
        if (gw < 64)       { L = 0; e = gw; }
        else if (gw < 192) { L = 1; e = gw - 64; }
        else               { L = 2; e = gw - 192; }
        if (L == 2 && e >= 512) return;
        int K    = (L == 0) ? 16 : (L == 1) ? 32 : 128;
        int dout = (L == 0) ? 32 : (L == 1) ? 128 : 512;
        const float* W  = (L == 0) ? W1  : (L == 1) ? W2  : W3;
        const float* as = (L == 0) ? as1 : (L == 1) ? as2 : as3;
        const float* ad = (L == 0) ? ad1 : (L == 1) ? ad2 : ad3;
        int h = e / K, k = e % K;
        const float* wr = W + (size_t)k * (H * dout) + h * dout;
        float vs = 0.f, vd = 0.f;
        for (int d = lane; d < dout; d += 32) {
            float w = wr[d];
            vs += w * as[h * dout + d];
            vd += w * ad[h * dout + d];
        }
#pragma unroll
        for (int o = 16; o > 0; o >>= 1) {
            vs += __shfl_xor_sync(0xffffffffu, vs, o);
            vd += __shfl_xor_sync(0xffffffffu, vd, o);
        }
        if (lane == 0) {
            g_usrc[L][e] = vs;
            g_udst[L][e] = vd;
        }
    } else {
        int L = b - 1008;
        int dout = (L == 0) ? 32 : (L == 1) ? 128 : 512;
        const float* We = (L == 0) ? We1 : (L == 1) ? We2 : We3;
        const float* ae = (L == 0) ? ae1 : (L == 1) ? ae2 : ae3;
        int HC = H * dout;
        int wrp = tid >> 5, lane = tid & 31;
#pragma unroll
        for (int i = 0; i < 4; i++) {
            int e = wrp * 4 + i;
            int t = e >> 2, h = e & 3;
            float s = 0.f;
            for (int c = lane; c < dout; c += 32)
                s += We[t * HC + h * dout + c] * ae[h * dout + c];
#pragma unroll
            for (int o = 16; o > 0; o >>= 1)
                s += __shfl_xor_sync(0xffffffffu, s, o);
            if (lane == 0) {
                sm[t][h] = s;
                g_etab[L][t * H + h] = s;
            }
        }
        __syncthreads();
        if (tid < H) {
            float s = 0.f;
            for (int t = 0; t < T; t++) s += sm[t][tid];
            g_etab[L][T * H + tid] = s * (1.0f / T);
        }
    }
}

// scan also RE-ZEROES g_deg (call-invariant).
__global__ void k_scan() {
    __shared__ int sh[1024];
    int t = threadIdx.x;
    int base = t * 32;
    int loc[32];
    int sum = 0;
#pragma unroll
    for (int i = 0; i < 32; i++) { loc[i] = sum; sum += g_deg[base + i]; g_deg[base + i] = 0; }
    sh[t] = sum;
    __syncthreads();
    for (int off = 1; off < 1024; off <<= 1) {
        int v = (t >= off) ? sh[t - off] : 0;
        __syncthreads();
        if (t >= off) sh[t] += v;
        __syncthreads();
    }
    int prev = (t == 0) ? 0 : sh[t - 1];
#pragma unroll
    for (int i = 0; i < 32; i++) {
        int v = prev + loc[i];
        g_rowptr[base + i] = v;
        g_fill[base + i]   = v;
    }
    if (t == 1023) g_rowptr[N] = sh[1023];
}

// ---- fused scatter + L1 scores (writes buffer A) ---------------------------
__global__ void k_scat_scores(const float* __restrict__ x) {
    int b = blockIdx.x, tid = threadIdx.x;
    if (b < 640) {
        int e = b * 256 + tid;
        if (e >= E) return;
        int pos = atomicAdd(&g_fill[g_dst[e]], 1);
        g_se[pos] = g_src[e] | (g_et[e] << 20);
    } else {
        int gw = (b - 640) * 8 + (tid >> 5);
        int lane = tid & 31, sl = lane & 15;
        int n = gw * 2 + (lane >> 4);
        float xv = x[n * 16 + sl];
        float p[8];
#pragma unroll
        for (int h = 0; h < H; h++) {
            p[h]     = xv * g_usrc[0][h * 16 + sl];
            p[h + 4] = xv * g_udst[0][h * 16 + sl];
        }
#pragma unroll
        for (int o = 8; o > 0; o >>= 1)
#pragma unroll
            for (int i = 0; i < 8; i++)
                p[i] += __shfl_xor_sync(0xffffffffu, p[i], o);
        if (sl < 8) {
            float v = p[sl];
            if (sl < 4) g_ssrcA[n * H + sl] = v;
            else        g_sdstA[n * H + (sl - 4)] = v;
        }
    }
}

// ---- shared edge-softmax helpers ------------------------------------------
__device__ __forceinline__ void warp_softmax(const float* __restrict__ ssrc,
                                             const float* __restrict__ sdst,
                                             int n, int L, int D,
                                             const int* s_pk, float (*s_aw)[H],
                                             int lane) {
    int hh = lane & 3;
    int j0 = lane >> 2;
    float sd = sdst[n * H + hh];
    float m = -1e30f, s = 0.f;
    for (int jj = j0; jj < D; jj += 8) {
        int p = s_pk[jj];
        int src = p & 0xFFFFF, et = p >> 20;
        float a = ssrc[src * H + hh] + sd + g_etab[L][et * H + hh];
        a = (a > 0.f) ? a : NEG * a;
        s_aw[jj][hh] = a;
        float mn = fmaxf(m, a);
        s = s * __expf(m - mn) + __expf(a - mn);
        m = mn;
    }
#pragma unroll
    for (int o = 4; o <= 16; o <<= 1) {
        float m2 = __shfl_xor_sync(0xffffffffu, m, o);
        float s2 = __shfl_xor_sync(0xffffffffu, s, o);
        float mn = fmaxf(m, m2);
        s = s * __expf(m - mn) + s2 * __expf(m2 - mn);
        m = mn;
    }
    float inv = 1.f / s;
    for (int jj = j0; jj < D; jj += 8)
        s_aw[jj][hh] = __expf(s_aw[jj][hh] - m) * inv;
}

__device__ __forceinline__ void warp_softmax_stats(const float* __restrict__ ssrc,
                                                   const float* __restrict__ sdst,
                                                   int n, int L, int D, int b0,
                                                   float* m4, float* i4, int lane) {
    int hh = lane & 3;
    int j0 = lane >> 2;
    float sd = sdst[n * H + hh];
    float m = -1e30f, s = 0.f;
    for (int jj = j0; jj < D; jj += 8) {
        int p = g_se[b0 + jj];
        int src = p & 0xFFFFF, et = p >> 20;
        float a = ssrc[src * H + hh] + sd + g_etab[L][et * H + hh];
        a = (a > 0.f) ? a : NEG * a;
        float mn = fmaxf(m, a);
        s = s * __expf(m - mn) + __expf(a - mn);
        m = mn;
    }
#pragma unroll
    for (int o = 4; o <= 16; o <<= 1) {
        float m2 = __shfl_xor_sync(0xffffffffu, m, o);
        float s2 = __shfl_xor_sync(0xffffffffu, s, o);
        float mn = fmaxf(m, m2);
        s = s * __expf(m - mn) + s2 * __expf(m2 - mn);
        m = mn;
    }
    float inv = 1.f / s;
#pragma unroll
    for (int h4 = 0; h4 < H; h4++) {
        m4[h4] = __shfl_sync(0xffffffffu, m, h4);
        i4[h4] = __shfl_sync(0xffffffffu, inv, h4);
    }
}

// ---- L1 FUSED: edge (reads A) + GEMM 64x32 (float4 LDS) + L2 scores (B) ---
constexpr int CAP = 64;

__global__ void __launch_bounds__(256)
k_l1_fused(const float* __restrict__ x, const float* __restrict__ bias,
           float* __restrict__ hbuf) {
    __shared__ float s_w1t[32][68];           // transposed: [d][hk], float4-friendly
    __shared__ float s_b[32];
    __shared__ int   s_pk[8][CAP];
    __shared__ float s_aw[8][CAP][H];
    __shared__ float s_ag[8][64];

    int tid = threadIdx.x;
    int lane = tid & 31, grp = tid >> 5;
    int n = blockIdx.x * 8 + grp;

    for (int i = tid; i < 2048; i += 256) s_w1t[i & 31][i >> 5] = g_wst1[i];
    if (tid < 32) s_b[tid] = bias[tid];
    __syncthreads();

    int b0 = g_rowptr[n], b1 = g_rowptr[n + 1];
    int D = b1 - b0;
    float a0 = 0.f, a1 = 0.f, a2 = 0.f, a3 = 0.f;

    if (D <= CAP) {
        for (int j = lane; j < D; j += 32) s_pk[grp][j] = g_se[b0 + j];
        __syncwarp();
        warp_softmax(g_ssrcA, g_sdstA, n, 0, D, s_pk[grp], s_aw[grp], lane);
        __syncwarp();
        if (lane < 16) {
            for (int jj = 0; jj < D; jj++) {
                int src = s_pk[grp][jj] & 0xFFFFF;
                float v = x[(size_t)src * 16 + lane];
                a0 += s_aw[grp][jj][0] * v;
                a1 += s_aw[grp][jj][1] * v;
                a2 += s_aw[grp][jj][2] * v;
                a3 += s_aw[grp][jj][3] * v;
            }
        }
    } else {
        float m4[H], i4[H];
        warp_softmax_stats(g_ssrcA, g_sdstA, n, 0, D, b0, m4, i4, lane);
        if (lane < 16) {
            float sd4[H];
#pragma unroll
            for (int h4 = 0; h4 < H; h4++) sd4[h4] = g_sdstA[n * H + h4];
            for (int jj = 0; jj < D; jj++) {
                int p = g_se[b0 + jj];
                int src = p & 0xFFFFF, et = p >> 20;
                float v = x[(size_t)src * 16 + lane];
#pragma unroll
                for (int h4 = 0; h4 < H; h4++) {
                    float a = g_ssrcA[src * H + h4] + sd4[h4] + g_etab[0][et * H + h4];
                    a = (a > 0.f) ? a : NEG * a;
                    float w = __expf(a - m4[h4]) * i4[h4];
                    if (h4 == 0) a0 += w * v;
                    else if (h4 == 1) a1 += w * v;
                    else if (h4 == 2) a2 += w * v;
                    else a3 += w * v;
                }
            }
        }
    }

    if (lane < 16) {
        s_ag[grp][lane]      = a0;
        s_ag[grp][16 + lane] = a1;
        s_ag[grp][32 + lane] = a2;
        s_ag[grp][48 + lane] = a3;
    }
    __syncwarp();

    // GEMM row: out[lane] = sum_hk s_ag[hk] * wst1[hk][lane] (hk ascending,
    // identical order via float4 pairs)
    float acc = 0.f;
#pragma unroll
    for (int q = 0; q < 16; q++) {
        float4 av = *reinterpret_cast<const float4*>(&s_ag[grp][q * 4]);
        float4 wv = *reinterpret_cast<const float4*>(&s_w1t[lane][q * 4]);
        acc += av.x * wv.x;
        acc += av.y * wv.y;
        acc += av.z * wv.z;
        acc += av.w * wv.w;
    }
    acc += s_b[lane];
    acc = fmaxf(acc, 0.f);
    hbuf[(size_t)n * 32 + lane] = acc;

    // fused L2 scores -> buffer B
    float rs[H], rd[H];
#pragma unroll
    for (int h = 0; h < H; h++) {
        rs[h] = acc * g_usrc[1][h * 32 + lane];
        rd[h] = acc * g_udst[1][h * 32 + lane];
#pragma unroll
        for (int o = 16; o > 0; o >>= 1) {
            rs[h] += __shfl_xor_sync(0xffffffffu, rs[h], o);
            rd[h] += __shfl_xor_sync(0xffffffffu, rd[h], o);
        }
    }
    if (lane == 0) {
#pragma unroll
        for (int h = 0; h < H; h++) {
            g_ssrcB[n * H + h] = rs[h];
            g_sdstB[n * H + h] = rd[h];
        }
    }
}

// ------- L2 edge kernel: K=32, 8 nodes/block, reads B, half out ------------
__global__ void __launch_bounds__(256)
k_gat_edge2(const float* __restrict__ h, __half* __restrict__ ah) {
    __shared__ int   s_pk[8][CAP];
    __shared__ float s_aw[8][CAP][H];

    int lane = threadIdx.x & 31;
    int grp  = threadIdx.x >> 5;
    int n    = blockIdx.x * 8 + grp;
    int b0 = g_rowptr[n], b1 = g_rowptr[n + 1];
    int D = b1 - b0;

    float a0 = 0.f, a1 = 0.f, a2 = 0.f, a3 = 0.f;

    if (D <= CAP) {
        for (int j = lane; j < D; j += 32) s_pk[grp][j] = g_se[b0 + j];
        __syncwarp();
        warp_softmax(g_ssrcB, g_sdstB, n, 1, D, s_pk[grp], s_aw[grp], lane);
        __syncwarp();
        int jj = 0;
        for (; jj + 4 <= D; jj += 4) {
            int s0 = s_pk[grp][jj]     & 0xFFFFF;
            int s1 = s_pk[grp][jj + 1] & 0xFFFFF;
            int s2 = s_pk[grp][jj + 2] & 0xFFFFF;
            int s3 = s_pk[grp][jj + 3] & 0xFFFFF;
            float v0 = h[(size_t)s0 * 32 + lane];
            float v1 = h[(size_t)s1 * 32 + lane];
            float v2 = h[(size_t)s2 * 32 + lane];
            float v3 = h[(size_t)s3 * 32 + lane];
            a0 += s_aw[grp][jj][0] * v0 + s_aw[grp][jj + 1][0] * v1
                + s_aw[grp][jj + 2][0] * v2 + s_aw[grp][jj + 3][0] * v3;
            a1 += s_aw[grp][jj][1] * v0 + s_aw[grp][jj + 1][1] * v1
                + s_aw[grp][jj + 2][1] * v2 + s_aw[grp][jj + 3][1] * v3;
            a2 += s_aw[grp][jj][2] * v0 + s_aw[grp][jj + 1][2] * v1
                + s_aw[grp][jj + 2][2] * v2 + s_aw[grp][jj + 3][2] * v3;
            a3 += s_aw[grp][jj][3] * v0 + s_aw[grp][jj + 1][3] * v1
                + s_aw[grp][jj + 2][3] * v2 + s_aw[grp][jj + 3][3] * v3;
        }
        for (; jj < D; jj++) {
            int src = s_pk[grp][jj] & 0xFFFFF;
            float v = h[(size_t)src * 32 + lane];
            a0 += s_aw[grp][jj][0] * v;
            a1 += s_aw[grp][jj][1] * v;
            a2 += s_aw[grp][jj][2] * v;
            a3 += s_aw[grp][jj][3] * v;
        }
    } else {
        float m4[H], i4[H];
        warp_softmax_stats(g_ssrcB, g_sdstB, n, 1, D, b0, m4, i4, lane);
        float sd4[H];
#pragma unroll
        for (int h4 = 0; h4 < H; h4++) sd4[h4] = g_sdstB[n * H + h4];
        for (int jj = 0; jj < D; jj++) {
            int p = g_se[b0 + jj];
            int src = p & 0xFFFFF, et = p >> 20;
            float v = h[(size_t)src * 32 + lane];
#pragma unroll
            for (int h4 = 0; h4 < H; h4++) {
                float a = g_ssrcB[src * H + h4] + sd4[h4] + g_etab[1][et * H + h4];
                a = (a > 0.f) ? a : NEG * a;
                float w = __expf(a - m4[h4]) * i4[h4];
                if (h4 == 0) a0 += w * v;
                else if (h4 == 1) a1 += w * v;
                else if (h4 == 2) a2 += w * v;
                else a3 += w * v;
            }
        }
    }

    size_t base = (size_t)n * 128 + lane;
    ah[base]      = __float2half(a0);
    ah[base + 32] = __float2half(a1);
    ah[base + 64] = __float2half(a2);
    ah[base + 96] = __float2half(a3);
}

// ------- L3 edge kernel: warp per node, 8 nodes/256-block, half2 gathers ---
// Each lane owns columns (lane, lane+32); reads buffer A scores.
__global__ void __launch_bounds__(256)
k_gat_edge3(const __half2* __restrict__ h2, __half2* __restrict__ agg2) {
    __shared__ int   s_pk[8][CAP];
    __shared__ float s_aw[8][CAP][H];

    int lane = threadIdx.x & 31;
    int grp  = threadIdx.x >> 5;
    int n    = blockIdx.x * 8 + grp;
    int b0 = g_rowptr[n], b1 = g_rowptr[n + 1];
    int D = b1 - b0;

    float ax[H], ay[H], bx[H], by[H];
#pragma unroll
    for (int h4 = 0; h4 < H; h4++) { ax[h4] = 0.f; ay[h4] = 0.f; bx[h4] = 0.f; by[h4] = 0.f; }

    if (D <= CAP) {
        for (int j = lane; j < D; j += 32) s_pk[grp][j] = g_se[b0 + j];
        __syncwarp();
        warp_softmax(g_ssrcA, g_sdstA, n, 2, D, s_pk[grp], s_aw[grp], lane);
        __syncwarp();
        int jj = 0;
        for (; jj + 2 <= D; jj += 2) {
            int s0 = s_pk[grp][jj]     & 0xFFFFF;
            int s1 = s_pk[grp][jj + 1] & 0xFFFFF;
            float2 v0 = __half22float2(h2[(size_t)s0 * 64 + lane]);
            float2 u0 = __half22float2(h2[(size_t)s0 * 64 + 32 + lane]);
            float2 v1 = __half22float2(h2[(size_t)s1 * 64 + lane]);
            float2 u1 = __half22float2(h2[(size_t)s1 * 64 + 32 + lane]);
#pragma unroll
            for (int h4 = 0; h4 < H; h4++) {
                float w0 = s_aw[grp][jj][h4], w1 = s_aw[grp][jj + 1][h4];
                ax[h4] += w0 * v0.x + w1 * v1.x;
                ay[h4] += w0 * v0.y + w1 * v1.y;
                bx[h4] += w0 * u0.x + w1 * u1.x;
                by[h4] += w0 * u0.y + w1 * u1.y;
            }
        }
        for (; jj < D; jj++) {
            int src = s_pk[grp][jj] & 0xFFFFF;
            float2 v = __half22float2(h2[(size_t)src * 64 + lane]);
            float2 u = __half22float2(h2[(size_t)src * 64 + 32 + lane]);
#pragma unroll
            for (int h4 = 0; h4 < H; h4++) {
                float w = s_aw[grp][jj][h4];
                ax[h4] += w * v.x;
                ay[h4] += w * v.y;
                bx[h4] += w * u.x;
                by[h4] += w * u.y;
            }
        }
    } else {
        float m4[H], i4[H];
        warp_softmax_stats(g_ssrcA, g_sdstA, n, 2, D, b0, m4, i4, lane);
        float sd4[H];
#pragma unroll
        for (int h4 = 0; h4 < H; h4++) sd4[h4] = g_sdstA[n * H + h4];
        for (int jj = 0; jj < D; jj++) {
            int p = g_se[b0 + jj];
            int src = p & 0xFFFFF, et = p >> 20;
            float2 v = __half22float2(h2[(size_t)src * 64 + lane]);
            float2 u = __half22float2(h2[(size_t)src * 64 + 32 + lane]);
#pragma unroll
            for (int h4 = 0; h4 < H; h4++) {
                float a = g_ssrcA[src * H + h4] + sd4[h4] + g_etab[2][et * H + h4];
                a = (a > 0.f) ? a : NEG * a;
                float w = __expf(a - m4[h4]) * i4[h4];
                ax[h4] += w * v.x;
                ay[h4] += w * v.y;
                bx[h4] += w * u.x;
                by[h4] += w * u.y;
            }
        }
    }

    size_t base = (size_t)n * 256 + lane;
#pragma unroll
    for (int h4 = 0; h4 < H; h4++) {
        agg2[base + h4 * 64]      = __floats2half2_rn(ax[h4], ay[h4]);
        agg2[base + h4 * 64 + 32] = __floats2half2_rn(bx[h4], by[h4]);
    }
}

// ------- fp16 TC GEMM: 128x128x32 tiles, 3-stage cp.async ring -------------
constexpr int STG_BYTES = 128 * 40 * 2 * 2;    // A+B per stage = 20480 B
constexpr int SMEM_HF   = 3 * STG_BYTES;       // 61440 B

__device__ __forceinline__ uint32_t smem_u32(const void* p) {
    uint32_t a;
    asm("{ .reg .u64 t; cvta.to.shared.u64 t, %1; cvt.u32.u64 %0, t; }" : "=r"(a) : "l"(p));
    return a;
}

__global__ void __launch_bounds__(256, 2)
k_gemm_hf(const __half* __restrict__ A, const __half* __restrict__ Bt,
          const float* __restrict__ bias, float* __restrict__ C,
          __half2* __restrict__ Ch2, const float* __restrict__ Usrc,
          const float* __restrict__ Udst, int K, int NN, int relu) {
    extern __shared__ char hsm[];
    int tid = threadIdx.x;
    int wid = tid >> 5, lane = tid & 31;
    int bm = blockIdx.y * 128, bn = blockIdx.x * 128;
    int wm = (wid >> 2) * 64;
    int wn = (wid & 3) * 32;
    int grp = lane >> 2, tig = lane & 3;

    auto stA = [&](int s) { return reinterpret_cast<__half*>(hsm + s * STG_BYTES); };
    auto stB = [&](int s) { return reinterpret_cast<__half*>(hsm + s * STG_BYTES) + 128 * 40; };

    float c[4][4][4];
#pragma unroll
    for (int mt = 0; mt < 4; mt++)
#pragma unroll
        for (int nt = 0; nt < 4; nt++)
#pragma unroll
            for (int q = 0; q < 4; q++) c[mt][nt][q] = 0.f;

    int nk = K >> 5;

    auto copy_tile = [&](int s, int k0) {
        __half* As = stA(s);
        __half* Bs = stB(s);
#pragma unroll
        for (int i = 0; i < 2; i++) {
            int f = tid + i * 256;
            int m = f >> 2, q = f & 3;
            uint32_t dst = smem_u32(&As[m * 40 + q * 8]);
            const __half* src = &A[(size_t)(bm + m) * K + k0 + q * 8];
            asm volatile("cp.async.ca.shared.global [%0], [%1], 16;" :: "r"(dst), "l"(src));
        }
#pragma unroll
        for (int i = 0; i < 2; i++) {
            int f = tid + i * 256;
            int nrow = f >> 2, q = f & 3;
            uint32_t dst = smem_u32(&Bs[nrow * 40 + q * 8]);
            const __half* src = &Bt[(size_t)(bn + nrow) * K + k0 + q * 8];
            asm volatile("cp.async.ca.shared.global [%0], [%1], 16;" :: "r"(dst), "l"(src));
        }
        asm volatile("cp.async.commit_group;");
    };

    copy_tile(0, 0);
    copy_tile(1, 32);

    int mtx = lane >> 3;
    int rin = lane & 7;

    for (int it = 0; it < nk; it++) {
        int cur = it % 3;
        if (it + 1 < nk) asm volatile("cp.async.wait_group 1;");
        else             asm volatile("cp.async.wait_group 0;");
        __syncthreads();
        if (it + 2 < nk) copy_tile((it + 2) % 3, (it + 2) * 32);

        __half* As = stA(cur);
        __half* Bs = stB(cur);
#pragma unroll
        for (int ks = 0; ks < 2; ks++) {
            uint32_t a[4][4], b[4][2];
#pragma unroll
            for (int mt = 0; mt < 4; mt++) {
                int row = wm + mt * 16 + (mtx & 1) * 8 + rin;
                int col = ks * 16 + (mtx >> 1) * 8;
                uint32_t addr = smem_u32(&As[row * 40 + col]);
                asm volatile("ldmatrix.sync.aligned.m8n8.x4.shared.b16 {%0,%1,%2,%3}, [%4];"
                             : "=r"(a[mt][0]), "=r"(a[mt][1]), "=r"(a[mt][2]), "=r"(a[mt][3])
                             : "r"(addr));
            }
#pragma unroll
            for (int np = 0; np < 2; np++) {
                int row = wn + np * 16 + (mtx >> 1) * 8 + rin;
                int col = ks * 16 + (mtx & 1) * 8;
                uint32_t addr = smem_u32(&Bs[row * 40 + col]);
                asm volatile("ldmatrix.sync.aligned.m8n8.x4.shared.b16 {%0,%1,%2,%3}, [%4];"
                             : "=r"(b[np * 2][0]), "=r"(b[np * 2][1]),
                               "=r"(b[np * 2 + 1][0]), "=r"(b[np * 2 + 1][1])
                             : "r"(addr));
            }
#pragma unroll
            for (int mt = 0; mt < 4; mt++)
#pragma unroll
                for (int nt = 0; nt < 4; nt++) {
                    asm volatile(
                        "mma.sync.aligned.m16n8k16.row.col.f32.f16.f16.f32 "
                        "{%0,%1,%2,%3}, {%4,%5,%6,%7}, {%8,%9}, {%0,%1,%2,%3};"
                        : "+f"(c[mt][nt][0]), "+f"(c[mt][nt][1]),
                          "+f"(c[mt][nt][2]), "+f"(c[mt][nt][3])
                        : "r"(a[mt][0]), "r"(a[mt][1]), "r"(a[mt][2]), "r"(a[mt][3]),
                          "r"(b[nt][0]), "r"(b[nt][1]));
                }
        }
        __syncthreads();
    }

    float bv[4][2];
#pragma unroll
    for (int nt = 0; nt < 4; nt++) {
        int col = bn + wn + nt * 8 + tig * 2;
        bv[nt][0] = bias[col];
        bv[nt][1] = bias[col + 1];
    }

#pragma unroll
    for (int mt = 0; mt < 4; mt++) {
#pragma unroll
        for (int nt = 0; nt < 4; nt++) {
            int col = bn + wn + nt * 8 + tig * 2;
            int r0 = bm + wm + mt * 16 + grp;
            float v00 = c[mt][nt][0] + bv[nt][0], v01 = c[mt][nt][1] + bv[nt][1];
            float v10 = c[mt][nt][2] + bv[nt][0], v11 = c[mt][nt][3] + bv[nt][1];
            if (relu) {
                v00 = fmaxf(v00, 0.f); v01 = fmaxf(v01, 0.f);
                v10 = fmaxf(v10, 0.f); v11 = fmaxf(v11, 0.f);
            }
            C[(size_t)r0 * NN + col]           = v00;
            C[(size_t)r0 * NN + col + 1]       = v01;
            C[(size_t)(r0 + 8) * NN + col]     = v10;
            C[(size_t)(r0 + 8) * NN + col + 1] = v11;
            if (Ch2) {
                Ch2[((size_t)r0 * NN + col) >> 1]       = __floats2half2_rn(v00, v01);
                Ch2[((size_t)(r0 + 8) * NN + col) >> 1] = __floats2half2_rn(v10, v11);
            }
        }
    }

    if (Usrc) {
        float* s_sc = reinterpret_cast<float*>(hsm);
        for (int i = tid; i < 128 * 8; i += 256) s_sc[i] = 0.f;
        __syncthreads();
#pragma unroll
        for (int h8 = 0; h8 < 8; h8++) {
            const float* U = (h8 < 4) ? (Usrc + h8 * NN) : (Udst + (h8 - 4) * NN);
            float u[4][2];
#pragma unroll
            for (int nt = 0; nt < 4; nt++) {
                int col = wn + nt * 8 + tig * 2;
                u[nt][0] = U[col];
                u[nt][1] = U[col + 1];
            }
#pragma unroll
            for (int mt = 0; mt < 4; mt++) {
                int r0 = wm + mt * 16 + grp;
                float p0 = 0.f, p1 = 0.f;
#pragma unroll
                for (int nt = 0; nt < 4; nt++) {
                    float v00 = c[mt][nt][0] + bv[nt][0], v01 = c[mt][nt][1] + bv[nt][1];
                    float v10 = c[mt][nt][2] + bv[nt][0], v11 = c[mt][nt][3] + bv[nt][1];
                    v00 = fmaxf(v00, 0.f); v01 = fmaxf(v01, 0.f);
                    v10 = fmaxf(v10, 0.f); v11 = fmaxf(v11, 0.f);
                    p0 += v00 * u[nt][0] + v01 * u[nt][1];
                    p1 += v10 * u[nt][0] + v11 * u[nt][1];
                }
                p0 += __shfl_xor_sync(0xffffffffu, p0, 1);
                p0 += __shfl_xor_sync(0xffffffffu, p0, 2);
                p1 += __shfl_xor_sync(0xffffffffu, p1, 1);
                p1 += __shfl_xor_sync(0xffffffffu, p1, 2);
                if (tig == 0) {
                    atomicAdd(&s_sc[r0 * 8 + h8], p0);
                    atomicAdd(&s_sc[(r0 + 8) * 8 + h8], p1);
                }
            }
        }
        __syncthreads();
        for (int i = tid; i < 128 * 8; i += 256) {
            int r = i >> 3, h8 = i & 7;
            float v = s_sc[i];
            if (h8 < 4) g_ssrcA[(bm + r) * H + h8] = v;
            else        g_sdstA[(bm + r) * H + (h8 - 4)] = v;
        }
    }
}

// ---------------------------------------------------------------------------
extern "C" void kernel_launch(void* const* d_in, const int* in_sizes, int n_in,
                              void* d_out, int out_size) {
    const float* x   = (const float*)d_in[0];
    const int*   eit = (const int*)d_in[1];
    const float* W1  = (const float*)d_in[2];
    const float* We1 = (const float*)d_in[3];
    const float* as1 = (const float*)d_in[4];
    const float* ad1 = (const float*)d_in[5];
    const float* ae1 = (const float*)d_in[6];
    const float* b1  = (const float*)d_in[7];
    const float* W2  = (const float*)d_in[8];
    const float* We2 = (const float*)d_in[9];
    const float* as2 = (const float*)d_in[10];
    const float* ad2 = (const float*)d_in[11];
    const float* ae2 = (const float*)d_in[12];
    const float* b2  = (const float*)d_in[13];
    const float* W3  = (const float*)d_in[14];
    const float* We3 = (const float*)d_in[15];
    const float* as3 = (const float*)d_in[16];
    const float* ad3 = (const float*)d_in[17];
    const float* ae3 = (const float*)d_in[18];
    const float* b3  = (const float*)d_in[19];
    float* out = (float*)d_out;

    float *agg = nullptr, *hbuf = nullptr;
    float *usrc = nullptr, *udst = nullptr;
    __half *wst2 = nullptr, *wst3 = nullptr;
    __half2 *hbufh2 = nullptr;
    cudaGetSymbolAddress((void**)&agg, g_agg);
    cudaGetSymbolAddress((void**)&hbuf, g_hbuf);
    cudaGetSymbolAddress((void**)&wst2, g_wst2);
    cudaGetSymbolAddress((void**)&wst3, g_wst3);
    cudaGetSymbolAddress((void**)&hbufh2, g_hbufh2);
    cudaGetSymbolAddress((void**)&usrc, g_usrc);
    cudaGetSymbolAddress((void**)&udst, g_udst);
    const __half* aggh = (const __half*)agg;
    __half* aggw = (__half*)agg;
    __half2* agg2 = (__half2*)agg;

    cudaFuncSetAttribute(k_gemm_hf, cudaFuncAttributeMaxDynamicSharedMemorySize, SMEM_HF);

    // ---- setup (build+prep), scan, scatter+L1 scores (A) ----
    k_setup<<<1011, 256>>>(eit,
                           W1, as1, ad1, We1, ae1,
                           W2, as2, ad2, We2, ae2,
                           W3, as3, ad3, We3, ae3);
    k_scan<<<1, 1024>>>();
    k_scat_scores<<<640 + 2048, 256>>>(x);

    // ---- layer 1 FUSED: edge(A) + GEMM + L2 scores(B) ----
    k_l1_fused<<<N / 8, 256>>>(x, b1, hbuf);

    // ---- layer 2: edge(B) + TC GEMM (fuses L3 scores->A, half2 out) ----
    k_gat_edge2<<<N / 8, 256>>>(hbuf, aggw);
    k_gemm_hf<<<dim3(1, N / 128), 256, SMEM_HF>>>(aggh, wst2, b2, hbuf, hbufh2,
                                                  usrc + 2 * 512, udst + 2 * 512, 128, 128, 1);

    // ---- layer 3: edge(A, warp/node) + TC GEMM -> out ----
    k_gat_edge3<<<N / 8, 256>>>(hbufh2, agg2);
    k_gemm_hf<<<dim3(4, N / 128), 256, SMEM_HF>>>(aggh, wst3, b3, out, nullptr,
                                                  nullptr, nullptr, 512, 512, 0);
}